// round 1
// baseline (speedup 1.0000x reference)
#include <cuda_runtime.h>
#include <cuda_bf16.h>
#include <math.h>

// Problem constants (fixed shapes)
#define BB   2
#define TT   2048
#define DIM  1024
#define NH   16
#define DK   64
#define TOPK 64
#define HID  8192
#define M_ROWS (BB*TT)           // 4096
#define NBH  (BB*NH)             // 32

// ---------------- scratch (static device memory; no allocations) -------------
__device__ float g_xn  [(size_t)M_ROWS * DIM];        // 16 MB
__device__ float g_qkv [(size_t)M_ROWS * 3 * DIM];    // 48 MB
__device__ float g_S   [(size_t)NBH * TT * TT];       // 512 MB
__device__ float g_attn[(size_t)M_ROWS * DIM];        // 16 MB
__device__ float g_x1  [(size_t)M_ROWS * DIM];        // 16 MB
__device__ float g_xn2 [(size_t)M_ROWS * DIM];        // 16 MB
__device__ float g_h   [(size_t)M_ROWS * HID];        // 128 MB

// ---------------- LayerNorm ---------------------------------------------------
__global__ __launch_bounds__(256)
void ln_kernel(const float* __restrict__ x, const float* __restrict__ g,
               const float* __restrict__ b, float* __restrict__ o)
{
    const int rowbase = blockIdx.x * DIM;
    const int tid = threadIdx.x;
    float v[4];
    float s = 0.f, s2 = 0.f;
#pragma unroll
    for (int i = 0; i < 4; i++) {
        v[i] = x[rowbase + tid + i * 256];
        s  += v[i];
        s2 += v[i] * v[i];
    }
    __shared__ float r1[256], r2[256];
    r1[tid] = s; r2[tid] = s2; __syncthreads();
    for (int st = 128; st > 0; st >>= 1) {
        if (tid < st) { r1[tid] += r1[tid + st]; r2[tid] += r2[tid + st]; }
        __syncthreads();
    }
    const float mu   = r1[0] * (1.f / DIM);
    const float var  = r2[0] * (1.f / DIM) - mu * mu;
    const float rstd = rsqrtf(var + 1e-5f);
#pragma unroll
    for (int i = 0; i < 4; i++) {
        int c = tid + i * 256;
        o[rowbase + c] = (v[i] - mu) * rstd * g[c] + b[c];
    }
}

// ---------------- generic tiled SGEMM: C = A[MxK] @ B[KxN] --------------------
// BM=BN=128, BK=16, 256 threads, 8x8 microtile.
// EPI: 0 plain | 1 resid+alpha*acc | 2 gelu(acc+bias) | 3 resid+alpha*(acc+bias)
template <int EPI>
__global__ __launch_bounds__(256)
void sgemm128(int M, int N, int K,
              const float* __restrict__ A, int lda,
              const float* __restrict__ B, int ldb,
              float* __restrict__ C, int ldc,
              const float* __restrict__ bias,
              const float* __restrict__ resid,
              const float* __restrict__ alphap)
{
    constexpr int BK = 16;
    __shared__ float As[BK][128];
    __shared__ float Bs[BK][128];

    const int tid = threadIdx.x;
    const int bm = blockIdx.y * 128;
    const int bn = blockIdx.x * 128;
    const int tx = tid & 15, ty = tid >> 4;

    float acc[8][8];
#pragma unroll
    for (int i = 0; i < 8; i++)
#pragma unroll
        for (int j = 0; j < 8; j++) acc[i][j] = 0.f;

    const int aRow = tid >> 1;            // 0..127
    const int aK   = (tid & 1) * 8;       // 0 or 8
    const int bK   = tid >> 4;            // 0..15
    const int bN   = (tid & 15) * 8;      // 0..120

    const float* Aptr = A + (size_t)(bm + aRow) * lda + aK;
    const float* Bptr = B + (size_t)bK * ldb + bn + bN;

    for (int k0 = 0; k0 < K; k0 += BK) {
        float4 a0 = *(const float4*)(Aptr + k0);
        float4 a1 = *(const float4*)(Aptr + k0 + 4);
        As[aK + 0][aRow] = a0.x; As[aK + 1][aRow] = a0.y;
        As[aK + 2][aRow] = a0.z; As[aK + 3][aRow] = a0.w;
        As[aK + 4][aRow] = a1.x; As[aK + 5][aRow] = a1.y;
        As[aK + 6][aRow] = a1.z; As[aK + 7][aRow] = a1.w;
        float4 b0 = *(const float4*)(Bptr + (size_t)k0 * ldb);
        float4 b1 = *(const float4*)(Bptr + (size_t)k0 * ldb + 4);
        *(float4*)&Bs[bK][bN]     = b0;
        *(float4*)&Bs[bK][bN + 4] = b1;
        __syncthreads();
#pragma unroll
        for (int kk = 0; kk < BK; kk++) {
            float a[8], b[8];
            *(float4*)(a)     = *(const float4*)&As[kk][ty * 8];
            *(float4*)(a + 4) = *(const float4*)&As[kk][ty * 8 + 4];
            *(float4*)(b)     = *(const float4*)&Bs[kk][tx * 8];
            *(float4*)(b + 4) = *(const float4*)&Bs[kk][tx * 8 + 4];
#pragma unroll
            for (int i = 0; i < 8; i++)
#pragma unroll
                for (int j = 0; j < 8; j++) acc[i][j] += a[i] * b[j];
        }
        __syncthreads();
    }

    const float al = (EPI == 1 || EPI == 3) ? alphap[0] : 0.f;
    const int row0 = bm + ty * 8;
    const int col0 = bn + tx * 8;
#pragma unroll
    for (int i = 0; i < 8; i++) {
        size_t coff = (size_t)(row0 + i) * ldc + col0;
#pragma unroll
        for (int j = 0; j < 8; j++) {
            float r;
            if (EPI == 0) {
                r = acc[i][j];
            } else if (EPI == 1) {
                r = resid[coff + j] + al * acc[i][j];
            } else if (EPI == 2) {
                float u = acc[i][j] + bias[col0 + j];
                r = 0.5f * u * (1.f + erff(u * 0.70710678118654752440f));
            } else {
                r = resid[coff + j] + al * (acc[i][j] + bias[col0 + j]);
            }
            C[coff + j] = r;
        }
    }
}

// ---------------- batched QK^T: S[bh] = Q_bh @ K_bh^T / 8 ---------------------
__global__ __launch_bounds__(256)
void qk_kernel(const float* __restrict__ qkv, float* __restrict__ S)
{
    constexpr int BK = 16;
    __shared__ float Qs[BK][128];
    __shared__ float Ks[BK][128];

    const int bh = blockIdx.z;
    const int b = bh >> 4, h = bh & 15;
    const float* Q  = qkv + (size_t)b * TT * (3 * DIM) + h * DK;
    const float* Kp = qkv + (size_t)b * TT * (3 * DIM) + DIM + h * DK;
    float* Sp = S + (size_t)bh * TT * TT;

    const int tid = threadIdx.x;
    const int bm = blockIdx.y * 128;   // q rows
    const int bn = blockIdx.x * 128;   // k rows
    const int tx = tid & 15, ty = tid >> 4;

    float acc[8][8];
#pragma unroll
    for (int i = 0; i < 8; i++)
#pragma unroll
        for (int j = 0; j < 8; j++) acc[i][j] = 0.f;

    const int aRow = tid >> 1;
    const int aK   = (tid & 1) * 8;
    const float* Qptr = Q  + (size_t)(bm + aRow) * (3 * DIM) + aK;
    const float* Kptr = Kp + (size_t)(bn + aRow) * (3 * DIM) + aK;

    for (int k0 = 0; k0 < DK; k0 += BK) {
        float4 q0 = *(const float4*)(Qptr + k0);
        float4 q1 = *(const float4*)(Qptr + k0 + 4);
        Qs[aK + 0][aRow] = q0.x; Qs[aK + 1][aRow] = q0.y;
        Qs[aK + 2][aRow] = q0.z; Qs[aK + 3][aRow] = q0.w;
        Qs[aK + 4][aRow] = q1.x; Qs[aK + 5][aRow] = q1.y;
        Qs[aK + 6][aRow] = q1.z; Qs[aK + 7][aRow] = q1.w;
        float4 c0 = *(const float4*)(Kptr + k0);
        float4 c1 = *(const float4*)(Kptr + k0 + 4);
        Ks[aK + 0][aRow] = c0.x; Ks[aK + 1][aRow] = c0.y;
        Ks[aK + 2][aRow] = c0.z; Ks[aK + 3][aRow] = c0.w;
        Ks[aK + 4][aRow] = c1.x; Ks[aK + 5][aRow] = c1.y;
        Ks[aK + 6][aRow] = c1.z; Ks[aK + 7][aRow] = c1.w;
        __syncthreads();
#pragma unroll
        for (int kk = 0; kk < BK; kk++) {
            float a[8], bvec[8];
            *(float4*)(a)        = *(const float4*)&Qs[kk][ty * 8];
            *(float4*)(a + 4)    = *(const float4*)&Qs[kk][ty * 8 + 4];
            *(float4*)(bvec)     = *(const float4*)&Ks[kk][tx * 8];
            *(float4*)(bvec + 4) = *(const float4*)&Ks[kk][tx * 8 + 4];
#pragma unroll
            for (int i = 0; i < 8; i++)
#pragma unroll
                for (int j = 0; j < 8; j++) acc[i][j] += a[i] * bvec[j];
        }
        __syncthreads();
    }

    const int row0 = bm + ty * 8;
    const int col0 = bn + tx * 8;
#pragma unroll
    for (int i = 0; i < 8; i++) {
        size_t coff = (size_t)(row0 + i) * TT + col0;
#pragma unroll
        for (int j = 0; j < 8; j++)
            Sp[coff + j] = acc[i][j] * 0.125f;   // 1/sqrt(64)
    }
}

// ---------------- fused dual softmax + exact top-64 (radix select) ------------
__device__ __forceinline__ unsigned int ordkey(float f)
{
    unsigned int u = __float_as_uint(f);
    return (u & 0x80000000u) ? ~u : (u | 0x80000000u);
}

__global__ __launch_bounds__(256)
void softmax_topk_kernel(float* __restrict__ S, const float* __restrict__ alpha_head)
{
    __shared__ float vals[TT];
    __shared__ float red[256];
    __shared__ int   hist[256];
    __shared__ unsigned char keep[TT];
    __shared__ int   sel[2];

    const int tid = threadIdx.x;
    const int rowid = blockIdx.x;            // 0 .. 65535
    const int h = (rowid >> 11) & 15;
    float* row = S + (size_t)rowid * TT;

    float lmax = -3.4e38f;
    for (int j = tid; j < TT; j += 256) {
        float v = row[j];
        vals[j] = v;
        lmax = fmaxf(lmax, v);
    }
    red[tid] = lmax; __syncthreads();
    for (int s = 128; s > 0; s >>= 1) { if (tid < s) red[tid] = fmaxf(red[tid], red[tid + s]); __syncthreads(); }
    const float m = red[0];
    __syncthreads();

    float lsum = 0.f;
    for (int j = tid; j < TT; j += 256) lsum += expf(vals[j] - m);
    red[tid] = lsum; __syncthreads();
    for (int s = 128; s > 0; s >>= 1) { if (tid < s) red[tid] += red[tid + s]; __syncthreads(); }
    const float Zd = red[0];
    __syncthreads();

    // exact 64th-largest via 4x8-bit radix select on order-preserving keys
    unsigned int prefix = 0u, pmask = 0u;
    int kth = TOPK;
    for (int shift = 24; shift >= 0; shift -= 8) {
        hist[tid] = 0;
        __syncthreads();
        for (int j = tid; j < TT; j += 256) {
            unsigned int u = ordkey(vals[j]);
            if ((u & pmask) == prefix) atomicAdd(&hist[(u >> shift) & 255], 1);
        }
        __syncthreads();
        if (tid == 0) {
            int c = 0, bsel = 0;
            for (int bb = 255; bb >= 0; bb--) {
                int nc = c + hist[bb];
                if (nc >= kth) { bsel = bb; break; }
                c = nc;
            }
            sel[0] = bsel; sel[1] = c;
        }
        __syncthreads();
        prefix |= ((unsigned int)sel[0]) << shift;
        pmask  |= 0xFFu << shift;
        kth    -= sel[1];
        __syncthreads();
    }
    const unsigned int thr = prefix;

    int lgt = 0, leq = 0;
    for (int j = tid; j < TT; j += 256) {
        unsigned int u = ordkey(vals[j]);
        unsigned char kf = (u > thr) ? 1 : ((u == thr) ? 2 : 0);
        keep[j] = kf;
        lgt += (kf == 1);
        leq += (kf == 2);
    }
    red[tid] = (float)lgt; __syncthreads();
    for (int s = 128; s > 0; s >>= 1) { if (tid < s) red[tid] += red[tid + s]; __syncthreads(); }
    const int n_gt = (int)red[0]; __syncthreads();
    red[tid] = (float)leq; __syncthreads();
    for (int s = 128; s > 0; s >>= 1) { if (tid < s) red[tid] += red[tid + s]; __syncthreads(); }
    const int n_eq = (int)red[0]; __syncthreads();

    const int need = TOPK - n_gt;
    if (need == n_eq) {
        for (int j = tid; j < TT; j += 256) if (keep[j] == 2) keep[j] = 1;
    } else if (tid == 0) {
        // ties: take lowest indices first (matches top_k tie-breaking)
        int taken = 0;
        for (int j = 0; j < TT; j++) {
            if (keep[j] == 2) { keep[j] = (taken < need) ? 1 : 0; taken++; }
        }
    }
    __syncthreads();

    float lss = 0.f;
    for (int j = tid; j < TT; j += 256) if (keep[j]) lss += expf(vals[j] - m);
    red[tid] = lss; __syncthreads();
    for (int s = 128; s > 0; s >>= 1) { if (tid < s) red[tid] += red[tid + s]; __syncthreads(); }
    const float Zs = red[0];

    const float gate = 1.f / (1.f + expf(-alpha_head[h]));
    const float cd = gate / Zd;
    const float cs = (1.f - gate) / Zs;
    for (int j = tid; j < TT; j += 256) {
        float e = expf(vals[j] - m);
        row[j] = e * cd + (keep[j] ? e * cs : 0.f);
    }
}

// ---------------- batched PV: attn_out = P @ V (reassembled layout) -----------
__global__ __launch_bounds__(256)
void pv_kernel(const float* __restrict__ S, const float* __restrict__ qkv,
               float* __restrict__ attn_out)
{
    constexpr int BK = 16;
    __shared__ float As[BK][128];
    __shared__ float Bs[BK][64];

    const int bh = blockIdx.z;
    const int b = bh >> 4, h = bh & 15;
    const float* P  = S + (size_t)bh * TT * TT;
    const float* Vp = qkv + (size_t)b * TT * (3 * DIM) + 2 * DIM + h * DK;

    const int tid = threadIdx.x;
    const int bm = blockIdx.y * 128;
    const int tx = tid & 15, ty = tid >> 4;   // tx: 16 x 4cols = 64, ty: 16 x 8rows

    float acc[8][4];
#pragma unroll
    for (int i = 0; i < 8; i++)
#pragma unroll
        for (int j = 0; j < 4; j++) acc[i][j] = 0.f;

    const int aRow = tid >> 1;
    const int aK   = (tid & 1) * 8;
    const int bK   = tid >> 4;            // 0..15 (j within tile)
    const int bN   = (tid & 15) * 4;      // 0..60 (d)

    const float* Aptr = P + (size_t)(bm + aRow) * TT + aK;

    for (int k0 = 0; k0 < TT; k0 += BK) {
        float4 a0 = *(const float4*)(Aptr + k0);
        float4 a1 = *(const float4*)(Aptr + k0 + 4);
        As[aK + 0][aRow] = a0.x; As[aK + 1][aRow] = a0.y;
        As[aK + 2][aRow] = a0.z; As[aK + 3][aRow] = a0.w;
        As[aK + 4][aRow] = a1.x; As[aK + 5][aRow] = a1.y;
        As[aK + 6][aRow] = a1.z; As[aK + 7][aRow] = a1.w;
        float4 b0 = *(const float4*)(Vp + (size_t)(k0 + bK) * (3 * DIM) + bN);
        *(float4*)&Bs[bK][bN] = b0;
        __syncthreads();
#pragma unroll
        for (int kk = 0; kk < BK; kk++) {
            float a[8], bvec[4];
            *(float4*)(a)     = *(const float4*)&As[kk][ty * 8];
            *(float4*)(a + 4) = *(const float4*)&As[kk][ty * 8 + 4];
            *(float4*)(bvec)  = *(const float4*)&Bs[kk][tx * 4];
#pragma unroll
            for (int i = 0; i < 8; i++)
#pragma unroll
                for (int j = 0; j < 4; j++) acc[i][j] += a[i] * bvec[j];
        }
        __syncthreads();
    }

    const int row0 = bm + ty * 8;
    const int col0 = tx * 4;
#pragma unroll
    for (int i = 0; i < 8; i++) {
        float4 r = make_float4(acc[i][0], acc[i][1], acc[i][2], acc[i][3]);
        *(float4*)&attn_out[(size_t)(b * TT + row0 + i) * DIM + h * DK + col0] = r;
    }
}

// ---------------- launch ------------------------------------------------------
extern "C" void kernel_launch(void* const* d_in, const int* in_sizes, int n_in,
                              void* d_out, int out_size)
{
    const float* x          = (const float*)d_in[0];
    const float* ln1_g      = (const float*)d_in[1];
    const float* ln1_b      = (const float*)d_in[2];
    const float* w_qkv      = (const float*)d_in[3];
    const float* alpha_head = (const float*)d_in[4];
    const float* w_out      = (const float*)d_in[5];
    const float* ln2_g      = (const float*)d_in[6];
    const float* ln2_b      = (const float*)d_in[7];
    const float* w1         = (const float*)d_in[8];
    const float* b1         = (const float*)d_in[9];
    const float* w2         = (const float*)d_in[10];
    const float* b2         = (const float*)d_in[11];
    const float* alpha      = (const float*)d_in[12];
    float* out = (float*)d_out;

    float *xn, *qkv, *Sm, *attn, *x1, *xn2, *hbuf;
    cudaGetSymbolAddress((void**)&xn,   g_xn);
    cudaGetSymbolAddress((void**)&qkv,  g_qkv);
    cudaGetSymbolAddress((void**)&Sm,   g_S);
    cudaGetSymbolAddress((void**)&attn, g_attn);
    cudaGetSymbolAddress((void**)&x1,   g_x1);
    cudaGetSymbolAddress((void**)&xn2,  g_xn2);
    cudaGetSymbolAddress((void**)&hbuf, g_h);

    // 1) LN1
    ln_kernel<<<M_ROWS, 256>>>(x, ln1_g, ln1_b, xn);
    // 2) QKV GEMM: [4096,1024] @ [1024,3072]
    sgemm128<0><<<dim3(3 * DIM / 128, M_ROWS / 128), 256>>>(
        M_ROWS, 3 * DIM, DIM, xn, DIM, w_qkv, 3 * DIM, qkv, 3 * DIM,
        nullptr, nullptr, nullptr);
    // 3) S = QK^T/8, batched over 32 (b,h)
    qk_kernel<<<dim3(TT / 128, TT / 128, NBH), 256>>>(qkv, Sm);
    // 4) fused dense+sparse softmax with exact top-64, S <- combined P
    softmax_topk_kernel<<<NBH * TT, 256>>>(Sm, alpha_head);
    // 5) attn_out = P @ V
    pv_kernel<<<dim3(1, TT / 128, NBH), 256>>>(Sm, qkv, attn);
    // 6) x1 = x + alpha * (attn_out @ w_out)
    sgemm128<1><<<dim3(DIM / 128, M_ROWS / 128), 256>>>(
        M_ROWS, DIM, DIM, attn, DIM, w_out, DIM, x1, DIM,
        nullptr, x, alpha);
    // 7) LN2
    ln_kernel<<<M_ROWS, 256>>>(x1, ln2_g, ln2_b, xn2);
    // 8) h = gelu(xn2 @ w1 + b1)
    sgemm128<2><<<dim3(HID / 128, M_ROWS / 128), 256>>>(
        M_ROWS, HID, DIM, xn2, DIM, w1, HID, hbuf, HID,
        b1, nullptr, nullptr);
    // 9) out = x1 + alpha * (h @ w2 + b2)
    sgemm128<3><<<dim3(DIM / 128, M_ROWS / 128), 256>>>(
        M_ROWS, DIM, HID, hbuf, HID, w2, DIM, out, DIM,
        b2, x1, alpha);
}

// round 2
// speedup vs baseline: 1.4278x; 1.4278x over previous
#include <cuda_runtime.h>
#include <math.h>

// Problem constants
#define BB   2
#define TT   2048
#define DIM  1024
#define NH   16
#define DK   64
#define TOPK 64
#define HID  8192
#define M_ROWS (BB*TT)           // 4096
#define NBH  (BB*NH)             // 32

// ---------------- scratch ------------------------------------------------------
__device__ float g_xn  [(size_t)M_ROWS * DIM];
__device__ float g_qkv [(size_t)M_ROWS * 3 * DIM];
__device__ float g_S   [(size_t)NBH * TT * TT];
__device__ float g_attn[(size_t)M_ROWS * DIM];
__device__ float g_x1  [(size_t)M_ROWS * DIM];
__device__ float g_xn2 [(size_t)M_ROWS * DIM];
__device__ float g_h   [(size_t)M_ROWS * HID];

// ---------------- helpers ------------------------------------------------------
__device__ __forceinline__ unsigned tf32b(float f)
{
    unsigned u;
    asm("cvt.rna.tf32.f32 %0, %1;" : "=r"(u) : "f"(f));
    return u;
}
__device__ __forceinline__ float4 tf32c4(float4 v)
{
    v.x = __uint_as_float(tf32b(v.x));
    v.y = __uint_as_float(tf32b(v.y));
    v.z = __uint_as_float(tf32b(v.z));
    v.w = __uint_as_float(tf32b(v.w));
    return v;
}
__device__ __forceinline__ void mma8(float* c, const unsigned* a, const unsigned* b)
{
    asm volatile(
        "mma.sync.aligned.m16n8k8.row.col.f32.tf32.tf32.f32 "
        "{%0,%1,%2,%3},{%4,%5,%6,%7},{%8,%9},{%0,%1,%2,%3};\n"
        : "+f"(c[0]), "+f"(c[1]), "+f"(c[2]), "+f"(c[3])
        : "r"(a[0]), "r"(a[1]), "r"(a[2]), "r"(a[3]), "r"(b[0]), "r"(b[1]));
}

// ---------------- LayerNorm ----------------------------------------------------
__global__ __launch_bounds__(256)
void ln_kernel(const float* __restrict__ x, const float* __restrict__ g,
               const float* __restrict__ b, float* __restrict__ o)
{
    const int rowbase = blockIdx.x * DIM;
    const int tid = threadIdx.x;
    float v[4];
    float s = 0.f, s2 = 0.f;
#pragma unroll
    for (int i = 0; i < 4; i++) {
        v[i] = x[rowbase + tid + i * 256];
        s  += v[i];
        s2 += v[i] * v[i];
    }
    __shared__ float r1[256], r2[256];
    r1[tid] = s; r2[tid] = s2; __syncthreads();
    for (int st = 128; st > 0; st >>= 1) {
        if (tid < st) { r1[tid] += r1[tid + st]; r2[tid] += r2[tid + st]; }
        __syncthreads();
    }
    const float mu   = r1[0] * (1.f / DIM);
    const float var  = r2[0] * (1.f / DIM) - mu * mu;
    const float rstd = rsqrtf(var + 1e-5f);
#pragma unroll
    for (int i = 0; i < 4; i++) {
        int c = tid + i * 256;
        o[rowbase + c] = (v[i] - mu) * rstd * g[c] + b[c];
    }
}

// ---------------- generic tf32 tensor-core GEMM --------------------------------
// C[M,N] = A[M,K](row) @ B[K,N](row).  256 threads.
// EPI: 0 plain | 1 resid+alpha*acc | 2 gelu(acc+bias) | 3 resid+alpha*(acc+bias)
template <int BM, int BN, int WM, int WN, int EPI>
__global__ __launch_bounds__(256)
void mma_gemm(int K,
              const float* __restrict__ A, int lda,
              const float* __restrict__ B, int ldb,
              float* __restrict__ C, int ldc,
              const float* __restrict__ bias,
              const float* __restrict__ resid,
              const float* __restrict__ alphap)
{
    constexpr int BK = 32;
    constexpr int MT = WM / 16, NT = WN / 8;
    constexpr int WGN = BN / WN;
    __shared__ float As[BM][BK + 4];     // [m][k]
    __shared__ float Bs[BK][BN + 8];     // [k][n]

    const int tid = threadIdx.x, lane = tid & 31, warp = tid >> 5;
    const int bm = blockIdx.y * BM, bn = blockIdx.x * BN;
    const int wm = (warp / WGN) * WM, wn = (warp % WGN) * WN;

    float acc[MT][NT][4];
#pragma unroll
    for (int mi = 0; mi < MT; mi++)
#pragma unroll
        for (int ni = 0; ni < NT; ni++)
#pragma unroll
            for (int q = 0; q < 4; q++) acc[mi][ni][q] = 0.f;

    for (int k0 = 0; k0 < K; k0 += BK) {
#pragma unroll
        for (int idx = tid; idx < BM * (BK / 4); idx += 256) {
            int m = idx >> 3, k4 = (idx & 7) << 2;
            float4 v = *(const float4*)(A + (size_t)(bm + m) * lda + k0 + k4);
            *(float4*)&As[m][k4] = tf32c4(v);
        }
#pragma unroll
        for (int idx = tid; idx < BK * (BN / 4); idx += 256) {
            int k = idx / (BN / 4), n4 = (idx % (BN / 4)) << 2;
            float4 v = *(const float4*)(B + (size_t)(k0 + k) * ldb + bn + n4);
            *(float4*)&Bs[k][n4] = tf32c4(v);
        }
        __syncthreads();
#pragma unroll
        for (int ks = 0; ks < BK / 8; ks++) {
            const int kb = ks * 8;
            unsigned af[MT][4], bf[NT][2];
#pragma unroll
            for (int mi = 0; mi < MT; mi++) {
                int m = wm + mi * 16 + (lane >> 2);
                int kk = kb + (lane & 3);
                af[mi][0] = __float_as_uint(As[m][kk]);
                af[mi][1] = __float_as_uint(As[m + 8][kk]);
                af[mi][2] = __float_as_uint(As[m][kk + 4]);
                af[mi][3] = __float_as_uint(As[m + 8][kk + 4]);
            }
#pragma unroll
            for (int ni = 0; ni < NT; ni++) {
                int n = wn + ni * 8 + (lane >> 2);
                bf[ni][0] = __float_as_uint(Bs[kb + (lane & 3)][n]);
                bf[ni][1] = __float_as_uint(Bs[kb + 4 + (lane & 3)][n]);
            }
#pragma unroll
            for (int mi = 0; mi < MT; mi++)
#pragma unroll
                for (int ni = 0; ni < NT; ni++) mma8(acc[mi][ni], af[mi], bf[ni]);
        }
        __syncthreads();
    }

    const float al = (EPI == 1 || EPI == 3) ? alphap[0] : 0.f;
#pragma unroll
    for (int mi = 0; mi < MT; mi++) {
#pragma unroll
        for (int ni = 0; ni < NT; ni++) {
            int r0 = bm + wm + mi * 16 + (lane >> 2);
            int c  = bn + wn + ni * 8 + 2 * (lane & 3);
#pragma unroll
            for (int half = 0; half < 2; half++) {
                int r = r0 + half * 8;
                size_t off = (size_t)r * ldc + c;
                float v0 = acc[mi][ni][half * 2];
                float v1 = acc[mi][ni][half * 2 + 1];
                float o0, o1;
                if (EPI == 0) {
                    o0 = v0; o1 = v1;
                } else if (EPI == 1) {
                    o0 = resid[off] + al * v0;
                    o1 = resid[off + 1] + al * v1;
                } else if (EPI == 2) {
                    float u0 = v0 + bias[c], u1 = v1 + bias[c + 1];
                    o0 = 0.5f * u0 * (1.f + erff(u0 * 0.70710678118654752440f));
                    o1 = 0.5f * u1 * (1.f + erff(u1 * 0.70710678118654752440f));
                } else {
                    o0 = resid[off] + al * (v0 + bias[c]);
                    o1 = resid[off + 1] + al * (v1 + bias[c + 1]);
                }
                *(float2*)(C + off) = make_float2(o0, o1);
            }
        }
    }
}

// ---------------- batched QK^T (tf32 MMA): S = Q @ K^T / 8 ---------------------
__global__ __launch_bounds__(256)
void mma_qk(const float* __restrict__ qkv, float* __restrict__ S)
{
    constexpr int BM = 128, BN = 128, BK = 32, WM = 64, WN = 32;
    constexpr int MT = WM / 16, NT = WN / 8, WGN = BN / WN;
    __shared__ float As[BM][BK + 4];
    __shared__ float Bs[BK][BN + 8];

    const int bh = blockIdx.z;
    const int b = bh >> 4, h = bh & 15;
    const float* Q  = qkv + (size_t)b * TT * (3 * DIM) + h * DK;
    const float* Kp = qkv + (size_t)b * TT * (3 * DIM) + DIM + h * DK;
    float* Sp = S + (size_t)bh * TT * TT;

    const int tid = threadIdx.x, lane = tid & 31, warp = tid >> 5;
    const int bm = blockIdx.y * BM, bn = blockIdx.x * BN;
    const int wm = (warp / WGN) * WM, wn = (warp % WGN) * WN;

    float acc[MT][NT][4];
#pragma unroll
    for (int mi = 0; mi < MT; mi++)
#pragma unroll
        for (int ni = 0; ni < NT; ni++)
#pragma unroll
            for (int q = 0; q < 4; q++) acc[mi][ni][q] = 0.f;

#pragma unroll
    for (int k0 = 0; k0 < DK; k0 += BK) {
#pragma unroll
        for (int idx = tid; idx < BM * 8; idx += 256) {
            int m = idx >> 3, k4 = (idx & 7) << 2;
            float4 v = *(const float4*)(Q + (size_t)(bm + m) * (3 * DIM) + k0 + k4);
            *(float4*)&As[m][k4] = tf32c4(v);
        }
        // B tile: Bs[k][n] = K[bn+n][k0+k]  (transposed scatter)
#pragma unroll
        for (int idx = tid; idx < BN * 8; idx += 256) {
            int n = idx >> 3, k4 = (idx & 7) << 2;
            float4 v = *(const float4*)(Kp + (size_t)(bn + n) * (3 * DIM) + k0 + k4);
            v = tf32c4(v);
            Bs[k4 + 0][n] = v.x;
            Bs[k4 + 1][n] = v.y;
            Bs[k4 + 2][n] = v.z;
            Bs[k4 + 3][n] = v.w;
        }
        __syncthreads();
#pragma unroll
        for (int ks = 0; ks < BK / 8; ks++) {
            const int kb = ks * 8;
            unsigned af[MT][4], bf[NT][2];
#pragma unroll
            for (int mi = 0; mi < MT; mi++) {
                int m = wm + mi * 16 + (lane >> 2);
                int kk = kb + (lane & 3);
                af[mi][0] = __float_as_uint(As[m][kk]);
                af[mi][1] = __float_as_uint(As[m + 8][kk]);
                af[mi][2] = __float_as_uint(As[m][kk + 4]);
                af[mi][3] = __float_as_uint(As[m + 8][kk + 4]);
            }
#pragma unroll
            for (int ni = 0; ni < NT; ni++) {
                int n = wn + ni * 8 + (lane >> 2);
                bf[ni][0] = __float_as_uint(Bs[kb + (lane & 3)][n]);
                bf[ni][1] = __float_as_uint(Bs[kb + 4 + (lane & 3)][n]);
            }
#pragma unroll
            for (int mi = 0; mi < MT; mi++)
#pragma unroll
                for (int ni = 0; ni < NT; ni++) mma8(acc[mi][ni], af[mi], bf[ni]);
        }
        __syncthreads();
    }

#pragma unroll
    for (int mi = 0; mi < MT; mi++)
#pragma unroll
        for (int ni = 0; ni < NT; ni++) {
            int r0 = bm + wm + mi * 16 + (lane >> 2);
            int c  = bn + wn + ni * 8 + 2 * (lane & 3);
#pragma unroll
            for (int half = 0; half < 2; half++) {
                size_t off = (size_t)(r0 + half * 8) * TT + c;
                *(float2*)(Sp + off) = make_float2(acc[mi][ni][half * 2] * 0.125f,
                                                   acc[mi][ni][half * 2 + 1] * 0.125f);
            }
        }
}

// ---------------- batched PV (tf32 MMA): attn = P @ V --------------------------
__global__ __launch_bounds__(256)
void mma_pv(const float* __restrict__ S, const float* __restrict__ qkv,
            float* __restrict__ attn_out)
{
    constexpr int BM = 128, BN = 64, BK = 32, WM = 32, WN = 32;
    constexpr int MT = WM / 16, NT = WN / 8, WGN = BN / WN;
    __shared__ float As[BM][BK + 4];
    __shared__ float Bs[BK][BN + 8];

    const int bh = blockIdx.y;
    const int b = bh >> 4, h = bh & 15;
    const float* P  = S + (size_t)bh * TT * TT;
    const float* Vp = qkv + (size_t)b * TT * (3 * DIM) + 2 * DIM + h * DK;

    const int tid = threadIdx.x, lane = tid & 31, warp = tid >> 5;
    const int bm = blockIdx.x * BM;
    const int wm = (warp / WGN) * WM, wn = (warp % WGN) * WN;

    float acc[MT][NT][4];
#pragma unroll
    for (int mi = 0; mi < MT; mi++)
#pragma unroll
        for (int ni = 0; ni < NT; ni++)
#pragma unroll
            for (int q = 0; q < 4; q++) acc[mi][ni][q] = 0.f;

    for (int k0 = 0; k0 < TT; k0 += BK) {
#pragma unroll
        for (int idx = tid; idx < BM * 8; idx += 256) {
            int m = idx >> 3, k4 = (idx & 7) << 2;
            float4 v = *(const float4*)(P + (size_t)(bm + m) * TT + k0 + k4);
            *(float4*)&As[m][k4] = tf32c4(v);
        }
#pragma unroll
        for (int idx = tid; idx < BK * (BN / 4); idx += 256) {
            int k = idx / (BN / 4), n4 = (idx % (BN / 4)) << 2;
            float4 v = *(const float4*)(Vp + (size_t)(k0 + k) * (3 * DIM) + n4);
            *(float4*)&Bs[k][n4] = tf32c4(v);
        }
        __syncthreads();
#pragma unroll
        for (int ks = 0; ks < BK / 8; ks++) {
            const int kb = ks * 8;
            unsigned af[MT][4], bf[NT][2];
#pragma unroll
            for (int mi = 0; mi < MT; mi++) {
                int m = wm + mi * 16 + (lane >> 2);
                int kk = kb + (lane & 3);
                af[mi][0] = __float_as_uint(As[m][kk]);
                af[mi][1] = __float_as_uint(As[m + 8][kk]);
                af[mi][2] = __float_as_uint(As[m][kk + 4]);
                af[mi][3] = __float_as_uint(As[m + 8][kk + 4]);
            }
#pragma unroll
            for (int ni = 0; ni < NT; ni++) {
                int n = wn + ni * 8 + (lane >> 2);
                bf[ni][0] = __float_as_uint(Bs[kb + (lane & 3)][n]);
                bf[ni][1] = __float_as_uint(Bs[kb + 4 + (lane & 3)][n]);
            }
#pragma unroll
            for (int mi = 0; mi < MT; mi++)
#pragma unroll
                for (int ni = 0; ni < NT; ni++) mma8(acc[mi][ni], af[mi], bf[ni]);
        }
        __syncthreads();
    }

#pragma unroll
    for (int mi = 0; mi < MT; mi++)
#pragma unroll
        for (int ni = 0; ni < NT; ni++) {
            int r0 = bm + wm + mi * 16 + (lane >> 2);
            int c  = wn + ni * 8 + 2 * (lane & 3);
#pragma unroll
            for (int half = 0; half < 2; half++) {
                int r = r0 + half * 8;
                size_t off = (size_t)(b * TT + r) * DIM + h * DK + c;
                *(float2*)(attn_out + off) = make_float2(acc[mi][ni][half * 2],
                                                         acc[mi][ni][half * 2 + 1]);
            }
        }
}

// ---------------- fused dual softmax + exact top-64 (1 expf/elem) --------------
__device__ __forceinline__ unsigned int ordkey(float f)
{
    unsigned int u = __float_as_uint(f);
    return (u & 0x80000000u) ? ~u : (u | 0x80000000u);
}

__global__ __launch_bounds__(256)
void softmax_topk_kernel(float* __restrict__ S, const float* __restrict__ alpha_head)
{
    __shared__ float vals[TT];
    __shared__ float red[256];
    __shared__ float red2[256];
    __shared__ int   hist[256];
    __shared__ unsigned char keep[TT];
    __shared__ int   sel[2];

    const int tid = threadIdx.x;
    const int rowid = blockIdx.x;
    const int h = (rowid >> 11) & 15;
    float* row = S + (size_t)rowid * TT;

    float lmax = -3.4e38f;
    for (int j = tid; j < TT; j += 256) {
        float v = row[j];
        vals[j] = v;
        lmax = fmaxf(lmax, v);
    }
    red[tid] = lmax; __syncthreads();
    for (int s = 128; s > 0; s >>= 1) { if (tid < s) red[tid] = fmaxf(red[tid], red[tid + s]); __syncthreads(); }
    const float m = red[0];
    __syncthreads();

    // exact 64th-largest via 4x8-bit radix select on order-preserving keys
    unsigned int prefix = 0u, pmask = 0u;
    int kth = TOPK;
    for (int shift = 24; shift >= 0; shift -= 8) {
        hist[tid] = 0;
        __syncthreads();
        for (int j = tid; j < TT; j += 256) {
            unsigned int u = ordkey(vals[j]);
            if ((u & pmask) == prefix) atomicAdd(&hist[(u >> shift) & 255], 1);
        }
        __syncthreads();
        if (tid == 0) {
            int c = 0, bsel = 0;
            for (int bb = 255; bb >= 0; bb--) {
                int nc = c + hist[bb];
                if (nc >= kth) { bsel = bb; break; }
                c = nc;
            }
            sel[0] = bsel; sel[1] = c;
        }
        __syncthreads();
        prefix |= ((unsigned int)sel[0]) << shift;
        pmask  |= 0xFFu << shift;
        kth    -= sel[1];
        __syncthreads();
    }
    const unsigned int thr = prefix;

    int lgt = 0, leq = 0;
    for (int j = tid; j < TT; j += 256) {
        unsigned int u = ordkey(vals[j]);
        unsigned char kf = (u > thr) ? 1 : ((u == thr) ? 2 : 0);
        keep[j] = kf;
        lgt += (kf == 1);
        leq += (kf == 2);
    }
    red[tid] = (float)lgt; red2[tid] = (float)leq; __syncthreads();
    for (int s = 128; s > 0; s >>= 1) {
        if (tid < s) { red[tid] += red[tid + s]; red2[tid] += red2[tid + s]; }
        __syncthreads();
    }
    const int n_gt = (int)red[0];
    const int n_eq = (int)red2[0];
    __syncthreads();

    const int need = TOPK - n_gt;
    if (need == n_eq) {
        for (int j = tid; j < TT; j += 256) if (keep[j] == 2) keep[j] = 1;
    } else if (tid == 0) {
        int taken = 0;
        for (int j = 0; j < TT; j++) {
            if (keep[j] == 2) { keep[j] = (taken < need) ? 1 : 0; taken++; }
        }
    }
    __syncthreads();

    // single exp pass: dense sum + sparse sum, cache e in vals
    float sd = 0.f, ss = 0.f;
    for (int j = tid; j < TT; j += 256) {
        float e = __expf(vals[j] - m);
        vals[j] = e;
        sd += e;
        if (keep[j]) ss += e;
    }
    red[tid] = sd; red2[tid] = ss; __syncthreads();
    for (int s = 128; s > 0; s >>= 1) {
        if (tid < s) { red[tid] += red[tid + s]; red2[tid] += red2[tid + s]; }
        __syncthreads();
    }
    const float Zd = red[0];
    const float Zs = red2[0];

    const float gate = 1.f / (1.f + __expf(-alpha_head[h]));
    const float cd = gate / Zd;
    const float cs = (1.f - gate) / Zs;
    for (int j = tid; j < TT; j += 256) {
        float e = vals[j];
        row[j] = e * (cd + (keep[j] ? cs : 0.f));
    }
}

// ---------------- launch --------------------------------------------------------
extern "C" void kernel_launch(void* const* d_in, const int* in_sizes, int n_in,
                              void* d_out, int out_size)
{
    const float* x          = (const float*)d_in[0];
    const float* ln1_g      = (const float*)d_in[1];
    const float* ln1_b      = (const float*)d_in[2];
    const float* w_qkv      = (const float*)d_in[3];
    const float* alpha_head = (const float*)d_in[4];
    const float* w_out      = (const float*)d_in[5];
    const float* ln2_g      = (const float*)d_in[6];
    const float* ln2_b      = (const float*)d_in[7];
    const float* w1         = (const float*)d_in[8];
    const float* b1         = (const float*)d_in[9];
    const float* w2         = (const float*)d_in[10];
    const float* b2         = (const float*)d_in[11];
    const float* alpha      = (const float*)d_in[12];
    float* out = (float*)d_out;

    float *xn, *qkv, *Sm, *attn, *x1, *xn2, *hbuf;
    cudaGetSymbolAddress((void**)&xn,   g_xn);
    cudaGetSymbolAddress((void**)&qkv,  g_qkv);
    cudaGetSymbolAddress((void**)&Sm,   g_S);
    cudaGetSymbolAddress((void**)&attn, g_attn);
    cudaGetSymbolAddress((void**)&x1,   g_x1);
    cudaGetSymbolAddress((void**)&xn2,  g_xn2);
    cudaGetSymbolAddress((void**)&hbuf, g_h);

    // 1) LN1
    ln_kernel<<<M_ROWS, 256>>>(x, ln1_g, ln1_b, xn);
    // 2) QKV GEMM
    mma_gemm<128,128,64,32,0><<<dim3(3*DIM/128, M_ROWS/128), 256>>>(
        DIM, xn, DIM, w_qkv, 3*DIM, qkv, 3*DIM, nullptr, nullptr, nullptr);
    // 3) S = QK^T/8
    mma_qk<<<dim3(TT/128, TT/128, NBH), 256>>>(qkv, Sm);
    // 4) fused dual softmax + exact top-64
    softmax_topk_kernel<<<NBH*TT, 256>>>(Sm, alpha_head);
    // 5) attn = P @ V
    mma_pv<<<dim3(TT/128, NBH), 256>>>(Sm, qkv, attn);
    // 6) x1 = x + alpha * (attn @ w_out)
    mma_gemm<128,128,64,32,1><<<dim3(DIM/128, M_ROWS/128), 256>>>(
        DIM, attn, DIM, w_out, DIM, x1, DIM, nullptr, x, alpha);
    // 7) LN2
    ln_kernel<<<M_ROWS, 256>>>(x1, ln2_g, ln2_b, xn2);
    // 8) h = gelu(xn2 @ w1 + b1)
    mma_gemm<128,128,64,32,2><<<dim3(HID/128, M_ROWS/128), 256>>>(
        DIM, xn2, DIM, w1, HID, hbuf, HID, b1, nullptr, nullptr);
    // 9) out = x1 + alpha * (h @ w2 + b2)
    mma_gemm<128,128,64,32,3><<<dim3(DIM/128, M_ROWS/128), 256>>>(
        HID, hbuf, HID, w2, DIM, out, DIM, b2, x1, alpha);
}

// round 3
// speedup vs baseline: 2.2813x; 1.5977x over previous
#include <cuda_runtime.h>
#include <math.h>

// Problem constants
#define BB   2
#define TT   2048
#define DIM  1024
#define NH   16
#define DK   64
#define TOPK 64
#define HID  8192
#define M_ROWS (BB*TT)           // 4096
#define NBH  (BB*NH)             // 32

// ---------------- scratch ------------------------------------------------------
__device__ float g_xn  [(size_t)M_ROWS * DIM];
__device__ float g_qkv [(size_t)M_ROWS * 3 * DIM];
__device__ float g_S   [(size_t)NBH * TT * TT];
__device__ float g_attn[(size_t)M_ROWS * DIM];
__device__ float g_x1  [(size_t)M_ROWS * DIM];
__device__ float g_xn2 [(size_t)M_ROWS * DIM];
__device__ float g_h   [(size_t)M_ROWS * HID];
// rounded weights: w_qkv(3M) | w_out(1M) | w1(8M) | w2(8M)
#define WOFF_QKV 0
#define WOFF_OUT ((size_t)DIM*3*DIM)
#define WOFF_W1  (WOFF_OUT + (size_t)DIM*DIM)
#define WOFF_W2  (WOFF_W1 + (size_t)DIM*HID)
__device__ float g_wr  [WOFF_W2 + (size_t)HID*DIM];

// ---------------- helpers ------------------------------------------------------
__device__ __forceinline__ float tf32r(float f)
{
    unsigned u;
    asm("cvt.rna.tf32.f32 %0, %1;" : "=r"(u) : "f"(f));
    return __uint_as_float(u);
}
__device__ __forceinline__ void mma8(float* c, const unsigned* a, const unsigned* b)
{
    asm volatile(
        "mma.sync.aligned.m16n8k8.row.col.f32.tf32.tf32.f32 "
        "{%0,%1,%2,%3},{%4,%5,%6,%7},{%8,%9},{%0,%1,%2,%3};\n"
        : "+f"(c[0]), "+f"(c[1]), "+f"(c[2]), "+f"(c[3])
        : "r"(a[0]), "r"(a[1]), "r"(a[2]), "r"(a[3]), "r"(b[0]), "r"(b[1]));
}
__device__ __forceinline__ void cp16(void* s, const void* g)
{
    unsigned sa = (unsigned)__cvta_generic_to_shared(s);
    asm volatile("cp.async.cg.shared.global [%0], [%1], 16;\n" :: "r"(sa), "l"(g));
}
#define CP_COMMIT() asm volatile("cp.async.commit_group;\n")

// ---------------- weight rounding (once per launch) -----------------------------
__global__ __launch_bounds__(256)
void round_copy4(const float* __restrict__ a, float* __restrict__ o, int n4)
{
    int i = blockIdx.x * 256 + threadIdx.x;
    if (i < n4) {
        float4 v = ((const float4*)a)[i];
        v.x = tf32r(v.x); v.y = tf32r(v.y); v.z = tf32r(v.z); v.w = tf32r(v.w);
        ((float4*)o)[i] = v;
    }
}

// ---------------- LayerNorm (tf32-rounded output) -------------------------------
__global__ __launch_bounds__(256)
void ln_kernel(const float* __restrict__ x, const float* __restrict__ g,
               const float* __restrict__ b, float* __restrict__ o)
{
    const int rowbase = blockIdx.x * DIM;
    const int tid = threadIdx.x;
    float v[4];
    float s = 0.f, s2 = 0.f;
#pragma unroll
    for (int i = 0; i < 4; i++) {
        v[i] = x[rowbase + tid + i * 256];
        s  += v[i];
        s2 += v[i] * v[i];
    }
    __shared__ float r1[256], r2[256];
    r1[tid] = s; r2[tid] = s2; __syncthreads();
    for (int st = 128; st > 0; st >>= 1) {
        if (tid < st) { r1[tid] += r1[tid + st]; r2[tid] += r2[tid + st]; }
        __syncthreads();
    }
    const float mu   = r1[0] * (1.f / DIM);
    const float var  = r2[0] * (1.f / DIM) - mu * mu;
    const float rstd = rsqrtf(var + 1e-5f);
#pragma unroll
    for (int i = 0; i < 4; i++) {
        int c = tid + i * 256;
        o[rowbase + c] = tf32r((v[i] - mu) * rstd * g[c] + b[c]);
    }
}

// ---------------- pipelined tf32 GEMM (cp.async, 3 stages) ----------------------
// C[M,N] = A[M,K](row, pre-rounded) @ B[K,N](row, pre-rounded)
// EPI: 0 plain | 1 resid+alpha*acc | 2 gelu(acc+bias) | 3 resid+alpha*(acc+bias)
// RND: round stored value to tf32 (when consumed by another GEMM)
#define G_BM 128
#define G_BN 128
#define G_BK 32
#define G_AS (G_BM*(G_BK+4))      // floats per A stage: 4608
#define G_BS (G_BK*(G_BN+8))      // floats per B stage: 4352
#define G_SMEM (3*(G_AS+G_BS)*4)  // bytes

template <int EPI, bool RND>
__global__ __launch_bounds__(256, 2)
void mma_gemm2(int K,
               const float* __restrict__ A, int lda,
               const float* __restrict__ B, int ldb,
               float* __restrict__ C, int ldc,
               const float* __restrict__ bias,
               const float* __restrict__ resid,
               const float* __restrict__ alphap)
{
    constexpr int WM = 64, WN = 32, MT = 4, NT = 4, WGN = 4;
    extern __shared__ float sm[];
    float (*As)[G_BM][G_BK + 4] = (float(*)[G_BM][G_BK + 4])sm;
    float (*Bs)[G_BK][G_BN + 8] = (float(*)[G_BK][G_BN + 8])(sm + 3 * G_AS);

    const int tid = threadIdx.x, lane = tid & 31, warp = tid >> 5;
    const int bm = blockIdx.y * G_BM, bn = blockIdx.x * G_BN;
    const int wm = (warp / WGN) * WM, wn = (warp % WGN) * WN;

    float acc[MT][NT][4];
#pragma unroll
    for (int mi = 0; mi < MT; mi++)
#pragma unroll
        for (int ni = 0; ni < NT; ni++)
#pragma unroll
            for (int q = 0; q < 4; q++) acc[mi][ni][q] = 0.f;

    const int am = tid >> 1;                 // A: 2 float4 per row pair mapping
    const int ak = (tid & 1) << 4;           // 0 or 16 (floats)
    const int bk = tid >> 5;                 // B: 8 rows per pass
    const int bn4 = (tid & 31) << 2;

    auto load_stage = [&](int st, int kt) {
        const int k0 = kt * G_BK;
        // A: 128 rows x 32 floats = 1024 float4; thread does 4 (2 rows x 2 seg)
#pragma unroll
        for (int i = 0; i < 2; i++) {
            int m = am + i * 128;            // am in 0..127, +128 wraps? no: am 0..127, i*? 
            // correct mapping below
        }
        // simple mapping: idx = tid + i*256 over 1024 float4
#pragma unroll
        for (int i = 0; i < 4; i++) {
            int idx = tid + i * 256;
            int m = idx >> 3, k4 = (idx & 7) << 2;
            cp16(&As[st][m][k4], A + (size_t)(bm + m) * lda + k0 + k4);
        }
#pragma unroll
        for (int i = 0; i < 4; i++) {
            int idx = tid + i * 256;
            int k = idx >> 5, n4 = (idx & 31) << 2;
            cp16(&Bs[st][k][n4], B + (size_t)(k0 + k) * ldb + bn + n4);
        }
    };

    const int KT = K / G_BK;
    load_stage(0, 0); CP_COMMIT();
    load_stage(1, 1); CP_COMMIT();

    for (int kt = 0; kt < KT; kt++) {
        if (kt + 2 < KT) {
            load_stage((kt + 2) % 3, kt + 2); CP_COMMIT();
            asm volatile("cp.async.wait_group 2;\n");
        } else {
            asm volatile("cp.async.wait_group 0;\n");
        }
        __syncthreads();
        const int st = kt % 3;
#pragma unroll
        for (int ks = 0; ks < G_BK / 8; ks++) {
            const int kb = ks * 8;
            unsigned af[MT][4], bf[NT][2];
#pragma unroll
            for (int mi = 0; mi < MT; mi++) {
                int m = wm + mi * 16 + (lane >> 2);
                int kk = kb + (lane & 3);
                af[mi][0] = __float_as_uint(As[st][m][kk]);
                af[mi][1] = __float_as_uint(As[st][m + 8][kk]);
                af[mi][2] = __float_as_uint(As[st][m][kk + 4]);
                af[mi][3] = __float_as_uint(As[st][m + 8][kk + 4]);
            }
#pragma unroll
            for (int ni = 0; ni < NT; ni++) {
                int n = wn + ni * 8 + (lane >> 2);
                bf[ni][0] = __float_as_uint(Bs[st][kb + (lane & 3)][n]);
                bf[ni][1] = __float_as_uint(Bs[st][kb + 4 + (lane & 3)][n]);
            }
#pragma unroll
            for (int mi = 0; mi < MT; mi++)
#pragma unroll
                for (int ni = 0; ni < NT; ni++) mma8(acc[mi][ni], af[mi], bf[ni]);
        }
        __syncthreads();
    }

    const float al = (EPI == 1 || EPI == 3) ? alphap[0] : 0.f;
#pragma unroll
    for (int mi = 0; mi < MT; mi++) {
#pragma unroll
        for (int ni = 0; ni < NT; ni++) {
            int r0 = bm + wm + mi * 16 + (lane >> 2);
            int c  = bn + wn + ni * 8 + 2 * (lane & 3);
#pragma unroll
            for (int half = 0; half < 2; half++) {
                int r = r0 + half * 8;
                size_t off = (size_t)r * ldc + c;
                float v0 = acc[mi][ni][half * 2];
                float v1 = acc[mi][ni][half * 2 + 1];
                float o0, o1;
                if (EPI == 0) {
                    o0 = v0; o1 = v1;
                } else if (EPI == 1) {
                    o0 = resid[off] + al * v0;
                    o1 = resid[off + 1] + al * v1;
                } else if (EPI == 2) {
                    float u0 = v0 + bias[c], u1 = v1 + bias[c + 1];
                    o0 = 0.5f * u0 * (1.f + erff(u0 * 0.70710678118654752440f));
                    o1 = 0.5f * u1 * (1.f + erff(u1 * 0.70710678118654752440f));
                } else {
                    o0 = resid[off] + al * (v0 + bias[c]);
                    o1 = resid[off + 1] + al * (v1 + bias[c + 1]);
                }
                if (RND) { o0 = tf32r(o0); o1 = tf32r(o1); }
                *(float2*)(C + off) = make_float2(o0, o1);
            }
        }
    }
}

// ---------------- batched QK^T (tf32 MMA): S = Q @ K^T / 8 ----------------------
__global__ __launch_bounds__(256)
void mma_qk(const float* __restrict__ qkv, float* __restrict__ S)
{
    constexpr int BM = 128, BN = 128, BK = 32, WM = 64, WN = 32;
    constexpr int MT = WM / 16, NT = WN / 8, WGN = BN / WN;
    __shared__ float As[BM][BK + 4];
    __shared__ float Bs[BK][BN + 8];

    const int bh = blockIdx.z;
    const int b = bh >> 4, h = bh & 15;
    const float* Q  = qkv + (size_t)b * TT * (3 * DIM) + h * DK;
    const float* Kp = qkv + (size_t)b * TT * (3 * DIM) + DIM + h * DK;
    float* Sp = S + (size_t)bh * TT * TT;

    const int tid = threadIdx.x, lane = tid & 31, warp = tid >> 5;
    const int bm = blockIdx.y * BM, bn = blockIdx.x * BN;
    const int wm = (warp / WGN) * WM, wn = (warp % WGN) * WN;

    float acc[MT][NT][4];
#pragma unroll
    for (int mi = 0; mi < MT; mi++)
#pragma unroll
        for (int ni = 0; ni < NT; ni++)
#pragma unroll
            for (int q = 0; q < 4; q++) acc[mi][ni][q] = 0.f;

#pragma unroll
    for (int k0 = 0; k0 < DK; k0 += BK) {
#pragma unroll
        for (int idx = tid; idx < BM * 8; idx += 256) {
            int m = idx >> 3, k4 = (idx & 7) << 2;
            float4 v = *(const float4*)(Q + (size_t)(bm + m) * (3 * DIM) + k0 + k4);
            *(float4*)&As[m][k4] = v;
        }
#pragma unroll
        for (int idx = tid; idx < BN * 8; idx += 256) {
            int n = idx >> 3, k4 = (idx & 7) << 2;
            float4 v = *(const float4*)(Kp + (size_t)(bn + n) * (3 * DIM) + k0 + k4);
            Bs[k4 + 0][n] = v.x;
            Bs[k4 + 1][n] = v.y;
            Bs[k4 + 2][n] = v.z;
            Bs[k4 + 3][n] = v.w;
        }
        __syncthreads();
#pragma unroll
        for (int ks = 0; ks < BK / 8; ks++) {
            const int kb = ks * 8;
            unsigned af[MT][4], bf[NT][2];
#pragma unroll
            for (int mi = 0; mi < MT; mi++) {
                int m = wm + mi * 16 + (lane >> 2);
                int kk = kb + (lane & 3);
                af[mi][0] = __float_as_uint(As[m][kk]);
                af[mi][1] = __float_as_uint(As[m + 8][kk]);
                af[mi][2] = __float_as_uint(As[m][kk + 4]);
                af[mi][3] = __float_as_uint(As[m + 8][kk + 4]);
            }
#pragma unroll
            for (int ni = 0; ni < NT; ni++) {
                int n = wn + ni * 8 + (lane >> 2);
                bf[ni][0] = __float_as_uint(Bs[kb + (lane & 3)][n]);
                bf[ni][1] = __float_as_uint(Bs[kb + 4 + (lane & 3)][n]);
            }
#pragma unroll
            for (int mi = 0; mi < MT; mi++)
#pragma unroll
                for (int ni = 0; ni < NT; ni++) mma8(acc[mi][ni], af[mi], bf[ni]);
        }
        __syncthreads();
    }

#pragma unroll
    for (int mi = 0; mi < MT; mi++)
#pragma unroll
        for (int ni = 0; ni < NT; ni++) {
            int r0 = bm + wm + mi * 16 + (lane >> 2);
            int c  = bn + wn + ni * 8 + 2 * (lane & 3);
#pragma unroll
            for (int half = 0; half < 2; half++) {
                size_t off = (size_t)(r0 + half * 8) * TT + c;
                *(float2*)(Sp + off) = make_float2(acc[mi][ni][half * 2] * 0.125f,
                                                   acc[mi][ni][half * 2 + 1] * 0.125f);
            }
        }
}

// ---------------- batched PV (tf32 MMA, cp.async 3-stage) ------------------------
#define P_AS (128*(32+4))
#define P_BS (32*(64+8))
#define P_SMEM (3*(P_AS+P_BS)*4)

__global__ __launch_bounds__(256, 2)
void mma_pv(const float* __restrict__ S, const float* __restrict__ qkv,
            float* __restrict__ attn_out)
{
    constexpr int BM = 128, BN = 64, BK = 32, WM = 32, WN = 32;
    constexpr int MT = 2, NT = 4, WGN = 2;
    extern __shared__ float sm[];
    float (*As)[BM][BK + 4] = (float(*)[BM][BK + 4])sm;
    float (*Bs)[BK][BN + 8] = (float(*)[BK][BN + 8])(sm + 3 * P_AS);

    const int bh = blockIdx.y;
    const int b = bh >> 4, h = bh & 15;
    const float* P  = S + (size_t)bh * TT * TT;
    const float* Vp = qkv + (size_t)b * TT * (3 * DIM) + 2 * DIM + h * DK;

    const int tid = threadIdx.x, lane = tid & 31, warp = tid >> 5;
    const int bm = blockIdx.x * BM;
    const int wm = (warp / WGN) * WM, wn = (warp % WGN) * WN;

    float acc[MT][NT][4];
#pragma unroll
    for (int mi = 0; mi < MT; mi++)
#pragma unroll
        for (int ni = 0; ni < NT; ni++)
#pragma unroll
            for (int q = 0; q < 4; q++) acc[mi][ni][q] = 0.f;

    auto load_stage = [&](int st, int kt) {
        const int k0 = kt * BK;
#pragma unroll
        for (int i = 0; i < 4; i++) {
            int idx = tid + i * 256;
            int m = idx >> 3, k4 = (idx & 7) << 2;
            cp16(&As[st][m][k4], P + (size_t)(bm + m) * TT + k0 + k4);
        }
        {
            int idx = tid;                       // 512 float4 over 256 threads x2
#pragma unroll
            for (int i = 0; i < 2; i++) {
                int id2 = idx + i * 256;
                int k = id2 >> 4, n4 = (id2 & 15) << 2;
                cp16(&Bs[st][k][n4], Vp + (size_t)(k0 + k) * (3 * DIM) + n4);
            }
        }
    };

    const int KT = TT / BK;                      // 64
    load_stage(0, 0); CP_COMMIT();
    load_stage(1, 1); CP_COMMIT();

    for (int kt = 0; kt < KT; kt++) {
        if (kt + 2 < KT) {
            load_stage((kt + 2) % 3, kt + 2); CP_COMMIT();
            asm volatile("cp.async.wait_group 2;\n");
        } else {
            asm volatile("cp.async.wait_group 0;\n");
        }
        __syncthreads();
        const int st = kt % 3;
#pragma unroll
        for (int ks = 0; ks < BK / 8; ks++) {
            const int kb = ks * 8;
            unsigned af[MT][4], bf[NT][2];
#pragma unroll
            for (int mi = 0; mi < MT; mi++) {
                int m = wm + mi * 16 + (lane >> 2);
                int kk = kb + (lane & 3);
                af[mi][0] = __float_as_uint(As[st][m][kk]);
                af[mi][1] = __float_as_uint(As[st][m + 8][kk]);
                af[mi][2] = __float_as_uint(As[st][m][kk + 4]);
                af[mi][3] = __float_as_uint(As[st][m + 8][kk + 4]);
            }
#pragma unroll
            for (int ni = 0; ni < NT; ni++) {
                int n = wn + ni * 8 + (lane >> 2);
                bf[ni][0] = __float_as_uint(Bs[st][kb + (lane & 3)][n]);
                bf[ni][1] = __float_as_uint(Bs[st][kb + 4 + (lane & 3)][n]);
            }
#pragma unroll
            for (int mi = 0; mi < MT; mi++)
#pragma unroll
                for (int ni = 0; ni < NT; ni++) mma8(acc[mi][ni], af[mi], bf[ni]);
        }
        __syncthreads();
    }

#pragma unroll
    for (int mi = 0; mi < MT; mi++)
#pragma unroll
        for (int ni = 0; ni < NT; ni++) {
            int r0 = bm + wm + mi * 16 + (lane >> 2);
            int c  = wn + ni * 8 + 2 * (lane & 3);
#pragma unroll
            for (int half = 0; half < 2; half++) {
                int r = r0 + half * 8;
                size_t off = (size_t)(b * TT + r) * DIM + h * DK + c;
                *(float2*)(attn_out + off) = make_float2(tf32r(acc[mi][ni][half * 2]),
                                                         tf32r(acc[mi][ni][half * 2 + 1]));
            }
        }
}

// ---------------- fused dual softmax + exact top-64 -----------------------------
__device__ __forceinline__ unsigned int ordkey(float f)
{
    unsigned int u = __float_as_uint(f);
    return (u & 0x80000000u) ? ~u : (u | 0x80000000u);
}

__global__ __launch_bounds__(256)
void softmax_topk_kernel(float* __restrict__ S, const float* __restrict__ alpha_head)
{
    __shared__ float vals[TT];
    __shared__ float red[256];
    __shared__ float red2[256];
    __shared__ int   hist[256];
    __shared__ unsigned char keep[TT];
    __shared__ int   sel[2];

    const int tid = threadIdx.x;
    const int rowid = blockIdx.x;
    const int h = (rowid >> 11) & 15;
    float* row = S + (size_t)rowid * TT;

    float lmax = -3.4e38f;
    for (int j = tid; j < TT; j += 256) {
        float v = row[j];
        vals[j] = v;
        lmax = fmaxf(lmax, v);
    }
    red[tid] = lmax; __syncthreads();
    for (int s = 128; s > 0; s >>= 1) { if (tid < s) red[tid] = fmaxf(red[tid], red[tid + s]); __syncthreads(); }
    const float m = red[0];
    __syncthreads();

    unsigned int prefix = 0u, pmask = 0u;
    int kth = TOPK;
    for (int shift = 24; shift >= 0; shift -= 8) {
        hist[tid] = 0;
        __syncthreads();
        for (int j = tid; j < TT; j += 256) {
            unsigned int u = ordkey(vals[j]);
            if ((u & pmask) == prefix) atomicAdd(&hist[(u >> shift) & 255], 1);
        }
        __syncthreads();
        if (tid == 0) {
            int c = 0, bsel = 0;
            for (int bb = 255; bb >= 0; bb--) {
                int nc = c + hist[bb];
                if (nc >= kth) { bsel = bb; break; }
                c = nc;
            }
            sel[0] = bsel; sel[1] = c;
        }
        __syncthreads();
        prefix |= ((unsigned int)sel[0]) << shift;
        pmask  |= 0xFFu << shift;
        kth    -= sel[1];
        __syncthreads();
    }
    const unsigned int thr = prefix;

    int lgt = 0, leq = 0;
    for (int j = tid; j < TT; j += 256) {
        unsigned int u = ordkey(vals[j]);
        unsigned char kf = (u > thr) ? 1 : ((u == thr) ? 2 : 0);
        keep[j] = kf;
        lgt += (kf == 1);
        leq += (kf == 2);
    }
    red[tid] = (float)lgt; red2[tid] = (float)leq; __syncthreads();
    for (int s = 128; s > 0; s >>= 1) {
        if (tid < s) { red[tid] += red[tid + s]; red2[tid] += red2[tid + s]; }
        __syncthreads();
    }
    const int n_gt = (int)red[0];
    const int n_eq = (int)red2[0];
    __syncthreads();

    const int need = TOPK - n_gt;
    if (need == n_eq) {
        for (int j = tid; j < TT; j += 256) if (keep[j] == 2) keep[j] = 1;
    } else if (tid == 0) {
        int taken = 0;
        for (int j = 0; j < TT; j++) {
            if (keep[j] == 2) { keep[j] = (taken < need) ? 1 : 0; taken++; }
        }
    }
    __syncthreads();

    float sd = 0.f, ss = 0.f;
    for (int j = tid; j < TT; j += 256) {
        float e = __expf(vals[j] - m);
        vals[j] = e;
        sd += e;
        if (keep[j]) ss += e;
    }
    red[tid] = sd; red2[tid] = ss; __syncthreads();
    for (int s = 128; s > 0; s >>= 1) {
        if (tid < s) { red[tid] += red[tid + s]; red2[tid] += red2[tid + s]; }
        __syncthreads();
    }
    const float Zd = red[0];
    const float Zs = red2[0];

    const float gate = 1.f / (1.f + __expf(-alpha_head[h]));
    const float cd = gate / Zd;
    const float cs = (1.f - gate) / Zs;
    for (int j = tid; j < TT; j += 256) {
        float e = vals[j];
        row[j] = tf32r(e * (cd + (keep[j] ? cs : 0.f)));   // rounded: PV consumes via cp.async
    }
}

// ---------------- launch --------------------------------------------------------
extern "C" void kernel_launch(void* const* d_in, const int* in_sizes, int n_in,
                              void* d_out, int out_size)
{
    const float* x          = (const float*)d_in[0];
    const float* ln1_g      = (const float*)d_in[1];
    const float* ln1_b      = (const float*)d_in[2];
    const float* w_qkv      = (const float*)d_in[3];
    const float* alpha_head = (const float*)d_in[4];
    const float* w_out      = (const float*)d_in[5];
    const float* ln2_g      = (const float*)d_in[6];
    const float* ln2_b      = (const float*)d_in[7];
    const float* w1         = (const float*)d_in[8];
    const float* b1         = (const float*)d_in[9];
    const float* w2         = (const float*)d_in[10];
    const float* b2         = (const float*)d_in[11];
    const float* alpha      = (const float*)d_in[12];
    float* out = (float*)d_out;

    float *xn, *qkv, *Sm, *attn, *x1, *xn2, *hbuf, *wr;
    cudaGetSymbolAddress((void**)&xn,   g_xn);
    cudaGetSymbolAddress((void**)&qkv,  g_qkv);
    cudaGetSymbolAddress((void**)&Sm,   g_S);
    cudaGetSymbolAddress((void**)&attn, g_attn);
    cudaGetSymbolAddress((void**)&x1,   g_x1);
    cudaGetSymbolAddress((void**)&xn2,  g_xn2);
    cudaGetSymbolAddress((void**)&hbuf, g_h);
    cudaGetSymbolAddress((void**)&wr,   g_wr);

    cudaFuncSetAttribute(mma_gemm2<0,true>,  cudaFuncAttributeMaxDynamicSharedMemorySize, G_SMEM);
    cudaFuncSetAttribute(mma_gemm2<1,false>, cudaFuncAttributeMaxDynamicSharedMemorySize, G_SMEM);
    cudaFuncSetAttribute(mma_gemm2<2,true>,  cudaFuncAttributeMaxDynamicSharedMemorySize, G_SMEM);
    cudaFuncSetAttribute(mma_gemm2<3,false>, cudaFuncAttributeMaxDynamicSharedMemorySize, G_SMEM);
    cudaFuncSetAttribute(mma_pv, cudaFuncAttributeMaxDynamicSharedMemorySize, P_SMEM);

    // 0) round weights to tf32 once per launch
    {
        int n;
        n = DIM * 3 * DIM / 4; round_copy4<<<(n + 255) / 256, 256>>>(w_qkv, wr + WOFF_QKV, n);
        n = DIM * DIM / 4;     round_copy4<<<(n + 255) / 256, 256>>>(w_out, wr + WOFF_OUT, n);
        n = DIM * HID / 4;     round_copy4<<<(n + 255) / 256, 256>>>(w1,    wr + WOFF_W1,  n);
        n = HID * DIM / 4;     round_copy4<<<(n + 255) / 256, 256>>>(w2,    wr + WOFF_W2,  n);
    }

    // 1) LN1 (tf32-rounded out)
    ln_kernel<<<M_ROWS, 256>>>(x, ln1_g, ln1_b, xn);
    // 2) QKV GEMM (rounded out)
    mma_gemm2<0,true><<<dim3(3*DIM/G_BN, M_ROWS/G_BM), 256, G_SMEM>>>(
        DIM, xn, DIM, wr + WOFF_QKV, 3*DIM, qkv, 3*DIM, nullptr, nullptr, nullptr);
    // 3) S = QK^T/8
    mma_qk<<<dim3(TT/128, TT/128, NBH), 256>>>(qkv, Sm);
    // 4) fused dual softmax + exact top-64 (rounded P out)
    softmax_topk_kernel<<<NBH*TT, 256>>>(Sm, alpha_head);
    // 5) attn = P @ V (rounded out)
    mma_pv<<<dim3(TT/128, NBH), 256, P_SMEM>>>(Sm, qkv, attn);
    // 6) x1 = x + alpha * (attn @ w_out)
    mma_gemm2<1,false><<<dim3(DIM/G_BN, M_ROWS/G_BM), 256, G_SMEM>>>(
        DIM, attn, DIM, wr + WOFF_OUT, DIM, x1, DIM, nullptr, x, alpha);
    // 7) LN2 (rounded out)
    ln_kernel<<<M_ROWS, 256>>>(x1, ln2_g, ln2_b, xn2);
    // 8) h = gelu(xn2 @ w1 + b1) (rounded out)
    mma_gemm2<2,true><<<dim3(HID/G_BN, M_ROWS/G_BM), 256, G_SMEM>>>(
        DIM, xn2, DIM, wr + WOFF_W1, HID, hbuf, HID, b1, nullptr, nullptr);
    // 9) out = x1 + alpha * (h @ w2 + b2)
    mma_gemm2<3,false><<<dim3(DIM/G_BN, M_ROWS/G_BM), 256, G_SMEM>>>(
        HID, hbuf, HID, wr + WOFF_W2, DIM, out, DIM, b2, x1, alpha);
}

// round 5
// speedup vs baseline: 2.9767x; 1.3048x over previous
#include <cuda_runtime.h>
#include <cuda_fp16.h>
#include <math.h>
#include <stdint.h>

// Problem constants
#define BB   2
#define TT   2048
#define DIM  1024
#define NH   16
#define DK   64
#define TOPK 64
#define HID  8192
#define M_ROWS (BB*TT)           // 4096
#define NBH  (BB*NH)             // 32

// ---------------- scratch ------------------------------------------------------
__device__ __half g_xn  [(size_t)M_ROWS * DIM];          // LN1 out (half)
__device__ __half g_qkv [(size_t)M_ROWS * 3 * DIM];      // QKV (half)
__device__ float  g_S   [(size_t)NBH * TT * TT];         // scores fp32 (512MB)
__device__ __half g_P   [(size_t)NBH * TT * TT];         // combined probs (256MB)
__device__ __half g_vt  [(size_t)NBH * DK * TT];         // V transposed [bh][d][t]
__device__ __half g_attn[(size_t)M_ROWS * DIM];          // attn out (half)
__device__ float  g_x1  [(size_t)M_ROWS * DIM];          // resid1 fp32
__device__ __half g_xn2 [(size_t)M_ROWS * DIM];          // LN2 out (half)
__device__ __half g_h   [(size_t)M_ROWS * HID];          // FFN hidden (half)
// transposed half weights [N][K]
__device__ __half g_wqkvT[(size_t)3 * DIM * DIM];
__device__ __half g_woutT[(size_t)DIM * DIM];
__device__ __half g_w1T  [(size_t)HID * DIM];
__device__ __half g_w2T  [(size_t)DIM * HID];

// ---------------- helpers ------------------------------------------------------
__device__ __forceinline__ void hmma(float* c, const unsigned* a, const unsigned* b)
{
    asm volatile(
        "mma.sync.aligned.m16n8k16.row.col.f32.f16.f16.f32 "
        "{%0,%1,%2,%3},{%4,%5,%6,%7},{%8,%9},{%0,%1,%2,%3};\n"
        : "+f"(c[0]), "+f"(c[1]), "+f"(c[2]), "+f"(c[3])
        : "r"(a[0]), "r"(a[1]), "r"(a[2]), "r"(a[3]), "r"(b[0]), "r"(b[1]));
}
__device__ __forceinline__ void cp16s(unsigned saddr, const void* g)
{
    asm volatile("cp.async.cg.shared.global [%0], [%1], 16;\n" :: "r"(saddr), "l"(g));
}
#define CP_COMMIT() asm volatile("cp.async.commit_group;\n")

// ---------------- weight transpose fp32 -> half [C][R] --------------------------
__global__ __launch_bounds__(256)
void trk(const float* __restrict__ src, __half* __restrict__ dst, int R, int C)
{
    __shared__ float t[32][33];
    const int c0 = blockIdx.x * 32, r0 = blockIdx.y * 32;
    const int x = threadIdx.x, y = threadIdx.y;
#pragma unroll
    for (int j = 0; j < 32; j += 8)
        t[y + j][x] = src[(size_t)(r0 + y + j) * C + c0 + x];
    __syncthreads();
#pragma unroll
    for (int j = 0; j < 32; j += 8)
        dst[(size_t)(c0 + y + j) * R + r0 + x] = __float2half_rn(t[x][y + j]);
}

// ---------------- V transpose: qkv half -> vt[bh][d][t] -------------------------
__global__ __launch_bounds__(256)
void vtrans(const __half* __restrict__ qkv, __half* __restrict__ vt)
{
    __shared__ __half t[32][33];
    const int bh = blockIdx.z, b = bh >> 4, h = bh & 15;
    const int t0 = blockIdx.x * 32, d0 = blockIdx.y * 32;
    const int x = threadIdx.x, y = threadIdx.y;
#pragma unroll
    for (int j = 0; j < 32; j += 8)
        t[y + j][x] = qkv[(size_t)(b * TT + t0 + y + j) * (3 * DIM) + 2 * DIM + h * DK + d0 + x];
    __syncthreads();
#pragma unroll
    for (int j = 0; j < 32; j += 8)
        vt[((size_t)bh * DK + d0 + y + j) * TT + t0 + x] = t[x][y + j];
}

// ---------------- LayerNorm (half output) ---------------------------------------
__global__ __launch_bounds__(256)
void ln_kernel(const float* __restrict__ x, const float* __restrict__ g,
               const float* __restrict__ b, __half* __restrict__ o)
{
    const int rowbase = blockIdx.x * DIM;
    const int tid = threadIdx.x;
    float v[4];
    float s = 0.f, s2 = 0.f;
#pragma unroll
    for (int i = 0; i < 4; i++) {
        v[i] = x[rowbase + tid + i * 256];
        s  += v[i];
        s2 += v[i] * v[i];
    }
    __shared__ float r1[256], r2[256];
    r1[tid] = s; r2[tid] = s2; __syncthreads();
    for (int st = 128; st > 0; st >>= 1) {
        if (tid < st) { r1[tid] += r1[tid + st]; r2[tid] += r2[tid + st]; }
        __syncthreads();
    }
    const float mu   = r1[0] * (1.f / DIM);
    const float var  = r2[0] * (1.f / DIM) - mu * mu;
    const float rstd = rsqrtf(var + 1e-5f);
#pragma unroll
    for (int i = 0; i < 4; i++) {
        int c = tid + i * 256;
        o[rowbase + c] = __float2half_rn((v[i] - mu) * rstd * g[c] + b[c]);
    }
}

// ---------------- fp16 pipelined GEMM (cp.async, 3 stages) ----------------------
// C[M,N] = A[M,K](half,row) @ Bt[N,K](half)^T.  256 threads, BM=BN=128, BK=32.
// EPI: 0 plain->half | 1 resid+a*acc->f32 | 2 gelu(acc+bias)->half | 3 resid+a*(acc+bias)->f32
#define H_LDA 40                      // halves per smem row (32 + 8 pad)
#define H_TILE (128*H_LDA)            // halves per tile
#define H_SMEM (3*2*H_TILE*2)         // bytes: 61440

template <int EPI>
__global__ __launch_bounds__(256, 2)
void hgemm(int K,
           const __half* __restrict__ A, int lda,
           const __half* __restrict__ Bt,
           void* __restrict__ Cv, int ldc,
           const float* __restrict__ bias,
           const float* __restrict__ resid,
           const float* __restrict__ alphap)
{
    constexpr bool HOUT = (EPI == 0 || EPI == 2);
    extern __shared__ __half smh[];
    const unsigned sbase = (unsigned)__cvta_generic_to_shared(smh);

    const int tid = threadIdx.x, lane = tid & 31, warp = tid >> 5;
    const int g = lane >> 2, tq = lane & 3;
    const int bm = blockIdx.y * 128, bn = blockIdx.x * 128;
    const int wm = (warp >> 2) * 64, wn = (warp & 3) * 32;   // 2x4 warps, 64x32 tiles

    float acc[4][4][4];
#pragma unroll
    for (int mi = 0; mi < 4; mi++)
#pragma unroll
        for (int ni = 0; ni < 4; ni++)
#pragma unroll
            for (int q = 0; q < 4; q++) acc[mi][ni][q] = 0.f;

    auto load_stage = [&](int i) {
        const int s = i % 3;
        const unsigned sA = sbase + (unsigned)(s * H_TILE * 2);
        const unsigned sB = sbase + (unsigned)((3 + s) * H_TILE * 2);
        const __half* Ap = A + (size_t)bm * lda + i * 32;
        const __half* Bp = Bt + (size_t)bn * K + i * 32;
#pragma unroll
        for (int j = 0; j < 2; j++) {
            int idx = tid + j * 256;
            int row = idx >> 2, seg = (idx & 3) << 4;     // byte seg 0/16/32/48
            cp16s(sA + row * (H_LDA * 2) + seg, Ap + (size_t)row * lda + (seg >> 1));
            cp16s(sB + row * (H_LDA * 2) + seg, Bp + (size_t)row * K + (seg >> 1));
        }
        CP_COMMIT();
    };

    const int KT = K / 32;
    load_stage(0);
    load_stage(1);

    for (int kt = 0; kt < KT; kt++) {
        if (kt + 1 < KT) asm volatile("cp.async.wait_group 1;\n" ::: "memory");
        else             asm volatile("cp.async.wait_group 0;\n" ::: "memory");
        __syncthreads();
        const int s = kt % 3;
        const __half* As = smh + s * H_TILE;
        const __half* Bs = smh + (3 + s) * H_TILE;
#pragma unroll
        for (int ks = 0; ks < 2; ks++) {
            const int kb = ks * 16;
            unsigned af[4][4], bf[4][2];
#pragma unroll
            for (int mi = 0; mi < 4; mi++) {
                int m = wm + mi * 16 + g;
                const __half* p0 = As + m * H_LDA + kb + 2 * tq;
                af[mi][0] = *(const unsigned*)(p0);
                af[mi][1] = *(const unsigned*)(p0 + 8 * H_LDA);
                af[mi][2] = *(const unsigned*)(p0 + 8);
                af[mi][3] = *(const unsigned*)(p0 + 8 * H_LDA + 8);
            }
#pragma unroll
            for (int ni = 0; ni < 4; ni++) {
                int n = wn + ni * 8 + g;
                const __half* p0 = Bs + n * H_LDA + kb + 2 * tq;
                bf[ni][0] = *(const unsigned*)(p0);
                bf[ni][1] = *(const unsigned*)(p0 + 8);
            }
#pragma unroll
            for (int mi = 0; mi < 4; mi++)
#pragma unroll
                for (int ni = 0; ni < 4; ni++) hmma(acc[mi][ni], af[mi], bf[ni]);
        }
        __syncthreads();
        if (kt + 2 < KT) load_stage(kt + 2);
    }

    const float al = (EPI == 1 || EPI == 3) ? alphap[0] : 0.f;
#pragma unroll
    for (int mi = 0; mi < 4; mi++) {
#pragma unroll
        for (int ni = 0; ni < 4; ni++) {
            int r0 = bm + wm + mi * 16 + g;
            int c  = bn + wn + ni * 8 + 2 * tq;
#pragma unroll
            for (int half = 0; half < 2; half++) {
                int r = r0 + half * 8;
                size_t off = (size_t)r * ldc + c;
                float v0 = acc[mi][ni][half * 2];
                float v1 = acc[mi][ni][half * 2 + 1];
                float o0, o1;
                if (EPI == 0) {
                    o0 = v0; o1 = v1;
                } else if (EPI == 1) {
                    o0 = resid[off] + al * v0;
                    o1 = resid[off + 1] + al * v1;
                } else if (EPI == 2) {
                    float u0 = v0 + bias[c], u1 = v1 + bias[c + 1];
                    o0 = 0.5f * u0 * (1.f + erff(u0 * 0.70710678118654752440f));
                    o1 = 0.5f * u1 * (1.f + erff(u1 * 0.70710678118654752440f));
                } else {
                    o0 = resid[off] + al * (v0 + bias[c]);
                    o1 = resid[off + 1] + al * (v1 + bias[c + 1]);
                }
                if (HOUT) {
                    __half2 hv = __floats2half2_rn(o0, o1);
                    *(__half2*)((__half*)Cv + off) = hv;
                } else {
                    *(float2*)((float*)Cv + off) = make_float2(o0, o1);
                }
            }
        }
    }
}

// ---------------- batched QK^T (fp16 MMA): S = Q @ K^T / 8 ----------------------
__global__ __launch_bounds__(256)
void hqk(const __half* __restrict__ qkv, float* __restrict__ S)
{
    __shared__ __half As[128][72];     // Q rows, K=64 halves + 8 pad
    __shared__ __half Bs[128][72];     // K rows

    const int bh = blockIdx.z, b = bh >> 4, h = bh & 15;
    const __half* Q  = qkv + (size_t)b * TT * (3 * DIM) + h * DK;
    const __half* Kp = qkv + (size_t)b * TT * (3 * DIM) + DIM + h * DK;
    float* Sp = S + (size_t)bh * TT * TT;

    const int tid = threadIdx.x, lane = tid & 31, warp = tid >> 5;
    const int g = lane >> 2, tq = lane & 3;
    const int bm = blockIdx.y * 128, bn = blockIdx.x * 128;
    const int wm = (warp >> 2) * 64, wn = (warp & 3) * 32;

    float acc[4][4][4];
#pragma unroll
    for (int mi = 0; mi < 4; mi++)
#pragma unroll
        for (int ni = 0; ni < 4; ni++)
#pragma unroll
            for (int q = 0; q < 4; q++) acc[mi][ni][q] = 0.f;

    // fill smem (K=64 whole depth)
#pragma unroll
    for (int j = 0; j < 4; j++) {
        int idx = tid + j * 256;
        int m = idx >> 3, seg = (idx & 7) << 3;       // 8 halves per uint4
        *(uint4*)&As[m][seg] = *(const uint4*)(Q  + (size_t)(bm + m) * (3 * DIM) + seg);
        *(uint4*)&Bs[m][seg] = *(const uint4*)(Kp + (size_t)(bn + m) * (3 * DIM) + seg);
    }
    __syncthreads();

#pragma unroll
    for (int ks = 0; ks < 4; ks++) {
        const int kb = ks * 16;
        unsigned af[4][4], bf[4][2];
#pragma unroll
        for (int mi = 0; mi < 4; mi++) {
            int m = wm + mi * 16 + g;
            const __half* p0 = &As[m][kb + 2 * tq];
            af[mi][0] = *(const unsigned*)(p0);
            af[mi][1] = *(const unsigned*)(p0 + 8 * 72);
            af[mi][2] = *(const unsigned*)(p0 + 8);
            af[mi][3] = *(const unsigned*)(p0 + 8 * 72 + 8);
        }
#pragma unroll
        for (int ni = 0; ni < 4; ni++) {
            int n = wn + ni * 8 + g;
            const __half* p0 = &Bs[n][kb + 2 * tq];
            bf[ni][0] = *(const unsigned*)(p0);
            bf[ni][1] = *(const unsigned*)(p0 + 8);
        }
#pragma unroll
        for (int mi = 0; mi < 4; mi++)
#pragma unroll
            for (int ni = 0; ni < 4; ni++) hmma(acc[mi][ni], af[mi], bf[ni]);
    }

#pragma unroll
    for (int mi = 0; mi < 4; mi++)
#pragma unroll
        for (int ni = 0; ni < 4; ni++) {
            int r0 = bm + wm + mi * 16 + g;
            int c  = bn + wn + ni * 8 + 2 * tq;
#pragma unroll
            for (int half = 0; half < 2; half++) {
                size_t off = (size_t)(r0 + half * 8) * TT + c;
                *(float2*)(Sp + off) = make_float2(acc[mi][ni][half * 2] * 0.125f,
                                                   acc[mi][ni][half * 2 + 1] * 0.125f);
            }
        }
}

// ---------------- batched PV (fp16 MMA, cp.async 3-stage) ------------------------
// attn[b,t,h*64+d] = P[bh] @ Vt[bh]^T   (Vt is [d][t], K-major over tokens)
#define PV_SMEM ((3*128*40 + 3*64*40)*2)

__global__ __launch_bounds__(256, 2)
void hpv(const __half* __restrict__ P, const __half* __restrict__ Vt,
         __half* __restrict__ attn_out)
{
    extern __shared__ __half smh[];
    const unsigned sbase = (unsigned)__cvta_generic_to_shared(smh);
    __half* AsBase = smh;                      // 3 stages x 128 x 40
    __half* BsBase = smh + 3 * 128 * 40;       // 3 stages x 64 x 40

    const int bh = blockIdx.y, b = bh >> 4, h = bh & 15;
    const __half* Pp = P + (size_t)bh * TT * TT;
    const __half* Vp = Vt + (size_t)bh * DK * TT;

    const int tid = threadIdx.x, lane = tid & 31, warp = tid >> 5;
    const int g = lane >> 2, tq = lane & 3;
    const int bm = blockIdx.x * 128;
    const int wm = (warp >> 1) * 32, wn = (warp & 1) * 32;   // 4x2 warps, 32x32

    float acc[2][4][4];
#pragma unroll
    for (int mi = 0; mi < 2; mi++)
#pragma unroll
        for (int ni = 0; ni < 4; ni++)
#pragma unroll
            for (int q = 0; q < 4; q++) acc[mi][ni][q] = 0.f;

    auto load_stage = [&](int i) {
        const int s = i % 3;
        const unsigned sA = sbase + (unsigned)(s * 128 * 40 * 2);
        const unsigned sB = sbase + (unsigned)((3 * 128 * 40 + s * 64 * 40) * 2);
        const __half* Ap = Pp + i * 32;
        const __half* Bp = Vp + i * 32;
#pragma unroll
        for (int j = 0; j < 2; j++) {
            int idx = tid + j * 256;
            int row = idx >> 2, seg = (idx & 3) << 4;
            cp16s(sA + row * 80 + seg, Ap + (size_t)(bm + row) * TT + (seg >> 1));
        }
        {
            int row = tid >> 2, seg = (tid & 3) << 4;     // 64 rows x 4 segs = 256
            cp16s(sB + row * 80 + seg, Bp + (size_t)row * TT + (seg >> 1));
        }
        CP_COMMIT();
    };

    const int KT = TT / 32;
    load_stage(0);
    load_stage(1);

    for (int kt = 0; kt < KT; kt++) {
        if (kt + 1 < KT) asm volatile("cp.async.wait_group 1;\n" ::: "memory");
        else             asm volatile("cp.async.wait_group 0;\n" ::: "memory");
        __syncthreads();
        const int s = kt % 3;
        const __half* As = AsBase + s * 128 * 40;
        const __half* Bs = BsBase + s * 64 * 40;
#pragma unroll
        for (int ks = 0; ks < 2; ks++) {
            const int kb = ks * 16;
            unsigned af[2][4], bf[4][2];
#pragma unroll
            for (int mi = 0; mi < 2; mi++) {
                int m = wm + mi * 16 + g;
                const __half* p0 = As + m * 40 + kb + 2 * tq;
                af[mi][0] = *(const unsigned*)(p0);
                af[mi][1] = *(const unsigned*)(p0 + 8 * 40);
                af[mi][2] = *(const unsigned*)(p0 + 8);
                af[mi][3] = *(const unsigned*)(p0 + 8 * 40 + 8);
            }
#pragma unroll
            for (int ni = 0; ni < 4; ni++) {
                int n = wn + ni * 8 + g;
                const __half* p0 = Bs + n * 40 + kb + 2 * tq;
                bf[ni][0] = *(const unsigned*)(p0);
                bf[ni][1] = *(const unsigned*)(p0 + 8);
            }
#pragma unroll
            for (int mi = 0; mi < 2; mi++)
#pragma unroll
                for (int ni = 0; ni < 4; ni++) hmma(acc[mi][ni], af[mi], bf[ni]);
        }
        __syncthreads();
        if (kt + 2 < KT) load_stage(kt + 2);
    }

#pragma unroll
    for (int mi = 0; mi < 2; mi++)
#pragma unroll
        for (int ni = 0; ni < 4; ni++) {
            int r0 = bm + wm + mi * 16 + g;
            int c  = wn + ni * 8 + 2 * tq;
#pragma unroll
            for (int half = 0; half < 2; half++) {
                int r = r0 + half * 8;
                size_t off = (size_t)(b * TT + r) * DIM + h * DK + c;
                *(__half2*)(attn_out + off) =
                    __floats2half2_rn(acc[mi][ni][half * 2], acc[mi][ni][half * 2 + 1]);
            }
        }
}

// ---------------- fused dual softmax + exact top-64 -----------------------------
__device__ __forceinline__ unsigned int ordkey(float f)
{
    unsigned int u = __float_as_uint(f);
    return (u & 0x80000000u) ? ~u : (u | 0x80000000u);
}

__global__ __launch_bounds__(256)
void softmax_topk_kernel(const float* __restrict__ S, __half* __restrict__ P,
                         const float* __restrict__ alpha_head)
{
    __shared__ float vals[TT];
    __shared__ float red[256];
    __shared__ float red2[256];
    __shared__ int   hist[256];
    __shared__ unsigned char keep[TT];
    __shared__ int   sel[2];

    const int tid = threadIdx.x;
    const int rowid = blockIdx.x;
    const int h = (rowid >> 11) & 15;
    const float* row = S + (size_t)rowid * TT;
    __half* prow = P + (size_t)rowid * TT;

    float lmax = -3.4e38f;
    for (int j = tid; j < TT; j += 256) {
        float v = row[j];
        vals[j] = v;
        lmax = fmaxf(lmax, v);
    }
    red[tid] = lmax; __syncthreads();
    for (int s = 128; s > 0; s >>= 1) { if (tid < s) red[tid] = fmaxf(red[tid], red[tid + s]); __syncthreads(); }
    const float m = red[0];
    __syncthreads();

    unsigned int prefix = 0u, pmask = 0u;
    int kth = TOPK;
    for (int shift = 24; shift >= 0; shift -= 8) {
        hist[tid] = 0;
        __syncthreads();
        for (int j = tid; j < TT; j += 256) {
            unsigned int u = ordkey(vals[j]);
            if ((u & pmask) == prefix) atomicAdd(&hist[(u >> shift) & 255], 1);
        }
        __syncthreads();
        if (tid == 0) {
            int c = 0, bsel = 0;
            for (int bb = 255; bb >= 0; bb--) {
                int nc = c + hist[bb];
                if (nc >= kth) { bsel = bb; break; }
                c = nc;
            }
            sel[0] = bsel; sel[1] = c;
        }
        __syncthreads();
        prefix |= ((unsigned int)sel[0]) << shift;
        pmask  |= 0xFFu << shift;
        kth    -= sel[1];
        __syncthreads();
    }
    const unsigned int thr = prefix;

    int lgt = 0, leq = 0;
    for (int j = tid; j < TT; j += 256) {
        unsigned int u = ordkey(vals[j]);
        unsigned char kf = (u > thr) ? 1 : ((u == thr) ? 2 : 0);
        keep[j] = kf;
        lgt += (kf == 1);
        leq += (kf == 2);
    }
    red[tid] = (float)lgt; red2[tid] = (float)leq; __syncthreads();
    for (int s = 128; s > 0; s >>= 1) {
        if (tid < s) { red[tid] += red[tid + s]; red2[tid] += red2[tid + s]; }
        __syncthreads();
    }
    const int n_gt = (int)red[0];
    const int n_eq = (int)red2[0];
    __syncthreads();

    const int need = TOPK - n_gt;
    if (need == n_eq) {
        for (int j = tid; j < TT; j += 256) if (keep[j] == 2) keep[j] = 1;
    } else if (tid == 0) {
        int taken = 0;
        for (int j = 0; j < TT; j++) {
            if (keep[j] == 2) { keep[j] = (taken < need) ? 1 : 0; taken++; }
        }
    }
    __syncthreads();

    float sd = 0.f, ss = 0.f;
    for (int j = tid; j < TT; j += 256) {
        float e = __expf(vals[j] - m);
        vals[j] = e;
        sd += e;
        if (keep[j]) ss += e;
    }
    red[tid] = sd; red2[tid] = ss; __syncthreads();
    for (int s = 128; s > 0; s >>= 1) {
        if (tid < s) { red[tid] += red[tid + s]; red2[tid] += red2[tid + s]; }
        __syncthreads();
    }
    const float Zd = red[0];
    const float Zs = red2[0];

    const float gate = 1.f / (1.f + __expf(-alpha_head[h]));
    const float cd = gate / Zd;
    const float cs = (1.f - gate) / Zs;
    for (int j = tid; j < TT; j += 256) {
        float e = vals[j];
        prow[j] = __float2half_rn(e * (cd + (keep[j] ? cs : 0.f)));
    }
}

// ---------------- launch --------------------------------------------------------
extern "C" void kernel_launch(void* const* d_in, const int* in_sizes, int n_in,
                              void* d_out, int out_size)
{
    const float* x          = (const float*)d_in[0];
    const float* ln1_g      = (const float*)d_in[1];
    const float* ln1_b      = (const float*)d_in[2];
    const float* w_qkv      = (const float*)d_in[3];
    const float* alpha_head = (const float*)d_in[4];
    const float* w_out      = (const float*)d_in[5];
    const float* ln2_g      = (const float*)d_in[6];
    const float* ln2_b      = (const float*)d_in[7];
    const float* w1         = (const float*)d_in[8];
    const float* b1         = (const float*)d_in[9];
    const float* w2         = (const float*)d_in[10];
    const float* b2         = (const float*)d_in[11];
    const float* alpha      = (const float*)d_in[12];
    float* out = (float*)d_out;

    __half *xn, *qkv, *P, *vt, *attn, *xn2, *hbuf, *wqkvT, *woutT, *w1T, *w2T;
    float *Sm, *x1;
    cudaGetSymbolAddress((void**)&xn,    g_xn);
    cudaGetSymbolAddress((void**)&qkv,   g_qkv);
    cudaGetSymbolAddress((void**)&Sm,    g_S);
    cudaGetSymbolAddress((void**)&P,     g_P);
    cudaGetSymbolAddress((void**)&vt,    g_vt);
    cudaGetSymbolAddress((void**)&attn,  g_attn);
    cudaGetSymbolAddress((void**)&x1,    g_x1);
    cudaGetSymbolAddress((void**)&xn2,   g_xn2);
    cudaGetSymbolAddress((void**)&hbuf,  g_h);
    cudaGetSymbolAddress((void**)&wqkvT, g_wqkvT);
    cudaGetSymbolAddress((void**)&woutT, g_woutT);
    cudaGetSymbolAddress((void**)&w1T,   g_w1T);
    cudaGetSymbolAddress((void**)&w2T,   g_w2T);

    cudaFuncSetAttribute(hgemm<0>, cudaFuncAttributeMaxDynamicSharedMemorySize, H_SMEM);
    cudaFuncSetAttribute(hgemm<1>, cudaFuncAttributeMaxDynamicSharedMemorySize, H_SMEM);
    cudaFuncSetAttribute(hgemm<2>, cudaFuncAttributeMaxDynamicSharedMemorySize, H_SMEM);
    cudaFuncSetAttribute(hgemm<3>, cudaFuncAttributeMaxDynamicSharedMemorySize, H_SMEM);
    cudaFuncSetAttribute(hpv, cudaFuncAttributeMaxDynamicSharedMemorySize, PV_SMEM);

    // 0) weight transpose + half convert (B operands, [N][K])
    trk<<<dim3(3*DIM/32, DIM/32), dim3(32,8)>>>(w_qkv, wqkvT, DIM, 3*DIM);
    trk<<<dim3(DIM/32,   DIM/32), dim3(32,8)>>>(w_out, woutT, DIM, DIM);
    trk<<<dim3(HID/32,   DIM/32), dim3(32,8)>>>(w1,    w1T,   DIM, HID);
    trk<<<dim3(DIM/32,   HID/32), dim3(32,8)>>>(w2,    w2T,   HID, DIM);

    // 1) LN1 -> half
    ln_kernel<<<M_ROWS, 256>>>(x, ln1_g, ln1_b, xn);
    // 2) QKV GEMM -> half
    hgemm<0><<<dim3(3*DIM/128, M_ROWS/128), 256, H_SMEM>>>(
        DIM, xn, DIM, wqkvT, qkv, 3*DIM, nullptr, nullptr, nullptr);
    // 3) S = QK^T/8 -> fp32
    hqk<<<dim3(TT/128, TT/128, NBH), 256>>>(qkv, Sm);
    // 3b) V transpose
    vtrans<<<dim3(TT/32, DK/32, NBH), dim3(32,8)>>>(qkv, vt);
    // 4) fused dual softmax + exact top-64 -> half P
    softmax_topk_kernel<<<NBH*TT, 256>>>(Sm, P, alpha_head);
    // 5) attn = P @ V -> half
    hpv<<<dim3(TT/128, NBH), 256, PV_SMEM>>>(P, vt, attn);
    // 6) x1 = x + alpha * (attn @ w_out) -> fp32
    hgemm<1><<<dim3(DIM/128, M_ROWS/128), 256, H_SMEM>>>(
        DIM, attn, DIM, woutT, x1, DIM, nullptr, x, alpha);
    // 7) LN2 -> half
    ln_kernel<<<M_ROWS, 256>>>(x1, ln2_g, ln2_b, xn2);
    // 8) h = gelu(xn2 @ w1 + b1) -> half
    hgemm<2><<<dim3(HID/128, M_ROWS/128), 256, H_SMEM>>>(
        DIM, xn2, DIM, w1T, hbuf, HID, b1, nullptr, nullptr);
    // 9) out = x1 + alpha * (h @ w2 + b2) -> fp32
    hgemm<3><<<dim3(DIM/128, M_ROWS/128), 256, H_SMEM>>>(
        HID, hbuf, HID, w2T, out, DIM, b2, x1, alpha);
}

// round 6
// speedup vs baseline: 3.0655x; 1.0298x over previous
#include <cuda_runtime.h>
#include <cuda_fp16.h>
#include <math.h>
#include <stdint.h>

// Problem constants
#define BB   2
#define TT   2048
#define DIM  1024
#define NH   16
#define DK   64
#define TOPK 64
#define HID  8192
#define M_ROWS (BB*TT)           // 4096
#define NBH  (BB*NH)             // 32

// ---------------- scratch ------------------------------------------------------
__device__ __half g_xn  [(size_t)M_ROWS * DIM];
__device__ __half g_qkv [(size_t)M_ROWS * 3 * DIM];
__device__ float  g_S   [(size_t)NBH * TT * TT];
__device__ __half g_P   [(size_t)NBH * TT * TT];
__device__ __half g_vt  [(size_t)NBH * DK * TT];
__device__ __half g_attn[(size_t)M_ROWS * DIM];
__device__ float  g_x1  [(size_t)M_ROWS * DIM];
__device__ __half g_xn2 [(size_t)M_ROWS * DIM];
__device__ __half g_h   [(size_t)M_ROWS * HID];
__device__ __half g_wqkvT[(size_t)3 * DIM * DIM];
__device__ __half g_woutT[(size_t)DIM * DIM];
__device__ __half g_w1T  [(size_t)HID * DIM];
__device__ __half g_w2T  [(size_t)DIM * HID];

// ---------------- helpers ------------------------------------------------------
__device__ __forceinline__ void hmma(float* c, const unsigned* a, const unsigned* b)
{
    asm volatile(
        "mma.sync.aligned.m16n8k16.row.col.f32.f16.f16.f32 "
        "{%0,%1,%2,%3},{%4,%5,%6,%7},{%8,%9},{%0,%1,%2,%3};\n"
        : "+f"(c[0]), "+f"(c[1]), "+f"(c[2]), "+f"(c[3])
        : "r"(a[0]), "r"(a[1]), "r"(a[2]), "r"(a[3]), "r"(b[0]), "r"(b[1]));
}
__device__ __forceinline__ void ldsm_x4(unsigned* r, unsigned saddr)
{
    asm volatile("ldmatrix.sync.aligned.m8n8.x4.shared.b16 {%0,%1,%2,%3}, [%4];"
                 : "=r"(r[0]), "=r"(r[1]), "=r"(r[2]), "=r"(r[3]) : "r"(saddr));
}
__device__ __forceinline__ void ldsm_x2(unsigned* r, unsigned saddr)
{
    asm volatile("ldmatrix.sync.aligned.m8n8.x2.shared.b16 {%0,%1}, [%2];"
                 : "=r"(r[0]), "=r"(r[1]) : "r"(saddr));
}
__device__ __forceinline__ void cp16s(unsigned saddr, const void* g)
{
    asm volatile("cp.async.cg.shared.global [%0], [%1], 16;\n" :: "r"(saddr), "l"(g));
}
#define CP_COMMIT() asm volatile("cp.async.commit_group;\n")

// ---------------- weight transpose fp32 -> half [C][R] --------------------------
__global__ __launch_bounds__(256)
void trk(const float* __restrict__ src, __half* __restrict__ dst, int R, int C)
{
    __shared__ float t[32][33];
    const int c0 = blockIdx.x * 32, r0 = blockIdx.y * 32;
    const int x = threadIdx.x, y = threadIdx.y;
#pragma unroll
    for (int j = 0; j < 32; j += 8)
        t[y + j][x] = src[(size_t)(r0 + y + j) * C + c0 + x];
    __syncthreads();
#pragma unroll
    for (int j = 0; j < 32; j += 8)
        dst[(size_t)(c0 + y + j) * R + r0 + x] = __float2half_rn(t[x][y + j]);
}

// ---------------- V transpose: qkv half -> vt[bh][d][t] -------------------------
__global__ __launch_bounds__(256)
void vtrans(const __half* __restrict__ qkv, __half* __restrict__ vt)
{
    __shared__ __half t[32][33];
    const int bh = blockIdx.z, b = bh >> 4, h = bh & 15;
    const int t0 = blockIdx.x * 32, d0 = blockIdx.y * 32;
    const int x = threadIdx.x, y = threadIdx.y;
#pragma unroll
    for (int j = 0; j < 32; j += 8)
        t[y + j][x] = qkv[(size_t)(b * TT + t0 + y + j) * (3 * DIM) + 2 * DIM + h * DK + d0 + x];
    __syncthreads();
#pragma unroll
    for (int j = 0; j < 32; j += 8)
        vt[((size_t)bh * DK + d0 + y + j) * TT + t0 + x] = t[x][y + j];
}

// ---------------- LayerNorm (half output) ---------------------------------------
__global__ __launch_bounds__(256)
void ln_kernel(const float* __restrict__ x, const float* __restrict__ g,
               const float* __restrict__ b, __half* __restrict__ o)
{
    const int rowbase = blockIdx.x * DIM;
    const int tid = threadIdx.x;
    float v[4];
    float s = 0.f, s2 = 0.f;
#pragma unroll
    for (int i = 0; i < 4; i++) {
        v[i] = x[rowbase + tid + i * 256];
        s  += v[i];
        s2 += v[i] * v[i];
    }
    __shared__ float r1[256], r2[256];
    r1[tid] = s; r2[tid] = s2; __syncthreads();
    for (int st = 128; st > 0; st >>= 1) {
        if (tid < st) { r1[tid] += r1[tid + st]; r2[tid] += r2[tid + st]; }
        __syncthreads();
    }
    const float mu   = r1[0] * (1.f / DIM);
    const float var  = r2[0] * (1.f / DIM) - mu * mu;
    const float rstd = rsqrtf(var + 1e-5f);
#pragma unroll
    for (int i = 0; i < 4; i++) {
        int c = tid + i * 256;
        o[rowbase + c] = __float2half_rn((v[i] - mu) * rstd * g[c] + b[c]);
    }
}

// ---------------- fp16 pipelined GEMM (cp.async 3-stage + ldmatrix) -------------
// C[M,N] = A[M,K](half,row) @ Bt[N,K](half)^T.  256 threads, BM=BN=128, BK=32.
#define H_LDA 40
#define H_TILE (128*H_LDA)
#define H_SMEM (3*2*H_TILE*2)

template <int EPI>
__global__ __launch_bounds__(256, 2)
void hgemm(int K,
           const __half* __restrict__ A, int lda,
           const __half* __restrict__ Bt,
           void* __restrict__ Cv, int ldc,
           const float* __restrict__ bias,
           const float* __restrict__ resid,
           const float* __restrict__ alphap)
{
    constexpr bool HOUT = (EPI == 0 || EPI == 2);
    extern __shared__ __half smh[];
    const unsigned sbase = (unsigned)__cvta_generic_to_shared(smh);

    const int tid = threadIdx.x, lane = tid & 31, warp = tid >> 5;
    const int g = lane >> 2, tq = lane & 3;
    const int bm = blockIdx.y * 128, bn = blockIdx.x * 128;
    const int wm = (warp >> 2) * 64, wn = (warp & 3) * 32;

    // ldmatrix lane addressing (byte offsets within a stage)
    const unsigned aoff = ((unsigned)((lane & 15) * H_LDA) + ((lane >> 4) << 3)) * 2;
    const unsigned boff = ((unsigned)((lane & 7) * H_LDA) + (((lane >> 3) & 1) << 3)) * 2;

    float acc[4][4][4];
#pragma unroll
    for (int mi = 0; mi < 4; mi++)
#pragma unroll
        for (int ni = 0; ni < 4; ni++)
#pragma unroll
            for (int q = 0; q < 4; q++) acc[mi][ni][q] = 0.f;

    auto load_stage = [&](int i) {
        const int s = i % 3;
        const unsigned sA = sbase + (unsigned)(s * H_TILE * 2);
        const unsigned sB = sbase + (unsigned)((3 + s) * H_TILE * 2);
        const __half* Ap = A + (size_t)bm * lda + i * 32;
        const __half* Bp = Bt + (size_t)bn * K + i * 32;
#pragma unroll
        for (int j = 0; j < 2; j++) {
            int idx = tid + j * 256;
            int row = idx >> 2, seg = (idx & 3) << 4;
            cp16s(sA + row * (H_LDA * 2) + seg, Ap + (size_t)row * lda + (seg >> 1));
            cp16s(sB + row * (H_LDA * 2) + seg, Bp + (size_t)row * K + (seg >> 1));
        }
        CP_COMMIT();
    };

    const int KT = K / 32;
    load_stage(0);
    load_stage(1);

    for (int kt = 0; kt < KT; kt++) {
        if (kt + 1 < KT) asm volatile("cp.async.wait_group 1;\n" ::: "memory");
        else             asm volatile("cp.async.wait_group 0;\n" ::: "memory");
        __syncthreads();
        const int s = kt % 3;
        const unsigned aStage = sbase + (unsigned)(s * H_TILE * 2);
        const unsigned bStage = sbase + (unsigned)((3 + s) * H_TILE * 2);
#pragma unroll
        for (int ks = 0; ks < 2; ks++) {
            const unsigned kbb = (unsigned)(ks * 16 * 2);
            unsigned af[4][4], bf[4][2];
#pragma unroll
            for (int mi = 0; mi < 4; mi++)
                ldsm_x4(af[mi], aStage + (unsigned)((wm + mi * 16) * H_LDA * 2) + aoff + kbb);
#pragma unroll
            for (int ni = 0; ni < 4; ni++)
                ldsm_x2(bf[ni], bStage + (unsigned)((wn + ni * 8) * H_LDA * 2) + boff + kbb);
#pragma unroll
            for (int mi = 0; mi < 4; mi++)
#pragma unroll
                for (int ni = 0; ni < 4; ni++) hmma(acc[mi][ni], af[mi], bf[ni]);
        }
        __syncthreads();
        if (kt + 2 < KT) load_stage(kt + 2);
    }

    const float al = (EPI == 1 || EPI == 3) ? alphap[0] : 0.f;
#pragma unroll
    for (int mi = 0; mi < 4; mi++) {
#pragma unroll
        for (int ni = 0; ni < 4; ni++) {
            int r0 = bm + wm + mi * 16 + g;
            int c  = bn + wn + ni * 8 + 2 * tq;
#pragma unroll
            for (int half = 0; half < 2; half++) {
                int r = r0 + half * 8;
                size_t off = (size_t)r * ldc + c;
                float v0 = acc[mi][ni][half * 2];
                float v1 = acc[mi][ni][half * 2 + 1];
                float o0, o1;
                if (EPI == 0) {
                    o0 = v0; o1 = v1;
                } else if (EPI == 1) {
                    o0 = resid[off] + al * v0;
                    o1 = resid[off + 1] + al * v1;
                } else if (EPI == 2) {
                    float u0 = v0 + bias[c], u1 = v1 + bias[c + 1];
                    o0 = 0.5f * u0 * (1.f + erff(u0 * 0.70710678118654752440f));
                    o1 = 0.5f * u1 * (1.f + erff(u1 * 0.70710678118654752440f));
                } else {
                    o0 = resid[off] + al * (v0 + bias[c]);
                    o1 = resid[off + 1] + al * (v1 + bias[c + 1]);
                }
                if (HOUT) {
                    *(__half2*)((__half*)Cv + off) = __floats2half2_rn(o0, o1);
                } else {
                    *(float2*)((float*)Cv + off) = make_float2(o0, o1);
                }
            }
        }
    }
}

// ---------------- batched QK^T (fp16 MMA + ldmatrix): S = Q @ K^T / 8 -----------
__global__ __launch_bounds__(256)
void hqk(const __half* __restrict__ qkv, float* __restrict__ S)
{
    __shared__ __half As[128][72];
    __shared__ __half Bs[128][72];

    const int bh = blockIdx.z, b = bh >> 4, h = bh & 15;
    const __half* Q  = qkv + (size_t)b * TT * (3 * DIM) + h * DK;
    const __half* Kp = qkv + (size_t)b * TT * (3 * DIM) + DIM + h * DK;
    float* Sp = S + (size_t)bh * TT * TT;

    const int tid = threadIdx.x, lane = tid & 31, warp = tid >> 5;
    const int g = lane >> 2, tq = lane & 3;
    const int bm = blockIdx.y * 128, bn = blockIdx.x * 128;
    const int wm = (warp >> 2) * 64, wn = (warp & 3) * 32;

    const unsigned sA = (unsigned)__cvta_generic_to_shared(&As[0][0]);
    const unsigned sB = (unsigned)__cvta_generic_to_shared(&Bs[0][0]);
    const unsigned aoff = ((unsigned)((lane & 15) * 72) + ((lane >> 4) << 3)) * 2;
    const unsigned boff = ((unsigned)((lane & 7) * 72) + (((lane >> 3) & 1) << 3)) * 2;

    float acc[4][4][4];
#pragma unroll
    for (int mi = 0; mi < 4; mi++)
#pragma unroll
        for (int ni = 0; ni < 4; ni++)
#pragma unroll
            for (int q = 0; q < 4; q++) acc[mi][ni][q] = 0.f;

#pragma unroll
    for (int j = 0; j < 4; j++) {
        int idx = tid + j * 256;
        int m = idx >> 3, seg = (idx & 7) << 3;
        *(uint4*)&As[m][seg] = *(const uint4*)(Q  + (size_t)(bm + m) * (3 * DIM) + seg);
        *(uint4*)&Bs[m][seg] = *(const uint4*)(Kp + (size_t)(bn + m) * (3 * DIM) + seg);
    }
    __syncthreads();

#pragma unroll
    for (int ks = 0; ks < 4; ks++) {
        const unsigned kbb = (unsigned)(ks * 16 * 2);
        unsigned af[4][4], bf[4][2];
#pragma unroll
        for (int mi = 0; mi < 4; mi++)
            ldsm_x4(af[mi], sA + (unsigned)((wm + mi * 16) * 72 * 2) + aoff + kbb);
#pragma unroll
        for (int ni = 0; ni < 4; ni++)
            ldsm_x2(bf[ni], sB + (unsigned)((wn + ni * 8) * 72 * 2) + boff + kbb);
#pragma unroll
        for (int mi = 0; mi < 4; mi++)
#pragma unroll
            for (int ni = 0; ni < 4; ni++) hmma(acc[mi][ni], af[mi], bf[ni]);
    }

#pragma unroll
    for (int mi = 0; mi < 4; mi++)
#pragma unroll
        for (int ni = 0; ni < 4; ni++) {
            int r0 = bm + wm + mi * 16 + g;
            int c  = bn + wn + ni * 8 + 2 * tq;
#pragma unroll
            for (int half = 0; half < 2; half++) {
                size_t off = (size_t)(r0 + half * 8) * TT + c;
                *(float2*)(Sp + off) = make_float2(acc[mi][ni][half * 2] * 0.125f,
                                                   acc[mi][ni][half * 2 + 1] * 0.125f);
            }
        }
}

// ---------------- batched PV (fp16 MMA, cp.async 3-stage + ldmatrix) ------------
#define PV_SMEM ((3*128*40 + 3*64*40)*2)

__global__ __launch_bounds__(256, 2)
void hpv(const __half* __restrict__ P, const __half* __restrict__ Vt,
         __half* __restrict__ attn_out)
{
    extern __shared__ __half smh[];
    const unsigned sbase = (unsigned)__cvta_generic_to_shared(smh);

    const int bh = blockIdx.y, b = bh >> 4, h = bh & 15;
    const __half* Pp = P + (size_t)bh * TT * TT;
    const __half* Vp = Vt + (size_t)bh * DK * TT;

    const int tid = threadIdx.x, lane = tid & 31, warp = tid >> 5;
    const int g = lane >> 2, tq = lane & 3;
    const int bm = blockIdx.x * 128;
    const int wm = (warp >> 1) * 32, wn = (warp & 1) * 32;

    const unsigned aoff = ((unsigned)((lane & 15) * 40) + ((lane >> 4) << 3)) * 2;
    const unsigned boff = ((unsigned)((lane & 7) * 40) + (((lane >> 3) & 1) << 3)) * 2;

    float acc[2][4][4];
#pragma unroll
    for (int mi = 0; mi < 2; mi++)
#pragma unroll
        for (int ni = 0; ni < 4; ni++)
#pragma unroll
            for (int q = 0; q < 4; q++) acc[mi][ni][q] = 0.f;

    auto load_stage = [&](int i) {
        const int s = i % 3;
        const unsigned sA = sbase + (unsigned)(s * 128 * 40 * 2);
        const unsigned sB = sbase + (unsigned)((3 * 128 * 40 + s * 64 * 40) * 2);
        const __half* Ap = Pp + i * 32;
        const __half* Bp = Vp + i * 32;
#pragma unroll
        for (int j = 0; j < 2; j++) {
            int idx = tid + j * 256;
            int row = idx >> 2, seg = (idx & 3) << 4;
            cp16s(sA + row * 80 + seg, Ap + (size_t)(bm + row) * TT + (seg >> 1));
        }
        {
            int row = tid >> 2, seg = (tid & 3) << 4;
            cp16s(sB + row * 80 + seg, Bp + (size_t)row * TT + (seg >> 1));
        }
        CP_COMMIT();
    };

    const int KT = TT / 32;
    load_stage(0);
    load_stage(1);

    for (int kt = 0; kt < KT; kt++) {
        if (kt + 1 < KT) asm volatile("cp.async.wait_group 1;\n" ::: "memory");
        else             asm volatile("cp.async.wait_group 0;\n" ::: "memory");
        __syncthreads();
        const int s = kt % 3;
        const unsigned aStage = sbase + (unsigned)(s * 128 * 40 * 2);
        const unsigned bStage = sbase + (unsigned)((3 * 128 * 40 + s * 64 * 40) * 2);
#pragma unroll
        for (int ks = 0; ks < 2; ks++) {
            const unsigned kbb = (unsigned)(ks * 16 * 2);
            unsigned af[2][4], bf[4][2];
#pragma unroll
            for (int mi = 0; mi < 2; mi++)
                ldsm_x4(af[mi], aStage + (unsigned)((wm + mi * 16) * 40 * 2) + aoff + kbb);
#pragma unroll
            for (int ni = 0; ni < 4; ni++)
                ldsm_x2(bf[ni], bStage + (unsigned)((wn + ni * 8) * 40 * 2) + boff + kbb);
#pragma unroll
            for (int mi = 0; mi < 2; mi++)
#pragma unroll
                for (int ni = 0; ni < 4; ni++) hmma(acc[mi][ni], af[mi], bf[ni]);
        }
        __syncthreads();
        if (kt + 2 < KT) load_stage(kt + 2);
    }

#pragma unroll
    for (int mi = 0; mi < 2; mi++)
#pragma unroll
        for (int ni = 0; ni < 4; ni++) {
            int r0 = bm + wm + mi * 16 + g;
            int c  = wn + ni * 8 + 2 * tq;
#pragma unroll
            for (int half = 0; half < 2; half++) {
                int r = r0 + half * 8;
                size_t off = (size_t)(b * TT + r) * DIM + h * DK + c;
                *(__half2*)(attn_out + off) =
                    __floats2half2_rn(acc[mi][ni][half * 2], acc[mi][ni][half * 2 + 1]);
            }
        }
}

// ---------------- fused dual softmax + exact top-64 -----------------------------
__device__ __forceinline__ unsigned int ordkey(float f)
{
    unsigned int u = __float_as_uint(f);
    return (u & 0x80000000u) ? ~u : (u | 0x80000000u);
}

__global__ __launch_bounds__(256)
void softmax_topk_kernel(const float* __restrict__ S, __half* __restrict__ P,
                         const float* __restrict__ alpha_head)
{
    __shared__ float vals[TT];
    __shared__ float red[256];
    __shared__ float red2[256];
    __shared__ int   hist[256];
    __shared__ unsigned char keep[TT];
    __shared__ int   sel[2];

    const int tid = threadIdx.x;
    const int rowid = blockIdx.x;
    const int h = (rowid >> 11) & 15;
    const float* row = S + (size_t)rowid * TT;
    __half* prow = P + (size_t)rowid * TT;

    float lmax = -3.4e38f;
    for (int j = tid; j < TT; j += 256) {
        float v = row[j];
        vals[j] = v;
        lmax = fmaxf(lmax, v);
    }
    red[tid] = lmax; __syncthreads();
    for (int s = 128; s > 0; s >>= 1) { if (tid < s) red[tid] = fmaxf(red[tid], red[tid + s]); __syncthreads(); }
    const float m = red[0];
    __syncthreads();

    unsigned int prefix = 0u, pmask = 0u;
    int kth = TOPK;
    for (int shift = 24; shift >= 0; shift -= 8) {
        hist[tid] = 0;
        __syncthreads();
        for (int j = tid; j < TT; j += 256) {
            unsigned int u = ordkey(vals[j]);
            if ((u & pmask) == prefix) atomicAdd(&hist[(u >> shift) & 255], 1);
        }
        __syncthreads();
        if (tid == 0) {
            int c = 0, bsel = 0;
            for (int bb = 255; bb >= 0; bb--) {
                int nc = c + hist[bb];
                if (nc >= kth) { bsel = bb; break; }
                c = nc;
            }
            sel[0] = bsel; sel[1] = c;
        }
        __syncthreads();
        prefix |= ((unsigned int)sel[0]) << shift;
        pmask  |= 0xFFu << shift;
        kth    -= sel[1];
        __syncthreads();
    }
    const unsigned int thr = prefix;

    int lgt = 0, leq = 0;
    for (int j = tid; j < TT; j += 256) {
        unsigned int u = ordkey(vals[j]);
        unsigned char kf = (u > thr) ? 1 : ((u == thr) ? 2 : 0);
        keep[j] = kf;
        lgt += (kf == 1);
        leq += (kf == 2);
    }
    red[tid] = (float)lgt; red2[tid] = (float)leq; __syncthreads();
    for (int s = 128; s > 0; s >>= 1) {
        if (tid < s) { red[tid] += red[tid + s]; red2[tid] += red2[tid + s]; }
        __syncthreads();
    }
    const int n_gt = (int)red[0];
    const int n_eq = (int)red2[0];
    __syncthreads();

    const int need = TOPK - n_gt;
    if (need == n_eq) {
        for (int j = tid; j < TT; j += 256) if (keep[j] == 2) keep[j] = 1;
    } else if (tid == 0) {
        int taken = 0;
        for (int j = 0; j < TT; j++) {
            if (keep[j] == 2) { keep[j] = (taken < need) ? 1 : 0; taken++; }
        }
    }
    __syncthreads();

    float sd = 0.f, ss = 0.f;
    for (int j = tid; j < TT; j += 256) {
        float e = __expf(vals[j] - m);
        vals[j] = e;
        sd += e;
        if (keep[j]) ss += e;
    }
    red[tid] = sd; red2[tid] = ss; __syncthreads();
    for (int s = 128; s > 0; s >>= 1) {
        if (tid < s) { red[tid] += red[tid + s]; red2[tid] += red2[tid + s]; }
        __syncthreads();
    }
    const float Zd = red[0];
    const float Zs = red2[0];

    const float gate = 1.f / (1.f + __expf(-alpha_head[h]));
    const float cd = gate / Zd;
    const float cs = (1.f - gate) / Zs;
    for (int j = tid; j < TT; j += 256) {
        float e = vals[j];
        prow[j] = __float2half_rn(e * (cd + (keep[j] ? cs : 0.f)));
    }
}

// ---------------- launch --------------------------------------------------------
extern "C" void kernel_launch(void* const* d_in, const int* in_sizes, int n_in,
                              void* d_out, int out_size)
{
    const float* x          = (const float*)d_in[0];
    const float* ln1_g      = (const float*)d_in[1];
    const float* ln1_b      = (const float*)d_in[2];
    const float* w_qkv      = (const float*)d_in[3];
    const float* alpha_head = (const float*)d_in[4];
    const float* w_out      = (const float*)d_in[5];
    const float* ln2_g      = (const float*)d_in[6];
    const float* ln2_b      = (const float*)d_in[7];
    const float* w1         = (const float*)d_in[8];
    const float* b1         = (const float*)d_in[9];
    const float* w2         = (const float*)d_in[10];
    const float* b2         = (const float*)d_in[11];
    const float* alpha      = (const float*)d_in[12];
    float* out = (float*)d_out;

    __half *xn, *qkv, *P, *vt, *attn, *xn2, *hbuf, *wqkvT, *woutT, *w1T, *w2T;
    float *Sm, *x1;
    cudaGetSymbolAddress((void**)&xn,    g_xn);
    cudaGetSymbolAddress((void**)&qkv,   g_qkv);
    cudaGetSymbolAddress((void**)&Sm,    g_S);
    cudaGetSymbolAddress((void**)&P,     g_P);
    cudaGetSymbolAddress((void**)&vt,    g_vt);
    cudaGetSymbolAddress((void**)&attn,  g_attn);
    cudaGetSymbolAddress((void**)&x1,    g_x1);
    cudaGetSymbolAddress((void**)&xn2,   g_xn2);
    cudaGetSymbolAddress((void**)&hbuf,  g_h);
    cudaGetSymbolAddress((void**)&wqkvT, g_wqkvT);
    cudaGetSymbolAddress((void**)&woutT, g_woutT);
    cudaGetSymbolAddress((void**)&w1T,   g_w1T);
    cudaGetSymbolAddress((void**)&w2T,   g_w2T);

    cudaFuncSetAttribute(hgemm<0>, cudaFuncAttributeMaxDynamicSharedMemorySize, H_SMEM);
    cudaFuncSetAttribute(hgemm<1>, cudaFuncAttributeMaxDynamicSharedMemorySize, H_SMEM);
    cudaFuncSetAttribute(hgemm<2>, cudaFuncAttributeMaxDynamicSharedMemorySize, H_SMEM);
    cudaFuncSetAttribute(hgemm<3>, cudaFuncAttributeMaxDynamicSharedMemorySize, H_SMEM);
    cudaFuncSetAttribute(hpv, cudaFuncAttributeMaxDynamicSharedMemorySize, PV_SMEM);

    trk<<<dim3(3*DIM/32, DIM/32), dim3(32,8)>>>(w_qkv, wqkvT, DIM, 3*DIM);
    trk<<<dim3(DIM/32,   DIM/32), dim3(32,8)>>>(w_out, woutT, DIM, DIM);
    trk<<<dim3(HID/32,   DIM/32), dim3(32,8)>>>(w1,    w1T,   DIM, HID);
    trk<<<dim3(DIM/32,   HID/32), dim3(32,8)>>>(w2,    w2T,   HID, DIM);

    ln_kernel<<<M_ROWS, 256>>>(x, ln1_g, ln1_b, xn);
    hgemm<0><<<dim3(3*DIM/128, M_ROWS/128), 256, H_SMEM>>>(
        DIM, xn, DIM, wqkvT, qkv, 3*DIM, nullptr, nullptr, nullptr);
    hqk<<<dim3(TT/128, TT/128, NBH), 256>>>(qkv, Sm);
    vtrans<<<dim3(TT/32, DK/32, NBH), dim3(32,8)>>>(qkv, vt);
    softmax_topk_kernel<<<NBH*TT, 256>>>(Sm, P, alpha_head);
    hpv<<<dim3(TT/128, NBH), 256, PV_SMEM>>>(P, vt, attn);
    hgemm<1><<<dim3(DIM/128, M_ROWS/128), 256, H_SMEM>>>(
        DIM, attn, DIM, woutT, x1, DIM, nullptr, x, alpha);
    ln_kernel<<<M_ROWS, 256>>>(x1, ln2_g, ln2_b, xn2);
    hgemm<2><<<dim3(HID/128, M_ROWS/128), 256, H_SMEM>>>(
        DIM, xn2, DIM, w1T, hbuf, HID, b1, nullptr, nullptr);
    hgemm<3><<<dim3(DIM/128, M_ROWS/128), 256, H_SMEM>>>(
        HID, hbuf, HID, w2T, out, DIM, b2, x1, alpha);
}

// round 7
// speedup vs baseline: 4.9497x; 1.6147x over previous
#include <cuda_runtime.h>
#include <cuda_fp16.h>
#include <math.h>
#include <stdint.h>

// Problem constants
#define BB   2
#define TT   2048
#define DIM  1024
#define NH   16
#define DK   64
#define TOPK 64
#define HID  8192
#define M_ROWS (BB*TT)           // 4096
#define NBH  (BB*NH)             // 32

// ---------------- scratch ------------------------------------------------------
__device__ __half g_xn  [(size_t)M_ROWS * DIM];
__device__ __half g_qkv [(size_t)M_ROWS * 3 * DIM];
__device__ float  g_S   [(size_t)NBH * TT * TT];
__device__ __half g_P   [(size_t)NBH * TT * TT];
__device__ __half g_vt  [(size_t)NBH * DK * TT];
__device__ __half g_attn[(size_t)M_ROWS * DIM];
__device__ float  g_x1  [(size_t)M_ROWS * DIM];
__device__ __half g_xn2 [(size_t)M_ROWS * DIM];
__device__ __half g_h   [(size_t)M_ROWS * HID];
__device__ __half g_wqkvT[(size_t)3 * DIM * DIM];
__device__ __half g_woutT[(size_t)DIM * DIM];
__device__ __half g_w1T  [(size_t)HID * DIM];
__device__ __half g_w2T  [(size_t)DIM * HID];

// ---------------- helpers ------------------------------------------------------
__device__ __forceinline__ void hmma(float* c, const unsigned* a, const unsigned* b)
{
    asm volatile(
        "mma.sync.aligned.m16n8k16.row.col.f32.f16.f16.f32 "
        "{%0,%1,%2,%3},{%4,%5,%6,%7},{%8,%9},{%0,%1,%2,%3};\n"
        : "+f"(c[0]), "+f"(c[1]), "+f"(c[2]), "+f"(c[3])
        : "r"(a[0]), "r"(a[1]), "r"(a[2]), "r"(a[3]), "r"(b[0]), "r"(b[1]));
}
__device__ __forceinline__ void ldsm_x4(unsigned* r, unsigned saddr)
{
    asm volatile("ldmatrix.sync.aligned.m8n8.x4.shared.b16 {%0,%1,%2,%3}, [%4];"
                 : "=r"(r[0]), "=r"(r[1]), "=r"(r[2]), "=r"(r[3]) : "r"(saddr));
}
__device__ __forceinline__ void ldsm_x2(unsigned* r, unsigned saddr)
{
    asm volatile("ldmatrix.sync.aligned.m8n8.x2.shared.b16 {%0,%1}, [%2];"
                 : "=r"(r[0]), "=r"(r[1]) : "r"(saddr));
}
__device__ __forceinline__ void cp16s(unsigned saddr, const void* g)
{
    asm volatile("cp.async.cg.shared.global [%0], [%1], 16;\n" :: "r"(saddr), "l"(g));
}
#define CP_COMMIT() asm volatile("cp.async.commit_group;\n")

// ---------------- weight transpose fp32 -> half [C][R] --------------------------
__global__ __launch_bounds__(256)
void trk(const float* __restrict__ src, __half* __restrict__ dst, int R, int C)
{
    __shared__ float t[32][33];
    const int c0 = blockIdx.x * 32, r0 = blockIdx.y * 32;
    const int x = threadIdx.x, y = threadIdx.y;
#pragma unroll
    for (int j = 0; j < 32; j += 8)
        t[y + j][x] = src[(size_t)(r0 + y + j) * C + c0 + x];
    __syncthreads();
#pragma unroll
    for (int j = 0; j < 32; j += 8)
        dst[(size_t)(c0 + y + j) * R + r0 + x] = __float2half_rn(t[x][y + j]);
}

// ---------------- V transpose: qkv half -> vt[bh][d][t] -------------------------
__global__ __launch_bounds__(256)
void vtrans(const __half* __restrict__ qkv, __half* __restrict__ vt)
{
    __shared__ __half t[32][33];
    const int bh = blockIdx.z, b = bh >> 4, h = bh & 15;
    const int t0 = blockIdx.x * 32, d0 = blockIdx.y * 32;
    const int x = threadIdx.x, y = threadIdx.y;
#pragma unroll
    for (int j = 0; j < 32; j += 8)
        t[y + j][x] = qkv[(size_t)(b * TT + t0 + y + j) * (3 * DIM) + 2 * DIM + h * DK + d0 + x];
    __syncthreads();
#pragma unroll
    for (int j = 0; j < 32; j += 8)
        vt[((size_t)bh * DK + d0 + y + j) * TT + t0 + x] = t[x][y + j];
}

// ---------------- LayerNorm (half output) ---------------------------------------
__global__ __launch_bounds__(256)
void ln_kernel(const float* __restrict__ x, const float* __restrict__ g,
               const float* __restrict__ b, __half* __restrict__ o)
{
    const int rowbase = blockIdx.x * DIM;
    const int tid = threadIdx.x;
    float v[4];
    float s = 0.f, s2 = 0.f;
#pragma unroll
    for (int i = 0; i < 4; i++) {
        v[i] = x[rowbase + tid + i * 256];
        s  += v[i];
        s2 += v[i] * v[i];
    }
    __shared__ float r1[256], r2[256];
    r1[tid] = s; r2[tid] = s2; __syncthreads();
    for (int st = 128; st > 0; st >>= 1) {
        if (tid < st) { r1[tid] += r1[tid + st]; r2[tid] += r2[tid + st]; }
        __syncthreads();
    }
    const float mu   = r1[0] * (1.f / DIM);
    const float var  = r2[0] * (1.f / DIM) - mu * mu;
    const float rstd = rsqrtf(var + 1e-5f);
#pragma unroll
    for (int i = 0; i < 4; i++) {
        int c = tid + i * 256;
        o[rowbase + c] = __float2half_rn((v[i] - mu) * rstd * g[c] + b[c]);
    }
}

// ---------------- fp16 pipelined GEMM (cp.async 3-stage + ldmatrix) -------------
#define H_LDA 40
#define H_TILE (128*H_LDA)
#define H_SMEM (3*2*H_TILE*2)

template <int EPI>
__global__ __launch_bounds__(256, 2)
void hgemm(int K,
           const __half* __restrict__ A, int lda,
           const __half* __restrict__ Bt,
           void* __restrict__ Cv, int ldc,
           const float* __restrict__ bias,
           const float* __restrict__ resid,
           const float* __restrict__ alphap)
{
    constexpr bool HOUT = (EPI == 0 || EPI == 2);
    extern __shared__ __half smh[];
    const unsigned sbase = (unsigned)__cvta_generic_to_shared(smh);

    const int tid = threadIdx.x, lane = tid & 31, warp = tid >> 5;
    const int g = lane >> 2, tq = lane & 3;
    const int bm = blockIdx.y * 128, bn = blockIdx.x * 128;
    const int wm = (warp >> 2) * 64, wn = (warp & 3) * 32;

    const unsigned aoff = ((unsigned)((lane & 15) * H_LDA) + ((lane >> 4) << 3)) * 2;
    const unsigned boff = ((unsigned)((lane & 7) * H_LDA) + (((lane >> 3) & 1) << 3)) * 2;

    float acc[4][4][4];
#pragma unroll
    for (int mi = 0; mi < 4; mi++)
#pragma unroll
        for (int ni = 0; ni < 4; ni++)
#pragma unroll
            for (int q = 0; q < 4; q++) acc[mi][ni][q] = 0.f;

    auto load_stage = [&](int i) {
        const int s = i % 3;
        const unsigned sA = sbase + (unsigned)(s * H_TILE * 2);
        const unsigned sB = sbase + (unsigned)((3 + s) * H_TILE * 2);
        const __half* Ap = A + (size_t)bm * lda + i * 32;
        const __half* Bp = Bt + (size_t)bn * K + i * 32;
#pragma unroll
        for (int j = 0; j < 2; j++) {
            int idx = tid + j * 256;
            int row = idx >> 2, seg = (idx & 3) << 4;
            cp16s(sA + row * (H_LDA * 2) + seg, Ap + (size_t)row * lda + (seg >> 1));
            cp16s(sB + row * (H_LDA * 2) + seg, Bp + (size_t)row * K + (seg >> 1));
        }
        CP_COMMIT();
    };

    const int KT = K / 32;
    load_stage(0);
    load_stage(1);

    for (int kt = 0; kt < KT; kt++) {
        if (kt + 1 < KT) asm volatile("cp.async.wait_group 1;\n" ::: "memory");
        else             asm volatile("cp.async.wait_group 0;\n" ::: "memory");
        __syncthreads();
        const int s = kt % 3;
        const unsigned aStage = sbase + (unsigned)(s * H_TILE * 2);
        const unsigned bStage = sbase + (unsigned)((3 + s) * H_TILE * 2);
#pragma unroll
        for (int ks = 0; ks < 2; ks++) {
            const unsigned kbb = (unsigned)(ks * 16 * 2);
            unsigned af[4][4], bf[4][2];
#pragma unroll
            for (int mi = 0; mi < 4; mi++)
                ldsm_x4(af[mi], aStage + (unsigned)((wm + mi * 16) * H_LDA * 2) + aoff + kbb);
#pragma unroll
            for (int ni = 0; ni < 4; ni++)
                ldsm_x2(bf[ni], bStage + (unsigned)((wn + ni * 8) * H_LDA * 2) + boff + kbb);
#pragma unroll
            for (int mi = 0; mi < 4; mi++)
#pragma unroll
                for (int ni = 0; ni < 4; ni++) hmma(acc[mi][ni], af[mi], bf[ni]);
        }
        __syncthreads();
        if (kt + 2 < KT) load_stage(kt + 2);
    }

    const float al = (EPI == 1 || EPI == 3) ? alphap[0] : 0.f;
#pragma unroll
    for (int mi = 0; mi < 4; mi++) {
#pragma unroll
        for (int ni = 0; ni < 4; ni++) {
            int r0 = bm + wm + mi * 16 + g;
            int c  = bn + wn + ni * 8 + 2 * tq;
#pragma unroll
            for (int half = 0; half < 2; half++) {
                int r = r0 + half * 8;
                size_t off = (size_t)r * ldc + c;
                float v0 = acc[mi][ni][half * 2];
                float v1 = acc[mi][ni][half * 2 + 1];
                float o0, o1;
                if (EPI == 0) {
                    o0 = v0; o1 = v1;
                } else if (EPI == 1) {
                    o0 = resid[off] + al * v0;
                    o1 = resid[off + 1] + al * v1;
                } else if (EPI == 2) {
                    float u0 = v0 + bias[c], u1 = v1 + bias[c + 1];
                    o0 = 0.5f * u0 * (1.f + erff(u0 * 0.70710678118654752440f));
                    o1 = 0.5f * u1 * (1.f + erff(u1 * 0.70710678118654752440f));
                } else {
                    o0 = resid[off] + al * (v0 + bias[c]);
                    o1 = resid[off + 1] + al * (v1 + bias[c + 1]);
                }
                if (HOUT) {
                    *(__half2*)((__half*)Cv + off) = __floats2half2_rn(o0, o1);
                } else {
                    *(float2*)((float*)Cv + off) = make_float2(o0, o1);
                }
            }
        }
    }
}

// ---------------- batched QK^T (fp16 MMA + ldmatrix): S = Q @ K^T / 8 -----------
__global__ __launch_bounds__(256)
void hqk(const __half* __restrict__ qkv, float* __restrict__ S)
{
    __shared__ __half As[128][72];
    __shared__ __half Bs[128][72];

    const int bh = blockIdx.z, b = bh >> 4, h = bh & 15;
    const __half* Q  = qkv + (size_t)b * TT * (3 * DIM) + h * DK;
    const __half* Kp = qkv + (size_t)b * TT * (3 * DIM) + DIM + h * DK;
    float* Sp = S + (size_t)bh * TT * TT;

    const int tid = threadIdx.x, lane = tid & 31, warp = tid >> 5;
    const int g = lane >> 2, tq = lane & 3;
    const int bm = blockIdx.y * 128, bn = blockIdx.x * 128;
    const int wm = (warp >> 2) * 64, wn = (warp & 3) * 32;

    const unsigned sA = (unsigned)__cvta_generic_to_shared(&As[0][0]);
    const unsigned sB = (unsigned)__cvta_generic_to_shared(&Bs[0][0]);
    const unsigned aoff = ((unsigned)((lane & 15) * 72) + ((lane >> 4) << 3)) * 2;
    const unsigned boff = ((unsigned)((lane & 7) * 72) + (((lane >> 3) & 1) << 3)) * 2;

    float acc[4][4][4];
#pragma unroll
    for (int mi = 0; mi < 4; mi++)
#pragma unroll
        for (int ni = 0; ni < 4; ni++)
#pragma unroll
            for (int q = 0; q < 4; q++) acc[mi][ni][q] = 0.f;

#pragma unroll
    for (int j = 0; j < 4; j++) {
        int idx = tid + j * 256;
        int m = idx >> 3, seg = (idx & 7) << 3;
        *(uint4*)&As[m][seg] = *(const uint4*)(Q  + (size_t)(bm + m) * (3 * DIM) + seg);
        *(uint4*)&Bs[m][seg] = *(const uint4*)(Kp + (size_t)(bn + m) * (3 * DIM) + seg);
    }
    __syncthreads();

#pragma unroll
    for (int ks = 0; ks < 4; ks++) {
        const unsigned kbb = (unsigned)(ks * 16 * 2);
        unsigned af[4][4], bf[4][2];
#pragma unroll
        for (int mi = 0; mi < 4; mi++)
            ldsm_x4(af[mi], sA + (unsigned)((wm + mi * 16) * 72 * 2) + aoff + kbb);
#pragma unroll
        for (int ni = 0; ni < 4; ni++)
            ldsm_x2(bf[ni], sB + (unsigned)((wn + ni * 8) * 72 * 2) + boff + kbb);
#pragma unroll
        for (int mi = 0; mi < 4; mi++)
#pragma unroll
            for (int ni = 0; ni < 4; ni++) hmma(acc[mi][ni], af[mi], bf[ni]);
    }

#pragma unroll
    for (int mi = 0; mi < 4; mi++)
#pragma unroll
        for (int ni = 0; ni < 4; ni++) {
            int r0 = bm + wm + mi * 16 + g;
            int c  = bn + wn + ni * 8 + 2 * tq;
#pragma unroll
            for (int half = 0; half < 2; half++) {
                size_t off = (size_t)(r0 + half * 8) * TT + c;
                *(float2*)(Sp + off) = make_float2(acc[mi][ni][half * 2] * 0.125f,
                                                   acc[mi][ni][half * 2 + 1] * 0.125f);
            }
        }
}

// ---------------- batched PV (fp16 MMA, cp.async 3-stage + ldmatrix) ------------
#define PV_SMEM ((3*128*40 + 3*64*40)*2)

__global__ __launch_bounds__(256, 2)
void hpv(const __half* __restrict__ P, const __half* __restrict__ Vt,
         __half* __restrict__ attn_out)
{
    extern __shared__ __half smh[];
    const unsigned sbase = (unsigned)__cvta_generic_to_shared(smh);

    const int bh = blockIdx.y, b = bh >> 4, h = bh & 15;
    const __half* Pp = P + (size_t)bh * TT * TT;
    const __half* Vp = Vt + (size_t)bh * DK * TT;

    const int tid = threadIdx.x, lane = tid & 31, warp = tid >> 5;
    const int g = lane >> 2, tq = lane & 3;
    const int bm = blockIdx.x * 128;
    const int wm = (warp >> 1) * 32, wn = (warp & 1) * 32;

    const unsigned aoff = ((unsigned)((lane & 15) * 40) + ((lane >> 4) << 3)) * 2;
    const unsigned boff = ((unsigned)((lane & 7) * 40) + (((lane >> 3) & 1) << 3)) * 2;

    float acc[2][4][4];
#pragma unroll
    for (int mi = 0; mi < 2; mi++)
#pragma unroll
        for (int ni = 0; ni < 4; ni++)
#pragma unroll
            for (int q = 0; q < 4; q++) acc[mi][ni][q] = 0.f;

    auto load_stage = [&](int i) {
        const int s = i % 3;
        const unsigned sA = sbase + (unsigned)(s * 128 * 40 * 2);
        const unsigned sB = sbase + (unsigned)((3 * 128 * 40 + s * 64 * 40) * 2);
        const __half* Ap = Pp + i * 32;
        const __half* Bp = Vp + i * 32;
#pragma unroll
        for (int j = 0; j < 2; j++) {
            int idx = tid + j * 256;
            int row = idx >> 2, seg = (idx & 3) << 4;
            cp16s(sA + row * 80 + seg, Ap + (size_t)(bm + row) * TT + (seg >> 1));
        }
        {
            int row = tid >> 2, seg = (tid & 3) << 4;
            cp16s(sB + row * 80 + seg, Bp + (size_t)row * TT + (seg >> 1));
        }
        CP_COMMIT();
    };

    const int KT = TT / 32;
    load_stage(0);
    load_stage(1);

    for (int kt = 0; kt < KT; kt++) {
        if (kt + 1 < KT) asm volatile("cp.async.wait_group 1;\n" ::: "memory");
        else             asm volatile("cp.async.wait_group 0;\n" ::: "memory");
        __syncthreads();
        const int s = kt % 3;
        const unsigned aStage = sbase + (unsigned)(s * 128 * 40 * 2);
        const unsigned bStage = sbase + (unsigned)((3 * 128 * 40 + s * 64 * 40) * 2);
#pragma unroll
        for (int ks = 0; ks < 2; ks++) {
            const unsigned kbb = (unsigned)(ks * 16 * 2);
            unsigned af[2][4], bf[4][2];
#pragma unroll
            for (int mi = 0; mi < 2; mi++)
                ldsm_x4(af[mi], aStage + (unsigned)((wm + mi * 16) * 40 * 2) + aoff + kbb);
#pragma unroll
            for (int ni = 0; ni < 4; ni++)
                ldsm_x2(bf[ni], bStage + (unsigned)((wn + ni * 8) * 40 * 2) + boff + kbb);
#pragma unroll
            for (int mi = 0; mi < 2; mi++)
#pragma unroll
                for (int ni = 0; ni < 4; ni++) hmma(acc[mi][ni], af[mi], bf[ni]);
        }
        __syncthreads();
        if (kt + 2 < KT) load_stage(kt + 2);
    }

#pragma unroll
    for (int mi = 0; mi < 2; mi++)
#pragma unroll
        for (int ni = 0; ni < 4; ni++) {
            int r0 = bm + wm + mi * 16 + g;
            int c  = wn + ni * 8 + 2 * tq;
#pragma unroll
            for (int half = 0; half < 2; half++) {
                int r = r0 + half * 8;
                size_t off = (size_t)(b * TT + r) * DIM + h * DK + c;
                *(__half2*)(attn_out + off) =
                    __floats2half2_rn(acc[mi][ni][half * 2], acc[mi][ni][half * 2 + 1]);
            }
        }
}

// ---------------- fused dual softmax + exact top-64 (register-resident) ---------
__device__ __forceinline__ unsigned int ordkey(float f)
{
    unsigned int u = __float_as_uint(f);
    return (u & 0x80000000u) ? ~u : (u | 0x80000000u);
}
__device__ __forceinline__ float ordkey_inv(unsigned int k)
{
    return __uint_as_float((k & 0x80000000u) ? (k & 0x7FFFFFFFu) : ~k);
}

__global__ __launch_bounds__(256)
void softmax_topk2(const float* __restrict__ S, __half* __restrict__ P,
                   const float* __restrict__ alpha_head)
{
    __shared__ int   hist[256];
    __shared__ int   chunkeq[256];
    __shared__ int   chunkpre[256];
    __shared__ float rmax[8];
    __shared__ int   wri[8];
    __shared__ float wrf1[8], wrf2[8];
    __shared__ unsigned selb;
    __shared__ int   selc;

    const int tid = threadIdx.x, lane = tid & 31, w = tid >> 5;
    const int rowid = blockIdx.x;
    const int h = (rowid >> 11) & 15;
    const float* row = S + (size_t)rowid * TT;
    __half* prow = P + (size_t)rowid * TT;

    // load 8 contiguous values into registers
    float v[8];
    *(float4*)&v[0] = *(const float4*)(row + tid * 8);
    *(float4*)&v[4] = *(const float4*)(row + tid * 8 + 4);
    unsigned u[8];
    float m = -3.4e38f;
#pragma unroll
    for (int i = 0; i < 8; i++) { u[i] = ordkey(v[i]); m = fmaxf(m, v[i]); }
#pragma unroll
    for (int o = 16; o > 0; o >>= 1) m = fmaxf(m, __shfl_xor_sync(0xFFFFFFFFu, m, o));
    if (lane == 0) rmax[w] = m;
    __syncthreads();
#pragma unroll
    for (int j = 0; j < 8; j++) m = fmaxf(m, rmax[j]);

    // 4x8-bit radix select (order-preserving keys), parallel bucket pick
    unsigned prefix = 0u, pmask = 0u;
    int kth = TOPK;
#pragma unroll
    for (int shift = 24; shift >= 0; shift -= 8) {
        hist[tid] = 0;
        __syncthreads();
#pragma unroll
        for (int i = 0; i < 8; i++)
            if ((u[i] & pmask) == prefix) atomicAdd(&hist[(u[i] >> shift) & 255], 1);
        __syncthreads();
        if (w == 0) {
            const int base = lane * 8;
            int hv[8], loc[8];
            int s = 0;
#pragma unroll
            for (int j = 7; j >= 0; j--) { hv[j] = hist[base + j]; s += hv[j]; loc[j] = s; }
            int suf = s;
#pragma unroll
            for (int o = 1; o < 32; o <<= 1) {
                int t = __shfl_down_sync(0xFFFFFFFFu, suf, o);
                if (lane + o < 32) suf += t;
            }
            const int higher = suf - s;
            int cand = -1, cabove = 0;
#pragma unroll
            for (int j = 7; j >= 0; j--) {
                int cum = higher + loc[j];
                if (cum >= kth) { cand = base + j; cabove = cum - hv[j]; break; }
            }
#pragma unroll
            for (int o = 16; o > 0; o >>= 1) {
                int oc = __shfl_xor_sync(0xFFFFFFFFu, cand, o);
                int oa = __shfl_xor_sync(0xFFFFFFFFu, cabove, o);
                if (oc > cand) { cand = oc; cabove = oa; }
            }
            if (lane == 0) { selb = (unsigned)cand; selc = cabove; }
        }
        __syncthreads();
        prefix |= selb << shift;
        pmask  |= 0xFFu << shift;
        kth    -= selc;
        __syncthreads();
    }
    const unsigned thr = prefix;

    // single pass: exp, dense sum, gt-sum, counts (ties all share one exp value)
    float e[8];
    float sd = 0.f, sgt = 0.f;
    int cgt = 0, ceq = 0;
#pragma unroll
    for (int i = 0; i < 8; i++) {
        e[i] = __expf(v[i] - m);
        sd += e[i];
        if (u[i] > thr) { cgt++; sgt += e[i]; }
        else if (u[i] == thr) ceq++;
    }
    chunkeq[tid] = ceq;
#pragma unroll
    for (int o = 16; o > 0; o >>= 1) {
        sd  += __shfl_xor_sync(0xFFFFFFFFu, sd, o);
        sgt += __shfl_xor_sync(0xFFFFFFFFu, sgt, o);
        cgt += __shfl_xor_sync(0xFFFFFFFFu, cgt, o);
    }
    if (lane == 0) { wri[w] = cgt; wrf1[w] = sd; wrf2[w] = sgt; }
    __syncthreads();
    int n_gt = 0; float Zd = 0.f, Sgt = 0.f;
#pragma unroll
    for (int j = 0; j < 8; j++) { n_gt += wri[j]; Zd += wrf1[j]; Sgt += wrf2[j]; }

    const int need = TOPK - n_gt;
    const float ethr = __expf(ordkey_inv(thr) - m);
    const float Zs = Sgt + (float)need * ethr;

    // exclusive prefix of tie counts over the 256 chunks (warp0)
    if (w == 0) {
        const int base = lane * 8;
        int c[8], loc[8];
        int ex = 0;
#pragma unroll
        for (int j = 0; j < 8; j++) { c[j] = chunkeq[base + j]; loc[j] = ex; ex += c[j]; }
        int acc = ex;
#pragma unroll
        for (int o = 1; o < 32; o <<= 1) {
            int t = __shfl_up_sync(0xFFFFFFFFu, acc, o);
            if (lane >= o) acc += t;
        }
        const int wex = acc - ex;
#pragma unroll
        for (int j = 0; j < 8; j++) chunkpre[base + j] = wex + loc[j];
    }
    __syncthreads();

    const float gate = 1.f / (1.f + __expf(-alpha_head[h]));
    const float cd = gate / Zd;
    const float cs = (1.f - gate) / Zs;

    int tierank = chunkpre[tid];
    __half hs[8];
#pragma unroll
    for (int i = 0; i < 8; i++) {
        bool inc;
        if (u[i] > thr) inc = true;
        else if (u[i] == thr) { inc = (tierank < need); tierank++; }
        else inc = false;
        hs[i] = __float2half_rn(e[i] * (cd + (inc ? cs : 0.f)));
    }
    *(uint4*)(prow + tid * 8) = *(uint4*)hs;
}

// ---------------- launch --------------------------------------------------------
extern "C" void kernel_launch(void* const* d_in, const int* in_sizes, int n_in,
                              void* d_out, int out_size)
{
    const float* x          = (const float*)d_in[0];
    const float* ln1_g      = (const float*)d_in[1];
    const float* ln1_b      = (const float*)d_in[2];
    const float* w_qkv      = (const float*)d_in[3];
    const float* alpha_head = (const float*)d_in[4];
    const float* w_out      = (const float*)d_in[5];
    const float* ln2_g      = (const float*)d_in[6];
    const float* ln2_b      = (const float*)d_in[7];
    const float* w1         = (const float*)d_in[8];
    const float* b1         = (const float*)d_in[9];
    const float* w2         = (const float*)d_in[10];
    const float* b2         = (const float*)d_in[11];
    const float* alpha      = (const float*)d_in[12];
    float* out = (float*)d_out;

    __half *xn, *qkv, *P, *vt, *attn, *xn2, *hbuf, *wqkvT, *woutT, *w1T, *w2T;
    float *Sm, *x1;
    cudaGetSymbolAddress((void**)&xn,    g_xn);
    cudaGetSymbolAddress((void**)&qkv,   g_qkv);
    cudaGetSymbolAddress((void**)&Sm,    g_S);
    cudaGetSymbolAddress((void**)&P,     g_P);
    cudaGetSymbolAddress((void**)&vt,    g_vt);
    cudaGetSymbolAddress((void**)&attn,  g_attn);
    cudaGetSymbolAddress((void**)&x1,    g_x1);
    cudaGetSymbolAddress((void**)&xn2,   g_xn2);
    cudaGetSymbolAddress((void**)&hbuf,  g_h);
    cudaGetSymbolAddress((void**)&wqkvT, g_wqkvT);
    cudaGetSymbolAddress((void**)&woutT, g_woutT);
    cudaGetSymbolAddress((void**)&w1T,   g_w1T);
    cudaGetSymbolAddress((void**)&w2T,   g_w2T);

    cudaFuncSetAttribute(hgemm<0>, cudaFuncAttributeMaxDynamicSharedMemorySize, H_SMEM);
    cudaFuncSetAttribute(hgemm<1>, cudaFuncAttributeMaxDynamicSharedMemorySize, H_SMEM);
    cudaFuncSetAttribute(hgemm<2>, cudaFuncAttributeMaxDynamicSharedMemorySize, H_SMEM);
    cudaFuncSetAttribute(hgemm<3>, cudaFuncAttributeMaxDynamicSharedMemorySize, H_SMEM);
    cudaFuncSetAttribute(hpv, cudaFuncAttributeMaxDynamicSharedMemorySize, PV_SMEM);

    trk<<<dim3(3*DIM/32, DIM/32), dim3(32,8)>>>(w_qkv, wqkvT, DIM, 3*DIM);
    trk<<<dim3(DIM/32,   DIM/32), dim3(32,8)>>>(w_out, woutT, DIM, DIM);
    trk<<<dim3(HID/32,   DIM/32), dim3(32,8)>>>(w1,    w1T,   DIM, HID);
    trk<<<dim3(DIM/32,   HID/32), dim3(32,8)>>>(w2,    w2T,   HID, DIM);

    ln_kernel<<<M_ROWS, 256>>>(x, ln1_g, ln1_b, xn);
    hgemm<0><<<dim3(3*DIM/128, M_ROWS/128), 256, H_SMEM>>>(
        DIM, xn, DIM, wqkvT, qkv, 3*DIM, nullptr, nullptr, nullptr);
    hqk<<<dim3(TT/128, TT/128, NBH), 256>>>(qkv, Sm);
    vtrans<<<dim3(TT/32, DK/32, NBH), dim3(32,8)>>>(qkv, vt);
    softmax_topk2<<<NBH*TT, 256>>>(Sm, P, alpha_head);
    hpv<<<dim3(TT/128, NBH), 256, PV_SMEM>>>(P, vt, attn);
    hgemm<1><<<dim3(DIM/128, M_ROWS/128), 256, H_SMEM>>>(
        DIM, attn, DIM, woutT, x1, DIM, nullptr, x, alpha);
    ln_kernel<<<M_ROWS, 256>>>(x1, ln2_g, ln2_b, xn2);
    hgemm<2><<<dim3(HID/128, M_ROWS/128), 256, H_SMEM>>>(
        DIM, xn2, DIM, w1T, hbuf, HID, b1, nullptr, nullptr);
    hgemm<3><<<dim3(DIM/128, M_ROWS/128), 256, H_SMEM>>>(
        HID, hbuf, HID, w2T, out, DIM, b2, x1, alpha);
}

// round 8
// speedup vs baseline: 4.9709x; 1.0043x over previous
#include <cuda_runtime.h>
#include <cuda_fp16.h>
#include <math.h>
#include <stdint.h>

// Problem constants
#define BB   2
#define TT   2048
#define DIM  1024
#define NH   16
#define DK   64
#define TOPK 64
#define HID  8192
#define M_ROWS (BB*TT)           // 4096
#define NBH  (BB*NH)             // 32

// ---------------- scratch ------------------------------------------------------
__device__ __half g_xn  [(size_t)M_ROWS * DIM];
__device__ __half g_qkv [(size_t)M_ROWS * 3 * DIM];
__device__ float  g_S   [(size_t)NBH * TT * TT];
__device__ __half g_P   [(size_t)NBH * TT * TT];
__device__ __half g_vt  [(size_t)NBH * DK * TT];
__device__ __half g_attn[(size_t)M_ROWS * DIM];
__device__ float  g_x1  [(size_t)M_ROWS * DIM];
__device__ __half g_xn2 [(size_t)M_ROWS * DIM];
__device__ __half g_h   [(size_t)M_ROWS * HID];
__device__ __half g_wqkvT[(size_t)3 * DIM * DIM];
__device__ __half g_woutT[(size_t)DIM * DIM];
__device__ __half g_w1T  [(size_t)HID * DIM];
__device__ __half g_w2T  [(size_t)DIM * HID];

// ---------------- helpers ------------------------------------------------------
__device__ __forceinline__ void hmma(float* c, const unsigned* a, const unsigned* b)
{
    asm volatile(
        "mma.sync.aligned.m16n8k16.row.col.f32.f16.f16.f32 "
        "{%0,%1,%2,%3},{%4,%5,%6,%7},{%8,%9},{%0,%1,%2,%3};\n"
        : "+f"(c[0]), "+f"(c[1]), "+f"(c[2]), "+f"(c[3])
        : "r"(a[0]), "r"(a[1]), "r"(a[2]), "r"(a[3]), "r"(b[0]), "r"(b[1]));
}
__device__ __forceinline__ void ldsm_x4(unsigned* r, unsigned saddr)
{
    asm volatile("ldmatrix.sync.aligned.m8n8.x4.shared.b16 {%0,%1,%2,%3}, [%4];"
                 : "=r"(r[0]), "=r"(r[1]), "=r"(r[2]), "=r"(r[3]) : "r"(saddr));
}
__device__ __forceinline__ void ldsm_x2(unsigned* r, unsigned saddr)
{
    asm volatile("ldmatrix.sync.aligned.m8n8.x2.shared.b16 {%0,%1}, [%2];"
                 : "=r"(r[0]), "=r"(r[1]) : "r"(saddr));
}
__device__ __forceinline__ void cp16s(unsigned saddr, const void* g)
{
    asm volatile("cp.async.cg.shared.global [%0], [%1], 16;\n" :: "r"(saddr), "l"(g));
}
#define CP_COMMIT() asm volatile("cp.async.commit_group;\n")

// ---------------- weight transpose fp32 -> half [C][R] --------------------------
__global__ __launch_bounds__(256)
void trk(const float* __restrict__ src, __half* __restrict__ dst, int R, int C)
{
    __shared__ float t[32][33];
    const int c0 = blockIdx.x * 32, r0 = blockIdx.y * 32;
    const int x = threadIdx.x, y = threadIdx.y;
#pragma unroll
    for (int j = 0; j < 32; j += 8)
        t[y + j][x] = src[(size_t)(r0 + y + j) * C + c0 + x];
    __syncthreads();
#pragma unroll
    for (int j = 0; j < 32; j += 8)
        dst[(size_t)(c0 + y + j) * R + r0 + x] = __float2half_rn(t[x][y + j]);
}

// ---------------- V transpose: qkv half -> vt[bh][d][t] -------------------------
__global__ __launch_bounds__(256)
void vtrans(const __half* __restrict__ qkv, __half* __restrict__ vt)
{
    __shared__ __half t[32][33];
    const int bh = blockIdx.z, b = bh >> 4, h = bh & 15;
    const int t0 = blockIdx.x * 32, d0 = blockIdx.y * 32;
    const int x = threadIdx.x, y = threadIdx.y;
#pragma unroll
    for (int j = 0; j < 32; j += 8)
        t[y + j][x] = qkv[(size_t)(b * TT + t0 + y + j) * (3 * DIM) + 2 * DIM + h * DK + d0 + x];
    __syncthreads();
#pragma unroll
    for (int j = 0; j < 32; j += 8)
        vt[((size_t)bh * DK + d0 + y + j) * TT + t0 + x] = t[x][y + j];
}

// ---------------- LayerNorm (half output) ---------------------------------------
__global__ __launch_bounds__(256)
void ln_kernel(const float* __restrict__ x, const float* __restrict__ g,
               const float* __restrict__ b, __half* __restrict__ o)
{
    const int rowbase = blockIdx.x * DIM;
    const int tid = threadIdx.x;
    float v[4];
    float s = 0.f, s2 = 0.f;
#pragma unroll
    for (int i = 0; i < 4; i++) {
        v[i] = x[rowbase + tid + i * 256];
        s  += v[i];
        s2 += v[i] * v[i];
    }
    __shared__ float r1[256], r2[256];
    r1[tid] = s; r2[tid] = s2; __syncthreads();
    for (int st = 128; st > 0; st >>= 1) {
        if (tid < st) { r1[tid] += r1[tid + st]; r2[tid] += r2[tid + st]; }
        __syncthreads();
    }
    const float mu   = r1[0] * (1.f / DIM);
    const float var  = r2[0] * (1.f / DIM) - mu * mu;
    const float rstd = rsqrtf(var + 1e-5f);
#pragma unroll
    for (int i = 0; i < 4; i++) {
        int c = tid + i * 256;
        o[rowbase + c] = __float2half_rn((v[i] - mu) * rstd * g[c] + b[c]);
    }
}

// ---------------- fp16 pipelined GEMM (cp.async 4-stage, single sync) -----------
#define H_LDA 40
#define H_TILE (128*H_LDA)
#define H_STG 4
#define H_SMEM (H_STG*2*H_TILE*2)     // 81920 B

template <int EPI>
__global__ __launch_bounds__(256, 2)
void hgemm(int K,
           const __half* __restrict__ A, int lda,
           const __half* __restrict__ Bt,
           void* __restrict__ Cv, int ldc,
           const float* __restrict__ bias,
           const float* __restrict__ resid,
           const float* __restrict__ alphap)
{
    constexpr bool HOUT = (EPI == 0 || EPI == 2);
    extern __shared__ __half smh[];
    const unsigned sbase = (unsigned)__cvta_generic_to_shared(smh);

    const int tid = threadIdx.x, lane = tid & 31, warp = tid >> 5;
    const int g = lane >> 2, tq = lane & 3;
    const int bm = blockIdx.y * 128, bn = blockIdx.x * 128;
    const int wm = (warp >> 2) * 64, wn = (warp & 3) * 32;

    const unsigned aoff = ((unsigned)((lane & 15) * H_LDA) + ((lane >> 4) << 3)) * 2;
    const unsigned boff = ((unsigned)((lane & 7) * H_LDA) + (((lane >> 3) & 1) << 3)) * 2;

    float acc[4][4][4];
#pragma unroll
    for (int mi = 0; mi < 4; mi++)
#pragma unroll
        for (int ni = 0; ni < 4; ni++)
#pragma unroll
            for (int q = 0; q < 4; q++) acc[mi][ni][q] = 0.f;

    auto load_stage = [&](int i) {
        const int s = i & (H_STG - 1);
        const unsigned sA = sbase + (unsigned)(s * H_TILE * 2);
        const unsigned sB = sbase + (unsigned)((H_STG + s) * H_TILE * 2);
        const __half* Ap = A + (size_t)bm * lda + i * 32;
        const __half* Bp = Bt + (size_t)bn * K + i * 32;
#pragma unroll
        for (int j = 0; j < 2; j++) {
            int idx = tid + j * 256;
            int row = idx >> 2, seg = (idx & 3) << 4;
            cp16s(sA + row * (H_LDA * 2) + seg, Ap + (size_t)row * lda + (seg >> 1));
            cp16s(sB + row * (H_LDA * 2) + seg, Bp + (size_t)row * K + (seg >> 1));
        }
        CP_COMMIT();
    };

    const int KT = K / 32;
    load_stage(0);
    load_stage(1);
    load_stage(2);

    for (int kt = 0; kt < KT; kt++) {
        if (kt + 2 < KT)      asm volatile("cp.async.wait_group 2;\n" ::: "memory");
        else if (kt + 1 < KT) asm volatile("cp.async.wait_group 1;\n" ::: "memory");
        else                  asm volatile("cp.async.wait_group 0;\n" ::: "memory");
        __syncthreads();
        if (kt + 3 < KT) load_stage(kt + 3);   // overlap loads with compute

        const int s = kt & (H_STG - 1);
        const unsigned aStage = sbase + (unsigned)(s * H_TILE * 2);
        const unsigned bStage = sbase + (unsigned)((H_STG + s) * H_TILE * 2);
#pragma unroll
        for (int ks = 0; ks < 2; ks++) {
            const unsigned kbb = (unsigned)(ks * 16 * 2);
            unsigned af[4][4], bf[4][2];
#pragma unroll
            for (int mi = 0; mi < 4; mi++)
                ldsm_x4(af[mi], aStage + (unsigned)((wm + mi * 16) * H_LDA * 2) + aoff + kbb);
#pragma unroll
            for (int ni = 0; ni < 4; ni++)
                ldsm_x2(bf[ni], bStage + (unsigned)((wn + ni * 8) * H_LDA * 2) + boff + kbb);
#pragma unroll
            for (int mi = 0; mi < 4; mi++)
#pragma unroll
                for (int ni = 0; ni < 4; ni++) hmma(acc[mi][ni], af[mi], bf[ni]);
        }
    }

    const float al = (EPI == 1 || EPI == 3) ? alphap[0] : 0.f;
#pragma unroll
    for (int mi = 0; mi < 4; mi++) {
#pragma unroll
        for (int ni = 0; ni < 4; ni++) {
            int r0 = bm + wm + mi * 16 + g;
            int c  = bn + wn + ni * 8 + 2 * tq;
#pragma unroll
            for (int half = 0; half < 2; half++) {
                int r = r0 + half * 8;
                size_t off = (size_t)r * ldc + c;
                float v0 = acc[mi][ni][half * 2];
                float v1 = acc[mi][ni][half * 2 + 1];
                float o0, o1;
                if (EPI == 0) {
                    o0 = v0; o1 = v1;
                } else if (EPI == 1) {
                    o0 = resid[off] + al * v0;
                    o1 = resid[off + 1] + al * v1;
                } else if (EPI == 2) {
                    float u0 = v0 + bias[c], u1 = v1 + bias[c + 1];
                    o0 = 0.5f * u0 * (1.f + erff(u0 * 0.70710678118654752440f));
                    o1 = 0.5f * u1 * (1.f + erff(u1 * 0.70710678118654752440f));
                } else {
                    o0 = resid[off] + al * (v0 + bias[c]);
                    o1 = resid[off + 1] + al * (v1 + bias[c + 1]);
                }
                if (HOUT) {
                    *(__half2*)((__half*)Cv + off) = __floats2half2_rn(o0, o1);
                } else {
                    *(float2*)((float*)Cv + off) = make_float2(o0, o1);
                }
            }
        }
    }
}

// ---------------- batched QK^T (fp16 MMA + ldmatrix): S = Q @ K^T / 8 -----------
__global__ __launch_bounds__(256)
void hqk(const __half* __restrict__ qkv, float* __restrict__ S)
{
    __shared__ __half As[128][72];
    __shared__ __half Bs[128][72];

    const int bh = blockIdx.z, b = bh >> 4, h = bh & 15;
    const __half* Q  = qkv + (size_t)b * TT * (3 * DIM) + h * DK;
    const __half* Kp = qkv + (size_t)b * TT * (3 * DIM) + DIM + h * DK;
    float* Sp = S + (size_t)bh * TT * TT;

    const int tid = threadIdx.x, lane = tid & 31, warp = tid >> 5;
    const int g = lane >> 2, tq = lane & 3;
    const int bm = blockIdx.y * 128, bn = blockIdx.x * 128;
    const int wm = (warp >> 2) * 64, wn = (warp & 3) * 32;

    const unsigned sA = (unsigned)__cvta_generic_to_shared(&As[0][0]);
    const unsigned sB = (unsigned)__cvta_generic_to_shared(&Bs[0][0]);
    const unsigned aoff = ((unsigned)((lane & 15) * 72) + ((lane >> 4) << 3)) * 2;
    const unsigned boff = ((unsigned)((lane & 7) * 72) + (((lane >> 3) & 1) << 3)) * 2;

    float acc[4][4][4];
#pragma unroll
    for (int mi = 0; mi < 4; mi++)
#pragma unroll
        for (int ni = 0; ni < 4; ni++)
#pragma unroll
            for (int q = 0; q < 4; q++) acc[mi][ni][q] = 0.f;

#pragma unroll
    for (int j = 0; j < 4; j++) {
        int idx = tid + j * 256;
        int m = idx >> 3, seg = (idx & 7) << 3;
        *(uint4*)&As[m][seg] = *(const uint4*)(Q  + (size_t)(bm + m) * (3 * DIM) + seg);
        *(uint4*)&Bs[m][seg] = *(const uint4*)(Kp + (size_t)(bn + m) * (3 * DIM) + seg);
    }
    __syncthreads();

#pragma unroll
    for (int ks = 0; ks < 4; ks++) {
        const unsigned kbb = (unsigned)(ks * 16 * 2);
        unsigned af[4][4], bf[4][2];
#pragma unroll
        for (int mi = 0; mi < 4; mi++)
            ldsm_x4(af[mi], sA + (unsigned)((wm + mi * 16) * 72 * 2) + aoff + kbb);
#pragma unroll
        for (int ni = 0; ni < 4; ni++)
            ldsm_x2(bf[ni], sB + (unsigned)((wn + ni * 8) * 72 * 2) + boff + kbb);
#pragma unroll
        for (int mi = 0; mi < 4; mi++)
#pragma unroll
            for (int ni = 0; ni < 4; ni++) hmma(acc[mi][ni], af[mi], bf[ni]);
    }

#pragma unroll
    for (int mi = 0; mi < 4; mi++)
#pragma unroll
        for (int ni = 0; ni < 4; ni++) {
            int r0 = bm + wm + mi * 16 + g;
            int c  = bn + wn + ni * 8 + 2 * tq;
#pragma unroll
            for (int half = 0; half < 2; half++) {
                size_t off = (size_t)(r0 + half * 8) * TT + c;
                *(float2*)(Sp + off) = make_float2(acc[mi][ni][half * 2] * 0.125f,
                                                   acc[mi][ni][half * 2 + 1] * 0.125f);
            }
        }
}

// ---------------- batched PV (fp16 MMA, cp.async 4-stage, single sync) ----------
#define PV_STG 4
#define PV_SMEM ((PV_STG*128*40 + PV_STG*64*40)*2)

__global__ __launch_bounds__(256, 2)
void hpv(const __half* __restrict__ P, const __half* __restrict__ Vt,
         __half* __restrict__ attn_out)
{
    extern __shared__ __half smh[];
    const unsigned sbase = (unsigned)__cvta_generic_to_shared(smh);

    const int bh = blockIdx.y, b = bh >> 4, h = bh & 15;
    const __half* Pp = P + (size_t)bh * TT * TT;
    const __half* Vp = Vt + (size_t)bh * DK * TT;

    const int tid = threadIdx.x, lane = tid & 31, warp = tid >> 5;
    const int g = lane >> 2, tq = lane & 3;
    const int bm = blockIdx.x * 128;
    const int wm = (warp >> 1) * 32, wn = (warp & 1) * 32;

    const unsigned aoff = ((unsigned)((lane & 15) * 40) + ((lane >> 4) << 3)) * 2;
    const unsigned boff = ((unsigned)((lane & 7) * 40) + (((lane >> 3) & 1) << 3)) * 2;

    float acc[2][4][4];
#pragma unroll
    for (int mi = 0; mi < 2; mi++)
#pragma unroll
        for (int ni = 0; ni < 4; ni++)
#pragma unroll
            for (int q = 0; q < 4; q++) acc[mi][ni][q] = 0.f;

    auto load_stage = [&](int i) {
        const int s = i & (PV_STG - 1);
        const unsigned sA = sbase + (unsigned)(s * 128 * 40 * 2);
        const unsigned sB = sbase + (unsigned)((PV_STG * 128 * 40 + s * 64 * 40) * 2);
        const __half* Ap = Pp + i * 32;
        const __half* Bp = Vp + i * 32;
#pragma unroll
        for (int j = 0; j < 2; j++) {
            int idx = tid + j * 256;
            int row = idx >> 2, seg = (idx & 3) << 4;
            cp16s(sA + row * 80 + seg, Ap + (size_t)(bm + row) * TT + (seg >> 1));
        }
        {
            int row = tid >> 2, seg = (tid & 3) << 4;
            cp16s(sB + row * 80 + seg, Bp + (size_t)row * TT + (seg >> 1));
        }
        CP_COMMIT();
    };

    const int KT = TT / 32;
    load_stage(0);
    load_stage(1);
    load_stage(2);

    for (int kt = 0; kt < KT; kt++) {
        if (kt + 2 < KT)      asm volatile("cp.async.wait_group 2;\n" ::: "memory");
        else if (kt + 1 < KT) asm volatile("cp.async.wait_group 1;\n" ::: "memory");
        else                  asm volatile("cp.async.wait_group 0;\n" ::: "memory");
        __syncthreads();
        if (kt + 3 < KT) load_stage(kt + 3);

        const int s = kt & (PV_STG - 1);
        const unsigned aStage = sbase + (unsigned)(s * 128 * 40 * 2);
        const unsigned bStage = sbase + (unsigned)((PV_STG * 128 * 40 + s * 64 * 40) * 2);
#pragma unroll
        for (int ks = 0; ks < 2; ks++) {
            const unsigned kbb = (unsigned)(ks * 16 * 2);
            unsigned af[2][4], bf[4][2];
#pragma unroll
            for (int mi = 0; mi < 2; mi++)
                ldsm_x4(af[mi], aStage + (unsigned)((wm + mi * 16) * 40 * 2) + aoff + kbb);
#pragma unroll
            for (int ni = 0; ni < 4; ni++)
                ldsm_x2(bf[ni], bStage + (unsigned)((wn + ni * 8) * 40 * 2) + boff + kbb);
#pragma unroll
            for (int mi = 0; mi < 2; mi++)
#pragma unroll
                for (int ni = 0; ni < 4; ni++) hmma(acc[mi][ni], af[mi], bf[ni]);
        }
    }

#pragma unroll
    for (int mi = 0; mi < 2; mi++)
#pragma unroll
        for (int ni = 0; ni < 4; ni++) {
            int r0 = bm + wm + mi * 16 + g;
            int c  = wn + ni * 8 + 2 * tq;
#pragma unroll
            for (int half = 0; half < 2; half++) {
                int r = r0 + half * 8;
                size_t off = (size_t)(b * TT + r) * DIM + h * DK + c;
                *(__half2*)(attn_out + off) =
                    __floats2half2_rn(acc[mi][ni][half * 2], acc[mi][ni][half * 2 + 1]);
            }
        }
}

// ---------------- fused dual softmax + exact top-64 (register-resident) ---------
__device__ __forceinline__ unsigned int ordkey(float f)
{
    unsigned int u = __float_as_uint(f);
    return (u & 0x80000000u) ? ~u : (u | 0x80000000u);
}
__device__ __forceinline__ float ordkey_inv(unsigned int k)
{
    return __uint_as_float((k & 0x80000000u) ? (k & 0x7FFFFFFFu) : ~k);
}

__global__ __launch_bounds__(256)
void softmax_topk2(const float* __restrict__ S, __half* __restrict__ P,
                   const float* __restrict__ alpha_head)
{
    __shared__ int   hist[256];
    __shared__ int   chunkeq[256];
    __shared__ int   chunkpre[256];
    __shared__ float rmax[8];
    __shared__ int   wri[8];
    __shared__ float wrf1[8], wrf2[8];
    __shared__ unsigned selb;
    __shared__ int   selc;

    const int tid = threadIdx.x, lane = tid & 31, w = tid >> 5;
    const int rowid = blockIdx.x;
    const int h = (rowid >> 11) & 15;
    const float* row = S + (size_t)rowid * TT;
    __half* prow = P + (size_t)rowid * TT;

    float v[8];
    *(float4*)&v[0] = *(const float4*)(row + tid * 8);
    *(float4*)&v[4] = *(const float4*)(row + tid * 8 + 4);
    unsigned u[8];
    float m = -3.4e38f;
#pragma unroll
    for (int i = 0; i < 8; i++) { u[i] = ordkey(v[i]); m = fmaxf(m, v[i]); }
#pragma unroll
    for (int o = 16; o > 0; o >>= 1) m = fmaxf(m, __shfl_xor_sync(0xFFFFFFFFu, m, o));
    if (lane == 0) rmax[w] = m;
    __syncthreads();
#pragma unroll
    for (int j = 0; j < 8; j++) m = fmaxf(m, rmax[j]);

    unsigned prefix = 0u, pmask = 0u;
    int kth = TOPK;
#pragma unroll
    for (int shift = 24; shift >= 0; shift -= 8) {
        hist[tid] = 0;
        __syncthreads();
#pragma unroll
        for (int i = 0; i < 8; i++)
            if ((u[i] & pmask) == prefix) atomicAdd(&hist[(u[i] >> shift) & 255], 1);
        __syncthreads();
        if (w == 0) {
            const int base = lane * 8;
            int hv[8], loc[8];
            int s = 0;
#pragma unroll
            for (int j = 7; j >= 0; j--) { hv[j] = hist[base + j]; s += hv[j]; loc[j] = s; }
            int suf = s;
#pragma unroll
            for (int o = 1; o < 32; o <<= 1) {
                int t = __shfl_down_sync(0xFFFFFFFFu, suf, o);
                if (lane + o < 32) suf += t;
            }
            const int higher = suf - s;
            int cand = -1, cabove = 0;
#pragma unroll
            for (int j = 7; j >= 0; j--) {
                int cum = higher + loc[j];
                if (cum >= kth) { cand = base + j; cabove = cum - hv[j]; break; }
            }
#pragma unroll
            for (int o = 16; o > 0; o >>= 1) {
                int oc = __shfl_xor_sync(0xFFFFFFFFu, cand, o);
                int oa = __shfl_xor_sync(0xFFFFFFFFu, cabove, o);
                if (oc > cand) { cand = oc; cabove = oa; }
            }
            if (lane == 0) { selb = (unsigned)cand; selc = cabove; }
        }
        __syncthreads();
        prefix |= selb << shift;
        pmask  |= 0xFFu << shift;
        kth    -= selc;
        __syncthreads();
    }
    const unsigned thr = prefix;

    float e[8];
    float sd = 0.f, sgt = 0.f;
    int cgt = 0, ceq = 0;
#pragma unroll
    for (int i = 0; i < 8; i++) {
        e[i] = __expf(v[i] - m);
        sd += e[i];
        if (u[i] > thr) { cgt++; sgt += e[i]; }
        else if (u[i] == thr) ceq++;
    }
    chunkeq[tid] = ceq;
#pragma unroll
    for (int o = 16; o > 0; o >>= 1) {
        sd  += __shfl_xor_sync(0xFFFFFFFFu, sd, o);
        sgt += __shfl_xor_sync(0xFFFFFFFFu, sgt, o);
        cgt += __shfl_xor_sync(0xFFFFFFFFu, cgt, o);
    }
    if (lane == 0) { wri[w] = cgt; wrf1[w] = sd; wrf2[w] = sgt; }
    __syncthreads();
    int n_gt = 0; float Zd = 0.f, Sgt = 0.f;
#pragma unroll
    for (int j = 0; j < 8; j++) { n_gt += wri[j]; Zd += wrf1[j]; Sgt += wrf2[j]; }

    const int need = TOPK - n_gt;
    const float ethr = __expf(ordkey_inv(thr) - m);
    const float Zs = Sgt + (float)need * ethr;

    if (w == 0) {
        const int base = lane * 8;
        int c[8], loc[8];
        int ex = 0;
#pragma unroll
        for (int j = 0; j < 8; j++) { c[j] = chunkeq[base + j]; loc[j] = ex; ex += c[j]; }
        int acc = ex;
#pragma unroll
        for (int o = 1; o < 32; o <<= 1) {
            int t = __shfl_up_sync(0xFFFFFFFFu, acc, o);
            if (lane >= o) acc += t;
        }
        const int wex = acc - ex;
#pragma unroll
        for (int j = 0; j < 8; j++) chunkpre[base + j] = wex + loc[j];
    }
    __syncthreads();

    const float gate = 1.f / (1.f + __expf(-alpha_head[h]));
    const float cd = gate / Zd;
    const float cs = (1.f - gate) / Zs;

    int tierank = chunkpre[tid];
    __half hs[8];
#pragma unroll
    for (int i = 0; i < 8; i++) {
        bool inc;
        if (u[i] > thr) inc = true;
        else if (u[i] == thr) { inc = (tierank < need); tierank++; }
        else inc = false;
        hs[i] = __float2half_rn(e[i] * (cd + (inc ? cs : 0.f)));
    }
    *(uint4*)(prow + tid * 8) = *(uint4*)hs;
}

// ---------------- launch --------------------------------------------------------
extern "C" void kernel_launch(void* const* d_in, const int* in_sizes, int n_in,
                              void* d_out, int out_size)
{
    const float* x          = (const float*)d_in[0];
    const float* ln1_g      = (const float*)d_in[1];
    const float* ln1_b      = (const float*)d_in[2];
    const float* w_qkv      = (const float*)d_in[3];
    const float* alpha_head = (const float*)d_in[4];
    const float* w_out      = (const float*)d_in[5];
    const float* ln2_g      = (const float*)d_in[6];
    const float* ln2_b      = (const float*)d_in[7];
    const float* w1         = (const float*)d_in[8];
    const float* b1         = (const float*)d_in[9];
    const float* w2         = (const float*)d_in[10];
    const float* b2         = (const float*)d_in[11];
    const float* alpha      = (const float*)d_in[12];
    float* out = (float*)d_out;

    __half *xn, *qkv, *P, *vt, *attn, *xn2, *hbuf, *wqkvT, *woutT, *w1T, *w2T;
    float *Sm, *x1;
    cudaGetSymbolAddress((void**)&xn,    g_xn);
    cudaGetSymbolAddress((void**)&qkv,   g_qkv);
    cudaGetSymbolAddress((void**)&Sm,    g_S);
    cudaGetSymbolAddress((void**)&P,     g_P);
    cudaGetSymbolAddress((void**)&vt,    g_vt);
    cudaGetSymbolAddress((void**)&attn,  g_attn);
    cudaGetSymbolAddress((void**)&x1,    g_x1);
    cudaGetSymbolAddress((void**)&xn2,   g_xn2);
    cudaGetSymbolAddress((void**)&hbuf,  g_h);
    cudaGetSymbolAddress((void**)&wqkvT, g_wqkvT);
    cudaGetSymbolAddress((void**)&woutT, g_woutT);
    cudaGetSymbolAddress((void**)&w1T,   g_w1T);
    cudaGetSymbolAddress((void**)&w2T,   g_w2T);

    cudaFuncSetAttribute(hgemm<0>, cudaFuncAttributeMaxDynamicSharedMemorySize, H_SMEM);
    cudaFuncSetAttribute(hgemm<1>, cudaFuncAttributeMaxDynamicSharedMemorySize, H_SMEM);
    cudaFuncSetAttribute(hgemm<2>, cudaFuncAttributeMaxDynamicSharedMemorySize, H_SMEM);
    cudaFuncSetAttribute(hgemm<3>, cudaFuncAttributeMaxDynamicSharedMemorySize, H_SMEM);
    cudaFuncSetAttribute(hpv, cudaFuncAttributeMaxDynamicSharedMemorySize, PV_SMEM);

    trk<<<dim3(3*DIM/32, DIM/32), dim3(32,8)>>>(w_qkv, wqkvT, DIM, 3*DIM);
    trk<<<dim3(DIM/32,   DIM/32), dim3(32,8)>>>(w_out, woutT, DIM, DIM);
    trk<<<dim3(HID/32,   DIM/32), dim3(32,8)>>>(w1,    w1T,   DIM, HID);
    trk<<<dim3(DIM/32,   HID/32), dim3(32,8)>>>(w2,    w2T,   HID, DIM);

    ln_kernel<<<M_ROWS, 256>>>(x, ln1_g, ln1_b, xn);
    hgemm<0><<<dim3(3*DIM/128, M_ROWS/128), 256, H_SMEM>>>(
        DIM, xn, DIM, wqkvT, qkv, 3*DIM, nullptr, nullptr, nullptr);
    hqk<<<dim3(TT/128, TT/128, NBH), 256>>>(qkv, Sm);
    vtrans<<<dim3(TT/32, DK/32, NBH), dim3(32,8)>>>(qkv, vt);
    softmax_topk2<<<NBH*TT, 256>>>(Sm, P, alpha_head);
    hpv<<<dim3(TT/128, NBH), 256, PV_SMEM>>>(P, vt, attn);
    hgemm<1><<<dim3(DIM/128, M_ROWS/128), 256, H_SMEM>>>(
        DIM, attn, DIM, woutT, x1, DIM, nullptr, x, alpha);
    ln_kernel<<<M_ROWS, 256>>>(x1, ln2_g, ln2_b, xn2);
    hgemm<2><<<dim3(HID/128, M_ROWS/128), 256, H_SMEM>>>(
        DIM, xn2, DIM, w1T, hbuf, HID, b1, nullptr, nullptr);
    hgemm<3><<<dim3(DIM/128, M_ROWS/128), 256, H_SMEM>>>(
        HID, hbuf, HID, w2T, out, DIM, b2, x1, alpha);
}

// round 9
// speedup vs baseline: 5.3179x; 1.0698x over previous
#include <cuda_runtime.h>
#include <cuda_fp16.h>
#include <math.h>
#include <stdint.h>

// Problem constants
#define BB   2
#define TT   2048
#define DIM  1024
#define NH   16
#define DK   64
#define TOPK 64
#define HID  8192
#define M_ROWS (BB*TT)           // 4096
#define NBH  (BB*NH)             // 32

// ---------------- scratch ------------------------------------------------------
__device__ __half g_xn  [(size_t)M_ROWS * DIM];
__device__ __half g_qkv [(size_t)M_ROWS * 3 * DIM];
__device__ __half g_S   [(size_t)NBH * TT * TT];     // scores fp16 (256MB)
__device__ __half g_P   [(size_t)NBH * TT * TT];
__device__ __half g_vt  [(size_t)NBH * DK * TT];
__device__ __half g_attn[(size_t)M_ROWS * DIM];
__device__ float  g_x1  [(size_t)M_ROWS * DIM];
__device__ __half g_xn2 [(size_t)M_ROWS * DIM];
__device__ __half g_h   [(size_t)M_ROWS * HID];
__device__ __half g_wqkvT[(size_t)3 * DIM * DIM];
__device__ __half g_woutT[(size_t)DIM * DIM];
__device__ __half g_w1T  [(size_t)HID * DIM];
__device__ __half g_w2T  [(size_t)DIM * HID];

// ---------------- helpers ------------------------------------------------------
__device__ __forceinline__ void hmma(float* c, const unsigned* a, const unsigned* b)
{
    asm volatile(
        "mma.sync.aligned.m16n8k16.row.col.f32.f16.f16.f32 "
        "{%0,%1,%2,%3},{%4,%5,%6,%7},{%8,%9},{%0,%1,%2,%3};\n"
        : "+f"(c[0]), "+f"(c[1]), "+f"(c[2]), "+f"(c[3])
        : "r"(a[0]), "r"(a[1]), "r"(a[2]), "r"(a[3]), "r"(b[0]), "r"(b[1]));
}
__device__ __forceinline__ void ldsm_x4(unsigned* r, unsigned saddr)
{
    asm volatile("ldmatrix.sync.aligned.m8n8.x4.shared.b16 {%0,%1,%2,%3}, [%4];"
                 : "=r"(r[0]), "=r"(r[1]), "=r"(r[2]), "=r"(r[3]) : "r"(saddr));
}
__device__ __forceinline__ void ldsm_x2(unsigned* r, unsigned saddr)
{
    asm volatile("ldmatrix.sync.aligned.m8n8.x2.shared.b16 {%0,%1}, [%2];"
                 : "=r"(r[0]), "=r"(r[1]) : "r"(saddr));
}
__device__ __forceinline__ void cp16s(unsigned saddr, const void* g)
{
    asm volatile("cp.async.cg.shared.global [%0], [%1], 16;\n" :: "r"(saddr), "l"(g));
}
#define CP_COMMIT() asm volatile("cp.async.commit_group;\n")

// ---------------- weight transpose fp32 -> half [C][R] --------------------------
__global__ __launch_bounds__(256)
void trk(const float* __restrict__ src, __half* __restrict__ dst, int R, int C)
{
    __shared__ float t[32][33];
    const int c0 = blockIdx.x * 32, r0 = blockIdx.y * 32;
    const int x = threadIdx.x, y = threadIdx.y;
#pragma unroll
    for (int j = 0; j < 32; j += 8)
        t[y + j][x] = src[(size_t)(r0 + y + j) * C + c0 + x];
    __syncthreads();
#pragma unroll
    for (int j = 0; j < 32; j += 8)
        dst[(size_t)(c0 + y + j) * R + r0 + x] = __float2half_rn(t[x][y + j]);
}

// ---------------- V transpose: qkv half -> vt[bh][d][t] -------------------------
__global__ __launch_bounds__(256)
void vtrans(const __half* __restrict__ qkv, __half* __restrict__ vt)
{
    __shared__ __half t[32][33];
    const int bh = blockIdx.z, b = bh >> 4, h = bh & 15;
    const int t0 = blockIdx.x * 32, d0 = blockIdx.y * 32;
    const int x = threadIdx.x, y = threadIdx.y;
#pragma unroll
    for (int j = 0; j < 32; j += 8)
        t[y + j][x] = qkv[(size_t)(b * TT + t0 + y + j) * (3 * DIM) + 2 * DIM + h * DK + d0 + x];
    __syncthreads();
#pragma unroll
    for (int j = 0; j < 32; j += 8)
        vt[((size_t)bh * DK + d0 + y + j) * TT + t0 + x] = t[x][y + j];
}

// ---------------- LayerNorm (half output) ---------------------------------------
__global__ __launch_bounds__(256)
void ln_kernel(const float* __restrict__ x, const float* __restrict__ g,
               const float* __restrict__ b, __half* __restrict__ o)
{
    const int rowbase = blockIdx.x * DIM;
    const int tid = threadIdx.x;
    float v[4];
    float s = 0.f, s2 = 0.f;
#pragma unroll
    for (int i = 0; i < 4; i++) {
        v[i] = x[rowbase + tid + i * 256];
        s  += v[i];
        s2 += v[i] * v[i];
    }
    __shared__ float r1[256], r2[256];
    r1[tid] = s; r2[tid] = s2; __syncthreads();
    for (int st = 128; st > 0; st >>= 1) {
        if (tid < st) { r1[tid] += r1[tid + st]; r2[tid] += r2[tid + st]; }
        __syncthreads();
    }
    const float mu   = r1[0] * (1.f / DIM);
    const float var  = r2[0] * (1.f / DIM) - mu * mu;
    const float rstd = rsqrtf(var + 1e-5f);
#pragma unroll
    for (int i = 0; i < 4; i++) {
        int c = tid + i * 256;
        o[rowbase + c] = __float2half_rn((v[i] - mu) * rstd * g[c] + b[c]);
    }
}

// ---------------- fp16 pipelined GEMM (cp.async 4-stage, single sync) -----------
#define H_LDA 40
#define H_TILE (128*H_LDA)
#define H_STG 4
#define H_SMEM (H_STG*2*H_TILE*2)

template <int EPI>
__global__ __launch_bounds__(256, 2)
void hgemm(int K,
           const __half* __restrict__ A, int lda,
           const __half* __restrict__ Bt,
           void* __restrict__ Cv, int ldc,
           const float* __restrict__ bias,
           const float* __restrict__ resid,
           const float* __restrict__ alphap)
{
    constexpr bool HOUT = (EPI == 0 || EPI == 2);
    extern __shared__ __half smh[];
    const unsigned sbase = (unsigned)__cvta_generic_to_shared(smh);

    const int tid = threadIdx.x, lane = tid & 31, warp = tid >> 5;
    const int g = lane >> 2, tq = lane & 3;
    const int bm = blockIdx.y * 128, bn = blockIdx.x * 128;
    const int wm = (warp >> 2) * 64, wn = (warp & 3) * 32;

    const unsigned aoff = ((unsigned)((lane & 15) * H_LDA) + ((lane >> 4) << 3)) * 2;
    const unsigned boff = ((unsigned)((lane & 7) * H_LDA) + (((lane >> 3) & 1) << 3)) * 2;

    float acc[4][4][4];
#pragma unroll
    for (int mi = 0; mi < 4; mi++)
#pragma unroll
        for (int ni = 0; ni < 4; ni++)
#pragma unroll
            for (int q = 0; q < 4; q++) acc[mi][ni][q] = 0.f;

    auto load_stage = [&](int i) {
        const int s = i & (H_STG - 1);
        const unsigned sA = sbase + (unsigned)(s * H_TILE * 2);
        const unsigned sB = sbase + (unsigned)((H_STG + s) * H_TILE * 2);
        const __half* Ap = A + (size_t)bm * lda + i * 32;
        const __half* Bp = Bt + (size_t)bn * K + i * 32;
#pragma unroll
        for (int j = 0; j < 2; j++) {
            int idx = tid + j * 256;
            int row = idx >> 2, seg = (idx & 3) << 4;
            cp16s(sA + row * (H_LDA * 2) + seg, Ap + (size_t)row * lda + (seg >> 1));
            cp16s(sB + row * (H_LDA * 2) + seg, Bp + (size_t)row * K + (seg >> 1));
        }
        CP_COMMIT();
    };

    const int KT = K / 32;
    load_stage(0);
    load_stage(1);
    load_stage(2);

    for (int kt = 0; kt < KT; kt++) {
        if (kt + 2 < KT)      asm volatile("cp.async.wait_group 2;\n" ::: "memory");
        else if (kt + 1 < KT) asm volatile("cp.async.wait_group 1;\n" ::: "memory");
        else                  asm volatile("cp.async.wait_group 0;\n" ::: "memory");
        __syncthreads();
        if (kt + 3 < KT) load_stage(kt + 3);

        const int s = kt & (H_STG - 1);
        const unsigned aStage = sbase + (unsigned)(s * H_TILE * 2);
        const unsigned bStage = sbase + (unsigned)((H_STG + s) * H_TILE * 2);
#pragma unroll
        for (int ks = 0; ks < 2; ks++) {
            const unsigned kbb = (unsigned)(ks * 16 * 2);
            unsigned af[4][4], bf[4][2];
#pragma unroll
            for (int mi = 0; mi < 4; mi++)
                ldsm_x4(af[mi], aStage + (unsigned)((wm + mi * 16) * H_LDA * 2) + aoff + kbb);
#pragma unroll
            for (int ni = 0; ni < 4; ni++)
                ldsm_x2(bf[ni], bStage + (unsigned)((wn + ni * 8) * H_LDA * 2) + boff + kbb);
#pragma unroll
            for (int mi = 0; mi < 4; mi++)
#pragma unroll
                for (int ni = 0; ni < 4; ni++) hmma(acc[mi][ni], af[mi], bf[ni]);
        }
    }

    const float al = (EPI == 1 || EPI == 3) ? alphap[0] : 0.f;
#pragma unroll
    for (int mi = 0; mi < 4; mi++) {
#pragma unroll
        for (int ni = 0; ni < 4; ni++) {
            int r0 = bm + wm + mi * 16 + g;
            int c  = bn + wn + ni * 8 + 2 * tq;
#pragma unroll
            for (int half = 0; half < 2; half++) {
                int r = r0 + half * 8;
                size_t off = (size_t)r * ldc + c;
                float v0 = acc[mi][ni][half * 2];
                float v1 = acc[mi][ni][half * 2 + 1];
                float o0, o1;
                if (EPI == 0) {
                    o0 = v0; o1 = v1;
                } else if (EPI == 1) {
                    o0 = resid[off] + al * v0;
                    o1 = resid[off + 1] + al * v1;
                } else if (EPI == 2) {
                    float u0 = v0 + bias[c], u1 = v1 + bias[c + 1];
                    o0 = 0.5f * u0 * (1.f + erff(u0 * 0.70710678118654752440f));
                    o1 = 0.5f * u1 * (1.f + erff(u1 * 0.70710678118654752440f));
                } else {
                    o0 = resid[off] + al * (v0 + bias[c]);
                    o1 = resid[off + 1] + al * (v1 + bias[c + 1]);
                }
                if (HOUT) {
                    *(__half2*)((__half*)Cv + off) = __floats2half2_rn(o0, o1);
                } else {
                    *(float2*)((float*)Cv + off) = make_float2(o0, o1);
                }
            }
        }
    }
}

// ---------------- batched QK^T (fp16 MMA + ldmatrix): S = Q @ K^T / 8 -> fp16 ---
__global__ __launch_bounds__(256)
void hqk(const __half* __restrict__ qkv, __half* __restrict__ S)
{
    __shared__ __half As[128][72];
    __shared__ __half Bs[128][72];

    const int bh = blockIdx.z, b = bh >> 4, h = bh & 15;
    const __half* Q  = qkv + (size_t)b * TT * (3 * DIM) + h * DK;
    const __half* Kp = qkv + (size_t)b * TT * (3 * DIM) + DIM + h * DK;
    __half* Sp = S + (size_t)bh * TT * TT;

    const int tid = threadIdx.x, lane = tid & 31, warp = tid >> 5;
    const int g = lane >> 2, tq = lane & 3;
    const int bm = blockIdx.y * 128, bn = blockIdx.x * 128;
    const int wm = (warp >> 2) * 64, wn = (warp & 3) * 32;

    const unsigned sA = (unsigned)__cvta_generic_to_shared(&As[0][0]);
    const unsigned sB = (unsigned)__cvta_generic_to_shared(&Bs[0][0]);
    const unsigned aoff = ((unsigned)((lane & 15) * 72) + ((lane >> 4) << 3)) * 2;
    const unsigned boff = ((unsigned)((lane & 7) * 72) + (((lane >> 3) & 1) << 3)) * 2;

    float acc[4][4][4];
#pragma unroll
    for (int mi = 0; mi < 4; mi++)
#pragma unroll
        for (int ni = 0; ni < 4; ni++)
#pragma unroll
            for (int q = 0; q < 4; q++) acc[mi][ni][q] = 0.f;

#pragma unroll
    for (int j = 0; j < 4; j++) {
        int idx = tid + j * 256;
        int m = idx >> 3, seg = (idx & 7) << 3;
        *(uint4*)&As[m][seg] = *(const uint4*)(Q  + (size_t)(bm + m) * (3 * DIM) + seg);
        *(uint4*)&Bs[m][seg] = *(const uint4*)(Kp + (size_t)(bn + m) * (3 * DIM) + seg);
    }
    __syncthreads();

#pragma unroll
    for (int ks = 0; ks < 4; ks++) {
        const unsigned kbb = (unsigned)(ks * 16 * 2);
        unsigned af[4][4], bf[4][2];
#pragma unroll
        for (int mi = 0; mi < 4; mi++)
            ldsm_x4(af[mi], sA + (unsigned)((wm + mi * 16) * 72 * 2) + aoff + kbb);
#pragma unroll
        for (int ni = 0; ni < 4; ni++)
            ldsm_x2(bf[ni], sB + (unsigned)((wn + ni * 8) * 72 * 2) + boff + kbb);
#pragma unroll
        for (int mi = 0; mi < 4; mi++)
#pragma unroll
            for (int ni = 0; ni < 4; ni++) hmma(acc[mi][ni], af[mi], bf[ni]);
    }

#pragma unroll
    for (int mi = 0; mi < 4; mi++)
#pragma unroll
        for (int ni = 0; ni < 4; ni++) {
            int r0 = bm + wm + mi * 16 + g;
            int c  = bn + wn + ni * 8 + 2 * tq;
#pragma unroll
            for (int half = 0; half < 2; half++) {
                size_t off = (size_t)(r0 + half * 8) * TT + c;
                *(__half2*)(Sp + off) = __floats2half2_rn(acc[mi][ni][half * 2] * 0.125f,
                                                          acc[mi][ni][half * 2 + 1] * 0.125f);
            }
        }
}

// ---------------- batched PV (fp16 MMA, cp.async 4-stage, single sync) ----------
#define PV_STG 4
#define PV_SMEM ((PV_STG*128*40 + PV_STG*64*40)*2)

__global__ __launch_bounds__(256, 2)
void hpv(const __half* __restrict__ P, const __half* __restrict__ Vt,
         __half* __restrict__ attn_out)
{
    extern __shared__ __half smh[];
    const unsigned sbase = (unsigned)__cvta_generic_to_shared(smh);

    const int bh = blockIdx.y, b = bh >> 4, h = bh & 15;
    const __half* Pp = P + (size_t)bh * TT * TT;
    const __half* Vp = Vt + (size_t)bh * DK * TT;

    const int tid = threadIdx.x, lane = tid & 31, warp = tid >> 5;
    const int g = lane >> 2, tq = lane & 3;
    const int bm = blockIdx.x * 128;
    const int wm = (warp >> 1) * 32, wn = (warp & 1) * 32;

    const unsigned aoff = ((unsigned)((lane & 15) * 40) + ((lane >> 4) << 3)) * 2;
    const unsigned boff = ((unsigned)((lane & 7) * 40) + (((lane >> 3) & 1) << 3)) * 2;

    float acc[2][4][4];
#pragma unroll
    for (int mi = 0; mi < 2; mi++)
#pragma unroll
        for (int ni = 0; ni < 4; ni++)
#pragma unroll
            for (int q = 0; q < 4; q++) acc[mi][ni][q] = 0.f;

    auto load_stage = [&](int i) {
        const int s = i & (PV_STG - 1);
        const unsigned sA = sbase + (unsigned)(s * 128 * 40 * 2);
        const unsigned sB = sbase + (unsigned)((PV_STG * 128 * 40 + s * 64 * 40) * 2);
        const __half* Ap = Pp + i * 32;
        const __half* Bp = Vp + i * 32;
#pragma unroll
        for (int j = 0; j < 2; j++) {
            int idx = tid + j * 256;
            int row = idx >> 2, seg = (idx & 3) << 4;
            cp16s(sA + row * 80 + seg, Ap + (size_t)(bm + row) * TT + (seg >> 1));
        }
        {
            int row = tid >> 2, seg = (tid & 3) << 4;
            cp16s(sB + row * 80 + seg, Bp + (size_t)row * TT + (seg >> 1));
        }
        CP_COMMIT();
    };

    const int KT = TT / 32;
    load_stage(0);
    load_stage(1);
    load_stage(2);

    for (int kt = 0; kt < KT; kt++) {
        if (kt + 2 < KT)      asm volatile("cp.async.wait_group 2;\n" ::: "memory");
        else if (kt + 1 < KT) asm volatile("cp.async.wait_group 1;\n" ::: "memory");
        else                  asm volatile("cp.async.wait_group 0;\n" ::: "memory");
        __syncthreads();
        if (kt + 3 < KT) load_stage(kt + 3);

        const int s = kt & (PV_STG - 1);
        const unsigned aStage = sbase + (unsigned)(s * 128 * 40 * 2);
        const unsigned bStage = sbase + (unsigned)((PV_STG * 128 * 40 + s * 64 * 40) * 2);
#pragma unroll
        for (int ks = 0; ks < 2; ks++) {
            const unsigned kbb = (unsigned)(ks * 16 * 2);
            unsigned af[2][4], bf[4][2];
#pragma unroll
            for (int mi = 0; mi < 2; mi++)
                ldsm_x4(af[mi], aStage + (unsigned)((wm + mi * 16) * 40 * 2) + aoff + kbb);
#pragma unroll
            for (int ni = 0; ni < 4; ni++)
                ldsm_x2(bf[ni], bStage + (unsigned)((wn + ni * 8) * 40 * 2) + boff + kbb);
#pragma unroll
            for (int mi = 0; mi < 2; mi++)
#pragma unroll
                for (int ni = 0; ni < 4; ni++) hmma(acc[mi][ni], af[mi], bf[ni]);
        }
    }

#pragma unroll
    for (int mi = 0; mi < 2; mi++)
#pragma unroll
        for (int ni = 0; ni < 4; ni++) {
            int r0 = bm + wm + mi * 16 + g;
            int c  = wn + ni * 8 + 2 * tq;
#pragma unroll
            for (int half = 0; half < 2; half++) {
                int r = r0 + half * 8;
                size_t off = (size_t)(b * TT + r) * DIM + h * DK + c;
                *(__half2*)(attn_out + off) =
                    __floats2half2_rn(acc[mi][ni][half * 2], acc[mi][ni][half * 2 + 1]);
            }
        }
}

// ---------------- fused dual softmax + exact top-64 (fp16 S, 16-bit radix) ------
__device__ __forceinline__ unsigned ordkey16(unsigned h)   // h: 16-bit half bits
{
    return (h & 0x8000u) ? (~h & 0xFFFFu) : (h | 0x8000u);
}
__device__ __forceinline__ float ordkey16_inv(unsigned k)
{
    unsigned short hb = (unsigned short)((k & 0x8000u) ? (k & 0x7FFFu) : (~k & 0xFFFFu));
    __half hv = __ushort_as_half(hb);
    return __half2float(hv);
}

__global__ __launch_bounds__(256)
void softmax_topk2(const __half* __restrict__ S, __half* __restrict__ P,
                   const float* __restrict__ alpha_head)
{
    __shared__ int   hist[256];
    __shared__ int   chunkeq[256];
    __shared__ int   chunkpre[256];
    __shared__ float rmax[8];
    __shared__ int   wri[8];
    __shared__ float wrf1[8], wrf2[8];
    __shared__ unsigned selb;
    __shared__ int   selc;

    const int tid = threadIdx.x, lane = tid & 31, w = tid >> 5;
    const int rowid = blockIdx.x;
    const int h = (rowid >> 11) & 15;
    const __half* row = S + (size_t)rowid * TT;
    __half* prow = P + (size_t)rowid * TT;

    // load 8 contiguous halves
    uint4 pk = *(const uint4*)(row + tid * 8);
    unsigned hw[4] = {pk.x, pk.y, pk.z, pk.w};
    float v[8];
    unsigned u[8];
    float m = -3.4e38f;
#pragma unroll
    for (int i = 0; i < 4; i++) {
        unsigned lo = hw[i] & 0xFFFFu, hi = hw[i] >> 16;
        v[2 * i]     = __half2float(__ushort_as_half((unsigned short)lo));
        v[2 * i + 1] = __half2float(__ushort_as_half((unsigned short)hi));
        u[2 * i]     = ordkey16(lo);
        u[2 * i + 1] = ordkey16(hi);
    }
#pragma unroll
    for (int i = 0; i < 8; i++) m = fmaxf(m, v[i]);
#pragma unroll
    for (int o = 16; o > 0; o >>= 1) m = fmaxf(m, __shfl_xor_sync(0xFFFFFFFFu, m, o));
    if (lane == 0) rmax[w] = m;
    __syncthreads();
#pragma unroll
    for (int j = 0; j < 8; j++) m = fmaxf(m, rmax[j]);

    // 2x8-bit radix select on 16-bit order-preserving keys
    unsigned prefix = 0u, pmask = 0u;
    int kth = TOPK;
#pragma unroll
    for (int shift = 8; shift >= 0; shift -= 8) {
        hist[tid] = 0;
        __syncthreads();
#pragma unroll
        for (int i = 0; i < 8; i++)
            if ((u[i] & pmask) == prefix) atomicAdd(&hist[(u[i] >> shift) & 255], 1);
        __syncthreads();
        if (w == 0) {
            const int base = lane * 8;
            int hv[8], loc[8];
            int s = 0;
#pragma unroll
            for (int j = 7; j >= 0; j--) { hv[j] = hist[base + j]; s += hv[j]; loc[j] = s; }
            int suf = s;
#pragma unroll
            for (int o = 1; o < 32; o <<= 1) {
                int t = __shfl_down_sync(0xFFFFFFFFu, suf, o);
                if (lane + o < 32) suf += t;
            }
            const int higher = suf - s;
            int cand = -1, cabove = 0;
#pragma unroll
            for (int j = 7; j >= 0; j--) {
                int cum = higher + loc[j];
                if (cum >= kth) { cand = base + j; cabove = cum - hv[j]; break; }
            }
#pragma unroll
            for (int o = 16; o > 0; o >>= 1) {
                int oc = __shfl_xor_sync(0xFFFFFFFFu, cand, o);
                int oa = __shfl_xor_sync(0xFFFFFFFFu, cabove, o);
                if (oc > cand) { cand = oc; cabove = oa; }
            }
            if (lane == 0) { selb = (unsigned)cand; selc = cabove; }
        }
        __syncthreads();
        prefix |= selb << shift;
        pmask  |= 0xFFu << shift;
        kth    -= selc;
        __syncthreads();
    }
    const unsigned thr = prefix;

    float e[8];
    float sd = 0.f, sgt = 0.f;
    int cgt = 0, ceq = 0;
#pragma unroll
    for (int i = 0; i < 8; i++) {
        e[i] = __expf(v[i] - m);
        sd += e[i];
        if (u[i] > thr) { cgt++; sgt += e[i]; }
        else if (u[i] == thr) ceq++;
    }
    chunkeq[tid] = ceq;
#pragma unroll
    for (int o = 16; o > 0; o >>= 1) {
        sd  += __shfl_xor_sync(0xFFFFFFFFu, sd, o);
        sgt += __shfl_xor_sync(0xFFFFFFFFu, sgt, o);
        cgt += __shfl_xor_sync(0xFFFFFFFFu, cgt, o);
    }
    if (lane == 0) { wri[w] = cgt; wrf1[w] = sd; wrf2[w] = sgt; }
    __syncthreads();
    int n_gt = 0; float Zd = 0.f, Sgt = 0.f;
#pragma unroll
    for (int j = 0; j < 8; j++) { n_gt += wri[j]; Zd += wrf1[j]; Sgt += wrf2[j]; }

    const int need = TOPK - n_gt;
    const float ethr = __expf(ordkey16_inv(thr) - m);
    const float Zs = Sgt + (float)need * ethr;

    if (w == 0) {
        const int base = lane * 8;
        int c[8], loc[8];
        int ex = 0;
#pragma unroll
        for (int j = 0; j < 8; j++) { c[j] = chunkeq[base + j]; loc[j] = ex; ex += c[j]; }
        int acc = ex;
#pragma unroll
        for (int o = 1; o < 32; o <<= 1) {
            int t = __shfl_up_sync(0xFFFFFFFFu, acc, o);
            if (lane >= o) acc += t;
        }
        const int wex = acc - ex;
#pragma unroll
        for (int j = 0; j < 8; j++) chunkpre[base + j] = wex + loc[j];
    }
    __syncthreads();

    const float gate = 1.f / (1.f + __expf(-alpha_head[h]));
    const float cd = gate / Zd;
    const float cs = (1.f - gate) / Zs;

    int tierank = chunkpre[tid];
    __half hs[8];
#pragma unroll
    for (int i = 0; i < 8; i++) {
        bool inc;
        if (u[i] > thr) inc = true;
        else if (u[i] == thr) { inc = (tierank < need); tierank++; }
        else inc = false;
        hs[i] = __float2half_rn(e[i] * (cd + (inc ? cs : 0.f)));
    }
    *(uint4*)(prow + tid * 8) = *(uint4*)hs;
}

// ---------------- launch --------------------------------------------------------
extern "C" void kernel_launch(void* const* d_in, const int* in_sizes, int n_in,
                              void* d_out, int out_size)
{
    const float* x          = (const float*)d_in[0];
    const float* ln1_g      = (const float*)d_in[1];
    const float* ln1_b      = (const float*)d_in[2];
    const float* w_qkv      = (const float*)d_in[3];
    const float* alpha_head = (const float*)d_in[4];
    const float* w_out      = (const float*)d_in[5];
    const float* ln2_g      = (const float*)d_in[6];
    const float* ln2_b      = (const float*)d_in[7];
    const float* w1         = (const float*)d_in[8];
    const float* b1         = (const float*)d_in[9];
    const float* w2         = (const float*)d_in[10];
    const float* b2         = (const float*)d_in[11];
    const float* alpha      = (const float*)d_in[12];
    float* out = (float*)d_out;

    __half *xn, *qkv, *Sm, *P, *vt, *attn, *xn2, *hbuf, *wqkvT, *woutT, *w1T, *w2T;
    float *x1;
    cudaGetSymbolAddress((void**)&xn,    g_xn);
    cudaGetSymbolAddress((void**)&qkv,   g_qkv);
    cudaGetSymbolAddress((void**)&Sm,    g_S);
    cudaGetSymbolAddress((void**)&P,     g_P);
    cudaGetSymbolAddress((void**)&vt,    g_vt);
    cudaGetSymbolAddress((void**)&attn,  g_attn);
    cudaGetSymbolAddress((void**)&x1,    g_x1);
    cudaGetSymbolAddress((void**)&xn2,   g_xn2);
    cudaGetSymbolAddress((void**)&hbuf,  g_h);
    cudaGetSymbolAddress((void**)&wqkvT, g_wqkvT);
    cudaGetSymbolAddress((void**)&woutT, g_woutT);
    cudaGetSymbolAddress((void**)&w1T,   g_w1T);
    cudaGetSymbolAddress((void**)&w2T,   g_w2T);

    cudaFuncSetAttribute(hgemm<0>, cudaFuncAttributeMaxDynamicSharedMemorySize, H_SMEM);
    cudaFuncSetAttribute(hgemm<1>, cudaFuncAttributeMaxDynamicSharedMemorySize, H_SMEM);
    cudaFuncSetAttribute(hgemm<2>, cudaFuncAttributeMaxDynamicSharedMemorySize, H_SMEM);
    cudaFuncSetAttribute(hgemm<3>, cudaFuncAttributeMaxDynamicSharedMemorySize, H_SMEM);
    cudaFuncSetAttribute(hpv, cudaFuncAttributeMaxDynamicSharedMemorySize, PV_SMEM);

    trk<<<dim3(3*DIM/32, DIM/32), dim3(32,8)>>>(w_qkv, wqkvT, DIM, 3*DIM);
    trk<<<dim3(DIM/32,   DIM/32), dim3(32,8)>>>(w_out, woutT, DIM, DIM);
    trk<<<dim3(HID/32,   DIM/32), dim3(32,8)>>>(w1,    w1T,   DIM, HID);
    trk<<<dim3(DIM/32,   HID/32), dim3(32,8)>>>(w2,    w2T,   HID, DIM);

    ln_kernel<<<M_ROWS, 256>>>(x, ln1_g, ln1_b, xn);
    hgemm<0><<<dim3(3*DIM/128, M_ROWS/128), 256, H_SMEM>>>(
        DIM, xn, DIM, wqkvT, qkv, 3*DIM, nullptr, nullptr, nullptr);
    hqk<<<dim3(TT/128, TT/128, NBH), 256>>>(qkv, Sm);
    vtrans<<<dim3(TT/32, DK/32, NBH), dim3(32,8)>>>(qkv, vt);
    softmax_topk2<<<NBH*TT, 256>>>(Sm, P, alpha_head);
    hpv<<<dim3(TT/128, NBH), 256, PV_SMEM>>>(P, vt, attn);
    hgemm<1><<<dim3(DIM/128, M_ROWS/128), 256, H_SMEM>>>(
        DIM, attn, DIM, woutT, x1, DIM, nullptr, x, alpha);
    ln_kernel<<<M_ROWS, 256>>>(x1, ln2_g, ln2_b, xn2);
    hgemm<2><<<dim3(HID/128, M_ROWS/128), 256, H_SMEM>>>(
        DIM, xn2, DIM, w1T, hbuf, HID, b1, nullptr, nullptr);
    hgemm<3><<<dim3(DIM/128, M_ROWS/128), 256, H_SMEM>>>(
        HID, hbuf, HID, w2T, out, DIM, b2, x1, alpha);
}

// round 10
// speedup vs baseline: 5.6711x; 1.0664x over previous
#include <cuda_runtime.h>
#include <cuda_fp16.h>
#include <math.h>
#include <stdint.h>

// Problem constants
#define BB   2
#define TT   2048
#define DIM  1024
#define NH   16
#define DK   64
#define TOPK 64
#define HID  8192
#define M_ROWS (BB*TT)           // 4096
#define NBH  (BB*NH)             // 32

// ---------------- scratch ------------------------------------------------------
__device__ __half g_xn  [(size_t)M_ROWS * DIM];
__device__ __half g_qkv [(size_t)M_ROWS * 3 * DIM];
__device__ __half g_S   [(size_t)NBH * TT * TT];
__device__ __half g_P   [(size_t)NBH * TT * TT];
__device__ __half g_vt  [(size_t)NBH * DK * TT];
__device__ __half g_attn[(size_t)M_ROWS * DIM];
__device__ float  g_x1  [(size_t)M_ROWS * DIM];
__device__ __half g_xn2 [(size_t)M_ROWS * DIM];
__device__ __half g_h   [(size_t)M_ROWS * HID];
__device__ __half g_wqkvT[(size_t)3 * DIM * DIM];
__device__ __half g_woutT[(size_t)DIM * DIM];
__device__ __half g_w1T  [(size_t)HID * DIM];
__device__ __half g_w2T  [(size_t)DIM * HID];

// ---------------- helpers ------------------------------------------------------
__device__ __forceinline__ void hmma(float* c, const unsigned* a, const unsigned* b)
{
    asm volatile(
        "mma.sync.aligned.m16n8k16.row.col.f32.f16.f16.f32 "
        "{%0,%1,%2,%3},{%4,%5,%6,%7},{%8,%9},{%0,%1,%2,%3};\n"
        : "+f"(c[0]), "+f"(c[1]), "+f"(c[2]), "+f"(c[3])
        : "r"(a[0]), "r"(a[1]), "r"(a[2]), "r"(a[3]), "r"(b[0]), "r"(b[1]));
}
__device__ __forceinline__ void ldsm_x4(unsigned* r, unsigned saddr)
{
    asm volatile("ldmatrix.sync.aligned.m8n8.x4.shared.b16 {%0,%1,%2,%3}, [%4];"
                 : "=r"(r[0]), "=r"(r[1]), "=r"(r[2]), "=r"(r[3]) : "r"(saddr));
}
__device__ __forceinline__ void ldsm_x2(unsigned* r, unsigned saddr)
{
    asm volatile("ldmatrix.sync.aligned.m8n8.x2.shared.b16 {%0,%1}, [%2];"
                 : "=r"(r[0]), "=r"(r[1]) : "r"(saddr));
}
__device__ __forceinline__ void cp16s(unsigned saddr, const void* g)
{
    asm volatile("cp.async.cg.shared.global [%0], [%1], 16;\n" :: "r"(saddr), "l"(g));
}
#define CP_COMMIT() asm volatile("cp.async.commit_group;\n")

// ---------------- weight transpose fp32 -> half [C][R] --------------------------
__global__ __launch_bounds__(256)
void trk(const float* __restrict__ src, __half* __restrict__ dst, int R, int C)
{
    __shared__ float t[32][33];
    const int c0 = blockIdx.x * 32, r0 = blockIdx.y * 32;
    const int x = threadIdx.x, y = threadIdx.y;
#pragma unroll
    for (int j = 0; j < 32; j += 8)
        t[y + j][x] = src[(size_t)(r0 + y + j) * C + c0 + x];
    __syncthreads();
#pragma unroll
    for (int j = 0; j < 32; j += 8)
        dst[(size_t)(c0 + y + j) * R + r0 + x] = __float2half_rn(t[x][y + j]);
}

// ---------------- V transpose: qkv half -> vt[bh][d][t] -------------------------
__global__ __launch_bounds__(256)
void vtrans(const __half* __restrict__ qkv, __half* __restrict__ vt)
{
    __shared__ __half t[32][33];
    const int bh = blockIdx.z, b = bh >> 4, h = bh & 15;
    const int t0 = blockIdx.x * 32, d0 = blockIdx.y * 32;
    const int x = threadIdx.x, y = threadIdx.y;
#pragma unroll
    for (int j = 0; j < 32; j += 8)
        t[y + j][x] = qkv[(size_t)(b * TT + t0 + y + j) * (3 * DIM) + 2 * DIM + h * DK + d0 + x];
    __syncthreads();
#pragma unroll
    for (int j = 0; j < 32; j += 8)
        vt[((size_t)bh * DK + d0 + y + j) * TT + t0 + x] = t[x][y + j];
}

// ---------------- LayerNorm (half output) ---------------------------------------
__global__ __launch_bounds__(256)
void ln_kernel(const float* __restrict__ x, const float* __restrict__ g,
               const float* __restrict__ b, __half* __restrict__ o)
{
    const int rowbase = blockIdx.x * DIM;
    const int tid = threadIdx.x;
    float v[4];
    float s = 0.f, s2 = 0.f;
#pragma unroll
    for (int i = 0; i < 4; i++) {
        v[i] = x[rowbase + tid + i * 256];
        s  += v[i];
        s2 += v[i] * v[i];
    }
    __shared__ float r1[256], r2[256];
    r1[tid] = s; r2[tid] = s2; __syncthreads();
    for (int st = 128; st > 0; st >>= 1) {
        if (tid < st) { r1[tid] += r1[tid + st]; r2[tid] += r2[tid + st]; }
        __syncthreads();
    }
    const float mu   = r1[0] * (1.f / DIM);
    const float var  = r2[0] * (1.f / DIM) - mu * mu;
    const float rstd = rsqrtf(var + 1e-5f);
#pragma unroll
    for (int i = 0; i < 4; i++) {
        int c = tid + i * 256;
        o[rowbase + c] = __float2half_rn((v[i] - mu) * rstd * g[c] + b[c]);
    }
}

// ---------------- fp16 pipelined GEMM (cp.async, BK=64, 2-stage) ----------------
// C[M,N] = A[M,K](half,row) @ Bt[N,K](half)^T.  256 threads, BM=BN=128, BK=64.
#define H_LDW 72
#define H_TILEW (128*H_LDW)               // halves per tile
#define H_SMEM (2*2*H_TILEW*2)            // bytes: 73728

template <int EPI>
__global__ __launch_bounds__(256, 2)
void hgemm(int K,
           const __half* __restrict__ A, int lda,
           const __half* __restrict__ Bt,
           void* __restrict__ Cv, int ldc,
           const float* __restrict__ bias,
           const float* __restrict__ resid,
           const float* __restrict__ alphap)
{
    constexpr bool HOUT = (EPI == 0 || EPI == 2);
    extern __shared__ __half smh[];
    const unsigned sbase = (unsigned)__cvta_generic_to_shared(smh);

    const int tid = threadIdx.x, lane = tid & 31, warp = tid >> 5;
    const int g = lane >> 2, tq = lane & 3;
    const int bm = blockIdx.y * 128, bn = blockIdx.x * 128;
    const int wm = (warp >> 2) * 64, wn = (warp & 3) * 32;

    const unsigned aoff = ((unsigned)((lane & 15) * H_LDW) + ((lane >> 4) << 3)) * 2;
    const unsigned boff = ((unsigned)((lane & 7) * H_LDW) + (((lane >> 3) & 1) << 3)) * 2;

    float acc[4][4][4];
#pragma unroll
    for (int mi = 0; mi < 4; mi++)
#pragma unroll
        for (int ni = 0; ni < 4; ni++)
#pragma unroll
            for (int q = 0; q < 4; q++) acc[mi][ni][q] = 0.f;

    auto load_stage = [&](int i) {
        const int s = i & 1;
        const unsigned sA = sbase + (unsigned)(s * 2 * H_TILEW * 2);
        const unsigned sB = sA + (unsigned)(H_TILEW * 2);
        const __half* Ap = A + (size_t)bm * lda + i * 64;
        const __half* Bp = Bt + (size_t)bn * K + i * 64;
#pragma unroll
        for (int j = 0; j < 4; j++) {
            int idx = tid + j * 256;
            int row = idx >> 3, segh = (idx & 7) << 3;
            cp16s(sA + row * (H_LDW * 2) + segh * 2, Ap + (size_t)row * lda + segh);
            cp16s(sB + row * (H_LDW * 2) + segh * 2, Bp + (size_t)row * K + segh);
        }
        CP_COMMIT();
    };

    const int KT = K / 64;
    load_stage(0);

    for (int kt = 0; kt < KT; kt++) {
        asm volatile("cp.async.wait_group 0;\n" ::: "memory");
        __syncthreads();
        if (kt + 1 < KT) load_stage(kt + 1);

        const int s = kt & 1;
        const unsigned aStage = sbase + (unsigned)(s * 2 * H_TILEW * 2);
        const unsigned bStage = aStage + (unsigned)(H_TILEW * 2);
#pragma unroll
        for (int ks = 0; ks < 4; ks++) {
            const unsigned kbb = (unsigned)(ks * 32);
            unsigned af[4][4], bf[4][2];
#pragma unroll
            for (int mi = 0; mi < 4; mi++)
                ldsm_x4(af[mi], aStage + (unsigned)((wm + mi * 16) * H_LDW * 2) + aoff + kbb);
#pragma unroll
            for (int ni = 0; ni < 4; ni++)
                ldsm_x2(bf[ni], bStage + (unsigned)((wn + ni * 8) * H_LDW * 2) + boff + kbb);
#pragma unroll
            for (int mi = 0; mi < 4; mi++)
#pragma unroll
                for (int ni = 0; ni < 4; ni++) hmma(acc[mi][ni], af[mi], bf[ni]);
        }
    }

    const float al = (EPI == 1 || EPI == 3) ? alphap[0] : 0.f;
#pragma unroll
    for (int mi = 0; mi < 4; mi++) {
#pragma unroll
        for (int ni = 0; ni < 4; ni++) {
            int r0 = bm + wm + mi * 16 + g;
            int c  = bn + wn + ni * 8 + 2 * tq;
#pragma unroll
            for (int half = 0; half < 2; half++) {
                int r = r0 + half * 8;
                size_t off = (size_t)r * ldc + c;
                float v0 = acc[mi][ni][half * 2];
                float v1 = acc[mi][ni][half * 2 + 1];
                float o0, o1;
                if (EPI == 0) {
                    o0 = v0; o1 = v1;
                } else if (EPI == 1) {
                    o0 = resid[off] + al * v0;
                    o1 = resid[off + 1] + al * v1;
                } else if (EPI == 2) {
                    float u0 = v0 + bias[c], u1 = v1 + bias[c + 1];
                    o0 = 0.5f * u0 * (1.f + erff(u0 * 0.70710678118654752440f));
                    o1 = 0.5f * u1 * (1.f + erff(u1 * 0.70710678118654752440f));
                } else {
                    o0 = resid[off] + al * (v0 + bias[c]);
                    o1 = resid[off + 1] + al * (v1 + bias[c + 1]);
                }
                if (HOUT) {
                    *(__half2*)((__half*)Cv + off) = __floats2half2_rn(o0, o1);
                } else {
                    *(float2*)((float*)Cv + off) = make_float2(o0, o1);
                }
            }
        }
    }
}

// ---------------- batched QK^T (fp16 MMA + ldmatrix): S = Q @ K^T / 8 -> fp16 ---
__global__ __launch_bounds__(256)
void hqk(const __half* __restrict__ qkv, __half* __restrict__ S)
{
    __shared__ __half As[128][72];
    __shared__ __half Bs[128][72];

    const int bh = blockIdx.z, b = bh >> 4, h = bh & 15;
    const __half* Q  = qkv + (size_t)b * TT * (3 * DIM) + h * DK;
    const __half* Kp = qkv + (size_t)b * TT * (3 * DIM) + DIM + h * DK;
    __half* Sp = S + (size_t)bh * TT * TT;

    const int tid = threadIdx.x, lane = tid & 31, warp = tid >> 5;
    const int g = lane >> 2, tq = lane & 3;
    const int bm = blockIdx.y * 128, bn = blockIdx.x * 128;
    const int wm = (warp >> 2) * 64, wn = (warp & 3) * 32;

    const unsigned sA = (unsigned)__cvta_generic_to_shared(&As[0][0]);
    const unsigned sB = (unsigned)__cvta_generic_to_shared(&Bs[0][0]);
    const unsigned aoff = ((unsigned)((lane & 15) * 72) + ((lane >> 4) << 3)) * 2;
    const unsigned boff = ((unsigned)((lane & 7) * 72) + (((lane >> 3) & 1) << 3)) * 2;

    float acc[4][4][4];
#pragma unroll
    for (int mi = 0; mi < 4; mi++)
#pragma unroll
        for (int ni = 0; ni < 4; ni++)
#pragma unroll
            for (int q = 0; q < 4; q++) acc[mi][ni][q] = 0.f;

#pragma unroll
    for (int j = 0; j < 4; j++) {
        int idx = tid + j * 256;
        int m = idx >> 3, seg = (idx & 7) << 3;
        *(uint4*)&As[m][seg] = *(const uint4*)(Q  + (size_t)(bm + m) * (3 * DIM) + seg);
        *(uint4*)&Bs[m][seg] = *(const uint4*)(Kp + (size_t)(bn + m) * (3 * DIM) + seg);
    }
    __syncthreads();

#pragma unroll
    for (int ks = 0; ks < 4; ks++) {
        const unsigned kbb = (unsigned)(ks * 16 * 2);
        unsigned af[4][4], bf[4][2];
#pragma unroll
        for (int mi = 0; mi < 4; mi++)
            ldsm_x4(af[mi], sA + (unsigned)((wm + mi * 16) * 72 * 2) + aoff + kbb);
#pragma unroll
        for (int ni = 0; ni < 4; ni++)
            ldsm_x2(bf[ni], sB + (unsigned)((wn + ni * 8) * 72 * 2) + boff + kbb);
#pragma unroll
        for (int mi = 0; mi < 4; mi++)
#pragma unroll
            for (int ni = 0; ni < 4; ni++) hmma(acc[mi][ni], af[mi], bf[ni]);
    }

#pragma unroll
    for (int mi = 0; mi < 4; mi++)
#pragma unroll
        for (int ni = 0; ni < 4; ni++) {
            int r0 = bm + wm + mi * 16 + g;
            int c  = bn + wn + ni * 8 + 2 * tq;
#pragma unroll
            for (int half = 0; half < 2; half++) {
                size_t off = (size_t)(r0 + half * 8) * TT + c;
                *(__half2*)(Sp + off) = __floats2half2_rn(acc[mi][ni][half * 2] * 0.125f,
                                                          acc[mi][ni][half * 2 + 1] * 0.125f);
            }
        }
}

// ---------------- batched PV (fp16 MMA, BK=64 2-stage, 3 CTAs/SM) ---------------
#define PV_AW (128*72)
#define PV_BW (64*72)
#define PV_SMEM (2*(PV_AW+PV_BW)*2)       // 55296 bytes

__global__ __launch_bounds__(256, 3)
void hpv(const __half* __restrict__ P, const __half* __restrict__ Vt,
         __half* __restrict__ attn_out)
{
    extern __shared__ __half smh[];
    const unsigned sbase = (unsigned)__cvta_generic_to_shared(smh);

    const int bh = blockIdx.y, b = bh >> 4, h = bh & 15;
    const __half* Pp = P + (size_t)bh * TT * TT;
    const __half* Vp = Vt + (size_t)bh * DK * TT;

    const int tid = threadIdx.x, lane = tid & 31, warp = tid >> 5;
    const int g = lane >> 2, tq = lane & 3;
    const int bm = blockIdx.x * 128;
    const int wm = (warp >> 1) * 32, wn = (warp & 1) * 32;

    const unsigned aoff = ((unsigned)((lane & 15) * 72) + ((lane >> 4) << 3)) * 2;
    const unsigned boff = ((unsigned)((lane & 7) * 72) + (((lane >> 3) & 1) << 3)) * 2;

    float acc[2][4][4];
#pragma unroll
    for (int mi = 0; mi < 2; mi++)
#pragma unroll
        for (int ni = 0; ni < 4; ni++)
#pragma unroll
            for (int q = 0; q < 4; q++) acc[mi][ni][q] = 0.f;

    auto load_stage = [&](int i) {
        const int s = i & 1;
        const unsigned sA = sbase + (unsigned)(s * (PV_AW + PV_BW) * 2);
        const unsigned sB = sA + (unsigned)(PV_AW * 2);
        const __half* Ap = Pp + i * 64;
        const __half* Bp = Vp + i * 64;
#pragma unroll
        for (int j = 0; j < 4; j++) {
            int idx = tid + j * 256;
            int row = idx >> 3, segh = (idx & 7) << 3;
            cp16s(sA + row * 144 + segh * 2, Ap + (size_t)(bm + row) * TT + segh);
        }
#pragma unroll
        for (int j = 0; j < 2; j++) {
            int idx = tid + j * 256;
            int row = idx >> 3, segh = (idx & 7) << 3;
            cp16s(sB + row * 144 + segh * 2, Bp + (size_t)row * TT + segh);
        }
        CP_COMMIT();
    };

    const int KT = TT / 64;
    load_stage(0);

    for (int kt = 0; kt < KT; kt++) {
        asm volatile("cp.async.wait_group 0;\n" ::: "memory");
        __syncthreads();
        if (kt + 1 < KT) load_stage(kt + 1);

        const int s = kt & 1;
        const unsigned aStage = sbase + (unsigned)(s * (PV_AW + PV_BW) * 2);
        const unsigned bStage = aStage + (unsigned)(PV_AW * 2);
#pragma unroll
        for (int ks = 0; ks < 4; ks++) {
            const unsigned kbb = (unsigned)(ks * 32);
            unsigned af[2][4], bf[4][2];
#pragma unroll
            for (int mi = 0; mi < 2; mi++)
                ldsm_x4(af[mi], aStage + (unsigned)((wm + mi * 16) * 144) + aoff + kbb);
#pragma unroll
            for (int ni = 0; ni < 4; ni++)
                ldsm_x2(bf[ni], bStage + (unsigned)((wn + ni * 8) * 144) + boff + kbb);
#pragma unroll
            for (int mi = 0; mi < 2; mi++)
#pragma unroll
                for (int ni = 0; ni < 4; ni++) hmma(acc[mi][ni], af[mi], bf[ni]);
        }
    }

#pragma unroll
    for (int mi = 0; mi < 2; mi++)
#pragma unroll
        for (int ni = 0; ni < 4; ni++) {
            int r0 = bm + wm + mi * 16 + g;
            int c  = wn + ni * 8 + 2 * tq;
#pragma unroll
            for (int half = 0; half < 2; half++) {
                int r = r0 + half * 8;
                size_t off = (size_t)(b * TT + r) * DIM + h * DK + c;
                *(__half2*)(attn_out + off) =
                    __floats2half2_rn(acc[mi][ni][half * 2], acc[mi][ni][half * 2 + 1]);
            }
        }
}

// ---------------- fused dual softmax + exact top-64 (fp16 S, 16-bit radix) ------
__device__ __forceinline__ unsigned ordkey16(unsigned h)
{
    return (h & 0x8000u) ? (~h & 0xFFFFu) : (h | 0x8000u);
}
__device__ __forceinline__ float ordkey16_inv(unsigned k)
{
    unsigned short hb = (unsigned short)((k & 0x8000u) ? (k & 0x7FFFu) : (~k & 0xFFFFu));
    __half hv = __ushort_as_half(hb);
    return __half2float(hv);
}

__global__ __launch_bounds__(256)
void softmax_topk2(const __half* __restrict__ S, __half* __restrict__ P,
                   const float* __restrict__ alpha_head)
{
    __shared__ int   hist[256];
    __shared__ int   chunkeq[256];
    __shared__ int   chunkpre[256];
    __shared__ float rmax[8];
    __shared__ int   wri[8];
    __shared__ float wrf1[8], wrf2[8];
    __shared__ unsigned selb;
    __shared__ int   selc;

    const int tid = threadIdx.x, lane = tid & 31, w = tid >> 5;
    const int rowid = blockIdx.x;
    const int h = (rowid >> 11) & 15;
    const __half* row = S + (size_t)rowid * TT;
    __half* prow = P + (size_t)rowid * TT;

    uint4 pk = *(const uint4*)(row + tid * 8);
    unsigned hw[4] = {pk.x, pk.y, pk.z, pk.w};
    float v[8];
    unsigned u[8];
    float m = -3.4e38f;
#pragma unroll
    for (int i = 0; i < 4; i++) {
        unsigned lo = hw[i] & 0xFFFFu, hi = hw[i] >> 16;
        v[2 * i]     = __half2float(__ushort_as_half((unsigned short)lo));
        v[2 * i + 1] = __half2float(__ushort_as_half((unsigned short)hi));
        u[2 * i]     = ordkey16(lo);
        u[2 * i + 1] = ordkey16(hi);
    }
#pragma unroll
    for (int i = 0; i < 8; i++) m = fmaxf(m, v[i]);
#pragma unroll
    for (int o = 16; o > 0; o >>= 1) m = fmaxf(m, __shfl_xor_sync(0xFFFFFFFFu, m, o));
    if (lane == 0) rmax[w] = m;
    __syncthreads();
#pragma unroll
    for (int j = 0; j < 8; j++) m = fmaxf(m, rmax[j]);

    unsigned prefix = 0u, pmask = 0u;
    int kth = TOPK;
#pragma unroll
    for (int shift = 8; shift >= 0; shift -= 8) {
        hist[tid] = 0;
        __syncthreads();
#pragma unroll
        for (int i = 0; i < 8; i++)
            if ((u[i] & pmask) == prefix) atomicAdd(&hist[(u[i] >> shift) & 255], 1);
        __syncthreads();
        if (w == 0) {
            const int base = lane * 8;
            int hv[8], loc[8];
            int s = 0;
#pragma unroll
            for (int j = 7; j >= 0; j--) { hv[j] = hist[base + j]; s += hv[j]; loc[j] = s; }
            int suf = s;
#pragma unroll
            for (int o = 1; o < 32; o <<= 1) {
                int t = __shfl_down_sync(0xFFFFFFFFu, suf, o);
                if (lane + o < 32) suf += t;
            }
            const int higher = suf - s;
            int cand = -1, cabove = 0;
#pragma unroll
            for (int j = 7; j >= 0; j--) {
                int cum = higher + loc[j];
                if (cum >= kth) { cand = base + j; cabove = cum - hv[j]; break; }
            }
#pragma unroll
            for (int o = 16; o > 0; o >>= 1) {
                int oc = __shfl_xor_sync(0xFFFFFFFFu, cand, o);
                int oa = __shfl_xor_sync(0xFFFFFFFFu, cabove, o);
                if (oc > cand) { cand = oc; cabove = oa; }
            }
            if (lane == 0) { selb = (unsigned)cand; selc = cabove; }
        }
        __syncthreads();
        prefix |= selb << shift;
        pmask  |= 0xFFu << shift;
        kth    -= selc;
        __syncthreads();
    }
    const unsigned thr = prefix;

    float e[8];
    float sd = 0.f, sgt = 0.f;
    int cgt = 0, ceq = 0;
#pragma unroll
    for (int i = 0; i < 8; i++) {
        e[i] = __expf(v[i] - m);
        sd += e[i];
        if (u[i] > thr) { cgt++; sgt += e[i]; }
        else if (u[i] == thr) ceq++;
    }
    chunkeq[tid] = ceq;
#pragma unroll
    for (int o = 16; o > 0; o >>= 1) {
        sd  += __shfl_xor_sync(0xFFFFFFFFu, sd, o);
        sgt += __shfl_xor_sync(0xFFFFFFFFu, sgt, o);
        cgt += __shfl_xor_sync(0xFFFFFFFFu, cgt, o);
    }
    if (lane == 0) { wri[w] = cgt; wrf1[w] = sd; wrf2[w] = sgt; }
    __syncthreads();
    int n_gt = 0; float Zd = 0.f, Sgt = 0.f;
#pragma unroll
    for (int j = 0; j < 8; j++) { n_gt += wri[j]; Zd += wrf1[j]; Sgt += wrf2[j]; }

    const int need = TOPK - n_gt;
    const float ethr = __expf(ordkey16_inv(thr) - m);
    const float Zs = Sgt + (float)need * ethr;

    if (w == 0) {
        const int base = lane * 8;
        int c[8], loc[8];
        int ex = 0;
#pragma unroll
        for (int j = 0; j < 8; j++) { c[j] = chunkeq[base + j]; loc[j] = ex; ex += c[j]; }
        int acc = ex;
#pragma unroll
        for (int o = 1; o < 32; o <<= 1) {
            int t = __shfl_up_sync(0xFFFFFFFFu, acc, o);
            if (lane >= o) acc += t;
        }
        const int wex = acc - ex;
#pragma unroll
        for (int j = 0; j < 8; j++) chunkpre[base + j] = wex + loc[j];
    }
    __syncthreads();

    const float gate = 1.f / (1.f + __expf(-alpha_head[h]));
    const float cd = gate / Zd;
    const float cs = (1.f - gate) / Zs;

    int tierank = chunkpre[tid];
    __half hs[8];
#pragma unroll
    for (int i = 0; i < 8; i++) {
        bool inc;
        if (u[i] > thr) inc = true;
        else if (u[i] == thr) { inc = (tierank < need); tierank++; }
        else inc = false;
        hs[i] = __float2half_rn(e[i] * (cd + (inc ? cs : 0.f)));
    }
    *(uint4*)(prow + tid * 8) = *(uint4*)hs;
}

// ---------------- launch --------------------------------------------------------
extern "C" void kernel_launch(void* const* d_in, const int* in_sizes, int n_in,
                              void* d_out, int out_size)
{
    const float* x          = (const float*)d_in[0];
    const float* ln1_g      = (const float*)d_in[1];
    const float* ln1_b      = (const float*)d_in[2];
    const float* w_qkv      = (const float*)d_in[3];
    const float* alpha_head = (const float*)d_in[4];
    const float* w_out      = (const float*)d_in[5];
    const float* ln2_g      = (const float*)d_in[6];
    const float* ln2_b      = (const float*)d_in[7];
    const float* w1         = (const float*)d_in[8];
    const float* b1         = (const float*)d_in[9];
    const float* w2         = (const float*)d_in[10];
    const float* b2         = (const float*)d_in[11];
    const float* alpha      = (const float*)d_in[12];
    float* out = (float*)d_out;

    __half *xn, *qkv, *Sm, *P, *vt, *attn, *xn2, *hbuf, *wqkvT, *woutT, *w1T, *w2T;
    float *x1;
    cudaGetSymbolAddress((void**)&xn,    g_xn);
    cudaGetSymbolAddress((void**)&qkv,   g_qkv);
    cudaGetSymbolAddress((void**)&Sm,    g_S);
    cudaGetSymbolAddress((void**)&P,     g_P);
    cudaGetSymbolAddress((void**)&vt,    g_vt);
    cudaGetSymbolAddress((void**)&attn,  g_attn);
    cudaGetSymbolAddress((void**)&x1,    g_x1);
    cudaGetSymbolAddress((void**)&xn2,   g_xn2);
    cudaGetSymbolAddress((void**)&hbuf,  g_h);
    cudaGetSymbolAddress((void**)&wqkvT, g_wqkvT);
    cudaGetSymbolAddress((void**)&woutT, g_woutT);
    cudaGetSymbolAddress((void**)&w1T,   g_w1T);
    cudaGetSymbolAddress((void**)&w2T,   g_w2T);

    cudaFuncSetAttribute(hgemm<0>, cudaFuncAttributeMaxDynamicSharedMemorySize, H_SMEM);
    cudaFuncSetAttribute(hgemm<1>, cudaFuncAttributeMaxDynamicSharedMemorySize, H_SMEM);
    cudaFuncSetAttribute(hgemm<2>, cudaFuncAttributeMaxDynamicSharedMemorySize, H_SMEM);
    cudaFuncSetAttribute(hgemm<3>, cudaFuncAttributeMaxDynamicSharedMemorySize, H_SMEM);
    cudaFuncSetAttribute(hpv, cudaFuncAttributeMaxDynamicSharedMemorySize, PV_SMEM);

    trk<<<dim3(3*DIM/32, DIM/32), dim3(32,8)>>>(w_qkv, wqkvT, DIM, 3*DIM);
    trk<<<dim3(DIM/32,   DIM/32), dim3(32,8)>>>(w_out, woutT, DIM, DIM);
    trk<<<dim3(HID/32,   DIM/32), dim3(32,8)>>>(w1,    w1T,   DIM, HID);
    trk<<<dim3(DIM/32,   HID/32), dim3(32,8)>>>(w2,    w2T,   HID, DIM);

    ln_kernel<<<M_ROWS, 256>>>(x, ln1_g, ln1_b, xn);
    hgemm<0><<<dim3(3*DIM/128, M_ROWS/128), 256, H_SMEM>>>(
        DIM, xn, DIM, wqkvT, qkv, 3*DIM, nullptr, nullptr, nullptr);
    hqk<<<dim3(TT/128, TT/128, NBH), 256>>>(qkv, Sm);
    vtrans<<<dim3(TT/32, DK/32, NBH), dim3(32,8)>>>(qkv, vt);
    softmax_topk2<<<NBH*TT, 256>>>(Sm, P, alpha_head);
    hpv<<<dim3(TT/128, NBH), 256, PV_SMEM>>>(P, vt, attn);
    hgemm<1><<<dim3(DIM/128, M_ROWS/128), 256, H_SMEM>>>(
        DIM, attn, DIM, woutT, x1, DIM, nullptr, x, alpha);
    ln_kernel<<<M_ROWS, 256>>>(x1, ln2_g, ln2_b, xn2);
    hgemm<2><<<dim3(HID/128, M_ROWS/128), 256, H_SMEM>>>(
        DIM, xn2, DIM, w1T, hbuf, HID, b1, nullptr, nullptr);
    hgemm<3><<<dim3(DIM/128, M_ROWS/128), 256, H_SMEM>>>(
        HID, hbuf, HID, w2T, out, DIM, b2, x1, alpha);
}